// round 1
// baseline (speedup 1.0000x reference)
#include <cuda_runtime.h>
#include <math.h>

// ---------------- Problem constants ----------------
#define Bz 128
#define IMG 28
#define PATCH 4
#define GRID7 7
#define L 49
#define DM 512
#define NL 8
#define DS 16
#define DC 4
#define DI 1024
#define DTR 32
#define NC 10
#define BL (Bz * L)          // 6272

// ---------------- Scratch ----------------
__device__ float g_h   [BL * DM];        // residual stream
__device__ float g_ln  [BL * DM];        // layernorm output
__device__ float g_xz  [BL * 2 * DI];    // xz = ln @ Win
__device__ float g_xc  [BL * DI];        // conv+silu output
__device__ float g_dbc [BL * 64];        // dt_lo | Bm | Cm
__device__ float g_dt  [BL * DI];        // softplus(dt_lo @ Wdt + bdt)
__device__ float g_y   [BL * DI];        // scan output * silu(z)
__device__ float g_pool[Bz * DM];
__device__ float g_hid [Bz * (DM / 2)];

// ---------------- Patch embed + pos ----------------
__global__ void patch_kernel(const float* __restrict__ x,
                             const float* __restrict__ pw,
                             const float* __restrict__ pb,
                             const float* __restrict__ pos,
                             float* __restrict__ out)
{
    int bl = blockIdx.x;           // 0..6271
    int b = bl / L, l = bl % L;
    int gr = l / GRID7, gc = l % GRID7;
    __shared__ float p[16];
    int t = threadIdx.x;           // 512
    if (t < 16) {
        int pr = t / 4, pc = t % 4;
        p[t] = x[b * (IMG * IMG) + (gr * 4 + pr) * IMG + gc * 4 + pc];
    }
    __syncthreads();
    float acc = pb[t] + pos[l * DM + t];
    const float* w = pw + t * 16;
#pragma unroll
    for (int k = 0; k < 16; ++k) acc += p[k] * w[k];
    out[bl * DM + t] = acc;
}

// ---------------- LayerNorm over DM=512 ----------------
__global__ void layernorm_kernel(const float* __restrict__ in,
                                 float* __restrict__ out,
                                 const float* __restrict__ g,
                                 const float* __restrict__ b)
{
    __shared__ float red[DM];
    int r = blockIdx.x;
    int t = threadIdx.x;           // 512
    float v = in[r * DM + t];
    red[t] = v; __syncthreads();
    for (int s = DM / 2; s > 0; s >>= 1) { if (t < s) red[t] += red[t + s]; __syncthreads(); }
    float mean = red[0] * (1.0f / DM);
    __syncthreads();
    float d = v - mean;
    red[t] = d * d; __syncthreads();
    for (int s = DM / 2; s > 0; s >>= 1) { if (t < s) red[t] += red[t + s]; __syncthreads(); }
    float var = red[0] * (1.0f / DM);
    out[r * DM + t] = d * rsqrtf(var + 1e-5f) * g[t] + b[t];
}

// ---------------- Generic fp32 GEMM: C[M,N] = A[M,K] @ B[K,N] ----------------
// BM=128, BN=64, BK=16, 256 threads, 8x4 per thread.
// EPI: 0=store, 1=C+=acc, 2=softplus(acc+bias), 3=gelu(acc+bias)
#define BM 128
#define BN 64
#define BK 16

template <int EPI>
__global__ void gemm_kernel(const float* __restrict__ A, int lda,
                            const float* __restrict__ Bm_, int ldb,
                            float* __restrict__ C, int ldc,
                            int M, int N, int K,
                            const float* __restrict__ bias)
{
    __shared__ float As[BK][BM];
    __shared__ float Bs[BK][BN];
    int tid = threadIdx.x;
    int bm = blockIdx.y * BM;
    int bn = blockIdx.x * BN;

    int m_a = tid >> 1;
    int k_a = (tid & 1) * 8;
    int k_b = tid >> 4;
    int n_b = (tid & 15) * 4;

    int tx = tid & 15;   // n
    int ty = tid >> 4;   // m
    float acc[8][4];
#pragma unroll
    for (int i = 0; i < 8; ++i)
#pragma unroll
        for (int j = 0; j < 4; ++j) acc[i][j] = 0.0f;

    for (int k0 = 0; k0 < K; k0 += BK) {
        const float* ap = A + (size_t)(bm + m_a) * lda + k0 + k_a;
        float4 a0 = *(const float4*)ap;
        float4 a1 = *(const float4*)(ap + 4);
        As[k_a + 0][m_a] = a0.x; As[k_a + 1][m_a] = a0.y;
        As[k_a + 2][m_a] = a0.z; As[k_a + 3][m_a] = a0.w;
        As[k_a + 4][m_a] = a1.x; As[k_a + 5][m_a] = a1.y;
        As[k_a + 6][m_a] = a1.z; As[k_a + 7][m_a] = a1.w;
        float4 b0 = *(const float4*)(Bm_ + (size_t)(k0 + k_b) * ldb + bn + n_b);
        *(float4*)&Bs[k_b][n_b] = b0;
        __syncthreads();
#pragma unroll
        for (int kk = 0; kk < BK; ++kk) {
            float a[8], bb[4];
#pragma unroll
            for (int i = 0; i < 8; ++i) a[i] = As[kk][ty * 8 + i];
#pragma unroll
            for (int j = 0; j < 4; ++j) bb[j] = Bs[kk][tx * 4 + j];
#pragma unroll
            for (int i = 0; i < 8; ++i)
#pragma unroll
                for (int j = 0; j < 4; ++j) acc[i][j] += a[i] * bb[j];
        }
        __syncthreads();
    }

#pragma unroll
    for (int i = 0; i < 8; ++i) {
        int m = bm + ty * 8 + i;
#pragma unroll
        for (int j = 0; j < 4; ++j) {
            int n = bn + tx * 4 + j;
            float v = acc[i][j];
            float* cp = C + (size_t)m * ldc + n;
            if (EPI == 0) {
                *cp = v;
            } else if (EPI == 1) {
                *cp += v;
            } else if (EPI == 2) {
                v += bias[n];
                *cp = (v > 20.0f) ? v : log1pf(expf(v));
            } else if (EPI == 3) {
                v += bias[n];
                *cp = 0.5f * v * (1.0f + erff(v * 0.70710678118654752f));
            }
        }
    }
}

// ---------------- causal conv1d (width 4) + silu ----------------
__global__ void conv_silu_kernel(const float* __restrict__ xz,
                                 const float* __restrict__ w,
                                 const float* __restrict__ cb,
                                 float* __restrict__ out)
{
    int id = blockIdx.x * blockDim.x + threadIdx.x;
    if (id >= BL * DI) return;
    int d = id % DI;
    int bl = id / DI;
    int t = bl % L;
    int b = bl / L;
    float y = cb[d];
    const float* wd = w + d * DC;
#pragma unroll
    for (int k = 0; k < DC; ++k) {
        int tt = t + k - (DC - 1);
        if (tt >= 0) y += wd[k] * xz[(size_t)(b * L + tt) * (2 * DI) + d];
    }
    // silu
    y = y / (1.0f + __expf(-y));
    out[(size_t)bl * DI + d] = y;
}

// ---------------- selective scan + gate ----------------
__global__ void scan_kernel(const float* __restrict__ xc,
                            const float* __restrict__ dt,
                            const float* __restrict__ dbc,
                            const float* __restrict__ xz,
                            const float* __restrict__ A_log,
                            const float* __restrict__ Dp,
                            float* __restrict__ yo)
{
    int b = blockIdx.x;                       // 0..127
    int d = blockIdx.y * 256 + threadIdx.x;   // 0..1023
    float A[DS], h[DS];
#pragma unroll
    for (int n = 0; n < DS; ++n) { A[n] = -__expf(A_log[d * DS + n]); h[n] = 0.0f; }
    float Dpd = Dp[d];
    __shared__ float Bs[DS], Cs[DS];
    for (int t = 0; t < L; ++t) {
        __syncthreads();
        if (threadIdx.x < 32) {
            int n = threadIdx.x;
            float v = dbc[(size_t)(b * L + t) * 64 + 32 + n];
            if (n < DS) Bs[n] = v; else Cs[n - DS] = v;
        }
        __syncthreads();
        size_t idx = (size_t)(b * L + t) * DI + d;
        float dtv = dt[idx];
        float xv  = xc[idx];
        float dx  = dtv * xv;
        float yv = 0.0f;
#pragma unroll
        for (int n = 0; n < DS; ++n) {
            float dA = __expf(dtv * A[n]);
            h[n] = dA * h[n] + dx * Bs[n];
            yv += h[n] * Cs[n];
        }
        yv += Dpd * xv;
        float z = xz[(size_t)(b * L + t) * (2 * DI) + DI + d];
        yv *= z / (1.0f + __expf(-z));
        yo[idx] = yv;
    }
}

// ---------------- mean-pool over L + LayerNorm ----------------
__global__ void pool_ln_kernel(const float* __restrict__ hin,
                               float* __restrict__ out,
                               const float* __restrict__ g,
                               const float* __restrict__ b)
{
    __shared__ float red[DM];
    int bb = blockIdx.x;
    int t = threadIdx.x;         // 512
    float s = 0.0f;
    for (int tt = 0; tt < L; ++tt) s += hin[(size_t)(bb * L + tt) * DM + t];
    float v = s * (1.0f / L);
    red[t] = v; __syncthreads();
    for (int st = DM / 2; st > 0; st >>= 1) { if (t < st) red[t] += red[t + st]; __syncthreads(); }
    float mean = red[0] * (1.0f / DM);
    __syncthreads();
    float d = v - mean;
    red[t] = d * d; __syncthreads();
    for (int st = DM / 2; st > 0; st >>= 1) { if (t < st) red[t] += red[t + st]; __syncthreads(); }
    float var = red[0] * (1.0f / DM);
    out[bb * DM + t] = d * rsqrtf(var + 1e-5f) * g[t] + b[t];
}

// ---------------- final logits ----------------
__global__ void logits_kernel(const float* __restrict__ hid,
                              const float* __restrict__ W2,
                              const float* __restrict__ b2,
                              float* __restrict__ out)
{
    int id = blockIdx.x * blockDim.x + threadIdx.x;
    if (id >= Bz * NC) return;
    int b = id / NC, c = id % NC;
    float acc = b2[c];
    const float* hp = hid + b * (DM / 2);
    for (int k = 0; k < DM / 2; ++k) acc += hp[k] * W2[k * NC + c];
    out[id] = acc;
}

// ---------------- launch ----------------
extern "C" void kernel_launch(void* const* d_in, const int* in_sizes, int n_in,
                              void* d_out, int out_size)
{
    const float* x      = (const float*)d_in[0];
    const float* pw     = (const float*)d_in[1];
    const float* pb     = (const float*)d_in[2];
    const float* pos    = (const float*)d_in[3];
    const float* Win    = (const float*)d_in[4];
    const float* conv_w = (const float*)d_in[5];
    const float* conv_b = (const float*)d_in[6];
    const float* Wx     = (const float*)d_in[7];
    const float* Wdt    = (const float*)d_in[8];
    const float* bdt    = (const float*)d_in[9];
    const float* A_log  = (const float*)d_in[10];
    const float* Dp     = (const float*)d_in[11];
    const float* Wout   = (const float*)d_in[12];
    const float* ln_g   = (const float*)d_in[13];
    const float* ln_b   = (const float*)d_in[14];
    const float* norm_g = (const float*)d_in[15];
    const float* norm_b = (const float*)d_in[16];
    const float* W1     = (const float*)d_in[17];
    const float* b1     = (const float*)d_in[18];
    const float* W2     = (const float*)d_in[19];
    const float* b2     = (const float*)d_in[20];

    float *h, *ln, *xz, *xc, *dbc, *dt, *y, *pool, *hid;
    cudaGetSymbolAddress((void**)&h,    g_h);
    cudaGetSymbolAddress((void**)&ln,   g_ln);
    cudaGetSymbolAddress((void**)&xz,   g_xz);
    cudaGetSymbolAddress((void**)&xc,   g_xc);
    cudaGetSymbolAddress((void**)&dbc,  g_dbc);
    cudaGetSymbolAddress((void**)&dt,   g_dt);
    cudaGetSymbolAddress((void**)&y,    g_y);
    cudaGetSymbolAddress((void**)&pool, g_pool);
    cudaGetSymbolAddress((void**)&hid,  g_hid);

    patch_kernel<<<BL, DM>>>(x, pw, pb, pos, h);

    for (int i = 0; i < NL; ++i) {
        layernorm_kernel<<<BL, DM>>>(h, ln, ln_g + i * DM, ln_b + i * DM);

        // xz = ln @ Win[i]   [6272,512]@[512,2048]
        gemm_kernel<0><<<dim3((2 * DI) / BN, BL / BM), 256>>>(
            ln, DM, Win + (size_t)i * DM * 2 * DI, 2 * DI,
            xz, 2 * DI, BL, 2 * DI, DM, nullptr);

        conv_silu_kernel<<<(BL * DI + 255) / 256, 256>>>(
            xz, conv_w + (size_t)i * DI * DC, conv_b + (size_t)i * DI, xc);

        // dbc = xc @ Wx[i]   [6272,1024]@[1024,64]
        gemm_kernel<0><<<dim3(64 / BN, BL / BM), 256>>>(
            xc, DI, Wx + (size_t)i * DI * 64, 64,
            dbc, 64, BL, 64, DI, nullptr);

        // dt = softplus(dt_lo @ Wdt[i] + bdt[i])  [6272,32]@[32,1024]
        gemm_kernel<2><<<dim3(DI / BN, BL / BM), 256>>>(
            dbc, 64, Wdt + (size_t)i * DTR * DI, DI,
            dt, DI, BL, DI, DTR, bdt + (size_t)i * DI);

        scan_kernel<<<dim3(Bz, DI / 256), 256>>>(
            xc, dt, dbc, xz,
            A_log + (size_t)i * DI * DS, Dp + (size_t)i * DI, y);

        // h += y @ Wout[i]   [6272,1024]@[1024,512]
        gemm_kernel<1><<<dim3(DM / BN, BL / BM), 256>>>(
            y, DI, Wout + (size_t)i * DI * DM, DM,
            h, DM, BL, DM, DI, nullptr);
    }

    pool_ln_kernel<<<Bz, DM>>>(h, pool, norm_g, norm_b);

    // hid = gelu(pool @ W1 + b1)  [128,512]@[512,256]
    gemm_kernel<3><<<dim3((DM / 2) / BN, Bz / BM), 256>>>(
        pool, DM, W1, DM / 2, hid, DM / 2, Bz, DM / 2, DM, b1);

    logits_kernel<<<(Bz * NC + 255) / 256, 256>>>(hid, W2, b2, (float*)d_out);
}

// round 2
// speedup vs baseline: 1.0164x; 1.0164x over previous
#include <cuda_runtime.h>
#include <math.h>

// ---------------- Problem constants ----------------
#define Bz 128
#define IMG 28
#define GRID7 7
#define L 49
#define DM 512
#define NL 8
#define DS 16
#define DC 4
#define DI 1024
#define DTR 32
#define NC 10
#define BL (Bz * L)          // 6272

typedef unsigned long long ull;

__device__ __forceinline__ ull pack2(float lo, float hi) {
    ull r; asm("mov.b64 %0, {%1, %2};" : "=l"(r) : "f"(lo), "f"(hi)); return r;
}
__device__ __forceinline__ void unpack2(ull v, float& lo, float& hi) {
    asm("mov.b64 {%0, %1}, %2;" : "=f"(lo), "=f"(hi) : "l"(v));
}
__device__ __forceinline__ void fma2(ull& d, ull a, ull b) {
    asm("fma.rn.f32x2 %0, %1, %2, %0;" : "+l"(d) : "l"(a), "l"(b));
}

// ---------------- Scratch ----------------
__device__ float g_h   [BL * DM];
__device__ float g_ln  [BL * DM];
__device__ float g_xz  [BL * 2 * DI];
__device__ float g_xc  [BL * DI];
__device__ float g_dbc [BL * 64];
__device__ float g_dbcp[4 * BL * 64];    // split-K partials
__device__ float g_dt  [BL * DI];
__device__ float g_y   [BL * DI];
__device__ float g_pool[Bz * DM];
__device__ float g_hid [Bz * (DM / 2)];

// ---------------- Patch embed + pos ----------------
__global__ void patch_kernel(const float* __restrict__ x,
                             const float* __restrict__ pw,
                             const float* __restrict__ pb,
                             const float* __restrict__ pos,
                             float* __restrict__ out)
{
    int bl = blockIdx.x;
    int b = bl / L, l = bl % L;
    int gr = l / GRID7, gc = l % GRID7;
    __shared__ float p[16];
    int t = threadIdx.x;
    if (t < 16) {
        int pr = t / 4, pc = t % 4;
        p[t] = x[b * (IMG * IMG) + (gr * 4 + pr) * IMG + gc * 4 + pc];
    }
    __syncthreads();
    float acc = pb[t] + pos[l * DM + t];
    const float* w = pw + t * 16;
#pragma unroll
    for (int k = 0; k < 16; ++k) acc += p[k] * w[k];
    out[bl * DM + t] = acc;
}

// ---------------- LayerNorm over DM=512 (warp-shuffle) ----------------
__global__ void layernorm_kernel(const float* __restrict__ in,
                                 float* __restrict__ out,
                                 const float* __restrict__ g,
                                 const float* __restrict__ b)
{
    __shared__ float ws[16], ws2[16];
    int r = blockIdx.x;
    int t = threadIdx.x;           // 512
    float v = in[(size_t)r * DM + t];
    float s = v, s2 = v * v;
#pragma unroll
    for (int o = 16; o; o >>= 1) {
        s  += __shfl_xor_sync(0xffffffffu, s,  o);
        s2 += __shfl_xor_sync(0xffffffffu, s2, o);
    }
    if ((t & 31) == 0) { ws[t >> 5] = s; ws2[t >> 5] = s2; }
    __syncthreads();
    if (t < 32) {
        float a  = (t < 16) ? ws[t]  : 0.0f;
        float a2 = (t < 16) ? ws2[t] : 0.0f;
#pragma unroll
        for (int o = 8; o; o >>= 1) {
            a  += __shfl_xor_sync(0xffffffffu, a,  o);
            a2 += __shfl_xor_sync(0xffffffffu, a2, o);
        }
        if (t == 0) { ws[0] = a; ws2[0] = a2; }
    }
    __syncthreads();
    float mean = ws[0] * (1.0f / DM);
    float var  = ws2[0] * (1.0f / DM) - mean * mean;
    out[(size_t)r * DM + t] = (v - mean) * rsqrtf(var + 1e-5f) * g[t] + b[t];
}

// ---------------- FFMA2 GEMM: C[M,N] = A[M,K] @ B[K,N] ----------------
// BM=128, BK=16, 256 threads. BN_T=128 -> 8x8/thread, BN_T=64 -> 8x4/thread.
// EPI: 0=store, 1=C+=acc, 2=softplus(acc+bias), 3=gelu(acc+bias)
template <int BN_T, int EPI>
__global__ __launch_bounds__(256) void gemm2_kernel(
    const float* __restrict__ A, int lda,
    const float* __restrict__ Bm_, int ldb,
    float* __restrict__ C, int ldc,
    int K, const float* __restrict__ bias, size_t splitC_stride)
{
    constexpr int TN = BN_T / 16;
    __shared__ float As[16][130];     // padded to dodge STS bank conflicts
    __shared__ float Bs[16][BN_T];

    int tid = threadIdx.x;
    int bm = blockIdx.y * 128;
    int bn = blockIdx.x * BN_T;
    int z  = blockIdx.z;
    A   += (size_t)z * K;             // split-K: k offset
    Bm_ += (size_t)z * K * ldb;
    C   += (size_t)z * splitC_stride;

    int m_a = tid >> 1, k_a = (tid & 1) * 8;
    int k_b = tid >> 4;
    int n_b = (tid & 15) * TN;
    int tx = tid & 15, ty = tid >> 4;

    ull acc[4][TN];
#pragma unroll
    for (int p = 0; p < 4; ++p)
#pragma unroll
        for (int j = 0; j < TN; ++j) acc[p][j] = 0ull;

    const float* Aptr = A + (size_t)(bm + m_a) * lda + k_a;
    const float* Bptr = Bm_ + (size_t)k_b * ldb + bn + n_b;

    float4 ra0 = *(const float4*)(Aptr);
    float4 ra1 = *(const float4*)(Aptr + 4);
    float4 rb0 = *(const float4*)(Bptr);
    float4 rb1;
    if constexpr (TN == 8) rb1 = *(const float4*)(Bptr + 4);

    int ntiles = K / 16;
    for (int kt = 0; kt < ntiles; ++kt) {
        As[k_a + 0][m_a] = ra0.x; As[k_a + 1][m_a] = ra0.y;
        As[k_a + 2][m_a] = ra0.z; As[k_a + 3][m_a] = ra0.w;
        As[k_a + 4][m_a] = ra1.x; As[k_a + 5][m_a] = ra1.y;
        As[k_a + 6][m_a] = ra1.z; As[k_a + 7][m_a] = ra1.w;
        *(float4*)&Bs[k_b][n_b] = rb0;
        if constexpr (TN == 8) *(float4*)&Bs[k_b][n_b + 4] = rb1;
        __syncthreads();

        if (kt + 1 < ntiles) {
            const float* Ap = Aptr + (kt + 1) * 16;
            ra0 = *(const float4*)(Ap);
            ra1 = *(const float4*)(Ap + 4);
            const float* Bp = Bptr + (size_t)(kt + 1) * 16 * ldb;
            rb0 = *(const float4*)(Bp);
            if constexpr (TN == 8) rb1 = *(const float4*)(Bp + 4);
        }

#pragma unroll
        for (int kk = 0; kk < 16; ++kk) {
            ull a2[4];
            const ull* ap = (const ull*)&As[kk][ty * 8];
            a2[0] = ap[0]; a2[1] = ap[1]; a2[2] = ap[2]; a2[3] = ap[3];
            float bf[TN];
            {
                float4 t0 = *(const float4*)&Bs[kk][tx * TN];
                bf[0] = t0.x; bf[1] = t0.y; bf[2] = t0.z; bf[3] = t0.w;
                if constexpr (TN == 8) {
                    float4 t1 = *(const float4*)&Bs[kk][tx * TN + 4];
                    bf[4] = t1.x; bf[5] = t1.y; bf[6] = t1.z; bf[7] = t1.w;
                }
            }
#pragma unroll
            for (int j = 0; j < TN; ++j) {
                ull bb = pack2(bf[j], bf[j]);
#pragma unroll
                for (int p = 0; p < 4; ++p) fma2(acc[p][j], a2[p], bb);
            }
        }
        __syncthreads();
    }

    // epilogue
    float cf[8][TN];
#pragma unroll
    for (int p = 0; p < 4; ++p)
#pragma unroll
        for (int j = 0; j < TN; ++j) unpack2(acc[p][j], cf[2 * p][j], cf[2 * p + 1][j]);

#pragma unroll
    for (int i = 0; i < 8; ++i) {
        int m = bm + ty * 8 + i;
        float* cp = C + (size_t)m * ldc + bn + tx * TN;
        if (EPI == 0) {
#pragma unroll
            for (int j = 0; j < TN; j += 4)
                *(float4*)(cp + j) = make_float4(cf[i][j], cf[i][j + 1], cf[i][j + 2], cf[i][j + 3]);
        } else if (EPI == 1) {
#pragma unroll
            for (int j = 0; j < TN; j += 4) {
                float4 o = *(const float4*)(cp + j);
                o.x += cf[i][j]; o.y += cf[i][j + 1]; o.z += cf[i][j + 2]; o.w += cf[i][j + 3];
                *(float4*)(cp + j) = o;
            }
        } else if (EPI == 2) {
#pragma unroll
            for (int j = 0; j < TN; ++j) {
                float v = cf[i][j] + bias[bn + tx * TN + j];
                cp[j] = fmaxf(v, 0.0f) + log1pf(__expf(-fabsf(v)));
            }
        } else {
#pragma unroll
            for (int j = 0; j < TN; ++j) {
                float v = cf[i][j] + bias[bn + tx * TN + j];
                cp[j] = 0.5f * v * (1.0f + erff(v * 0.70710678118654752f));
            }
        }
    }
}

// ---------------- split-K reduce (4 partials) ----------------
__global__ void reduce4_kernel(const float* __restrict__ p, float* __restrict__ out)
{
    int i = blockIdx.x * 256 + threadIdx.x;      // float4 index
    const int n4 = BL * 64 / 4;
    if (i >= n4) return;
    const float4* p4 = (const float4*)p;
    float4 a = p4[i], b = p4[i + n4], c = p4[i + 2 * n4], d = p4[i + 3 * n4];
    a.x += b.x + c.x + d.x; a.y += b.y + c.y + d.y;
    a.z += b.z + c.z + d.z; a.w += b.w + c.w + d.w;
    ((float4*)out)[i] = a;
}

// ---------------- causal conv1d (width 4) + silu, float4 over channels ----------------
__global__ void conv_silu_kernel(const float* __restrict__ xz,
                                 const float* __restrict__ w,
                                 const float* __restrict__ cb,
                                 float* __restrict__ out)
{
    int id = blockIdx.x * 256 + threadIdx.x;
    if (id >= BL * DI / 4) return;
    int dq = id % (DI / 4);
    int bl = id / (DI / 4);
    int d = dq * 4;
    int t = bl % L;
    int b = bl / L;
    float4 w0 = ((const float4*)w)[d + 0];  // 4 taps of channel d
    float4 w1 = ((const float4*)w)[d + 1];
    float4 w2 = ((const float4*)w)[d + 2];
    float4 w3 = ((const float4*)w)[d + 3];
    float4 acc = *(const float4*)&cb[d];
    const float* base = xz + (size_t)(b * L) * (2 * DI) + d;
    if (t - 3 >= 0) {
        float4 xv = *(const float4*)(base + (size_t)(t - 3) * (2 * DI));
        acc.x += w0.x * xv.x; acc.y += w1.x * xv.y; acc.z += w2.x * xv.z; acc.w += w3.x * xv.w;
    }
    if (t - 2 >= 0) {
        float4 xv = *(const float4*)(base + (size_t)(t - 2) * (2 * DI));
        acc.x += w0.y * xv.x; acc.y += w1.y * xv.y; acc.z += w2.y * xv.z; acc.w += w3.y * xv.w;
    }
    if (t - 1 >= 0) {
        float4 xv = *(const float4*)(base + (size_t)(t - 1) * (2 * DI));
        acc.x += w0.z * xv.x; acc.y += w1.z * xv.y; acc.z += w2.z * xv.z; acc.w += w3.z * xv.w;
    }
    {
        float4 xv = *(const float4*)(base + (size_t)t * (2 * DI));
        acc.x += w0.w * xv.x; acc.y += w1.w * xv.y; acc.z += w2.w * xv.z; acc.w += w3.w * xv.w;
    }
    acc.x = acc.x / (1.0f + __expf(-acc.x));
    acc.y = acc.y / (1.0f + __expf(-acc.y));
    acc.z = acc.z / (1.0f + __expf(-acc.z));
    acc.w = acc.w / (1.0f + __expf(-acc.w));
    *(float4*)&out[(size_t)bl * DI + d] = acc;
}

// ---------------- selective scan + gate ----------------
__global__ void scan_kernel(const float* __restrict__ xc,
                            const float* __restrict__ dt,
                            const float* __restrict__ dbc,
                            const float* __restrict__ xz,
                            const float* __restrict__ A_log,
                            const float* __restrict__ Dp,
                            float* __restrict__ yo)
{
    int b = blockIdx.x;
    int d = blockIdx.y * 256 + threadIdx.x;
    float A[DS], h[DS];
#pragma unroll
    for (int n = 0; n < DS; ++n) { A[n] = -__expf(A_log[d * DS + n]); h[n] = 0.0f; }
    float Dpd = Dp[d];
    __shared__ float Bs[DS], Cs[DS];
    for (int t = 0; t < L; ++t) {
        __syncthreads();
        if (threadIdx.x < 32) {
            int n = threadIdx.x;
            float v = dbc[(size_t)(b * L + t) * 64 + 32 + n];
            if (n < DS) Bs[n] = v; else Cs[n - DS] = v;
        }
        __syncthreads();
        size_t idx = (size_t)(b * L + t) * DI + d;
        float dtv = dt[idx];
        float xv  = xc[idx];
        float dx  = dtv * xv;
        float yv = 0.0f;
#pragma unroll
        for (int n = 0; n < DS; ++n) {
            float dA = __expf(dtv * A[n]);
            h[n] = dA * h[n] + dx * Bs[n];
            yv += h[n] * Cs[n];
        }
        yv += Dpd * xv;
        float z = xz[(size_t)(b * L + t) * (2 * DI) + DI + d];
        yv *= z / (1.0f + __expf(-z));
        yo[idx] = yv;
    }
}

// ---------------- mean-pool over L + LayerNorm ----------------
__global__ void pool_ln_kernel(const float* __restrict__ hin,
                               float* __restrict__ out,
                               const float* __restrict__ g,
                               const float* __restrict__ b)
{
    __shared__ float ws[16], ws2[16];
    int bb = blockIdx.x;
    int t = threadIdx.x;
    float s = 0.0f;
    for (int tt = 0; tt < L; ++tt) s += hin[(size_t)(bb * L + tt) * DM + t];
    float v = s * (1.0f / L);
    float sm = v, s2 = v * v;
#pragma unroll
    for (int o = 16; o; o >>= 1) {
        sm += __shfl_xor_sync(0xffffffffu, sm, o);
        s2 += __shfl_xor_sync(0xffffffffu, s2, o);
    }
    if ((t & 31) == 0) { ws[t >> 5] = sm; ws2[t >> 5] = s2; }
    __syncthreads();
    if (t < 32) {
        float a  = (t < 16) ? ws[t]  : 0.0f;
        float a2 = (t < 16) ? ws2[t] : 0.0f;
#pragma unroll
        for (int o = 8; o; o >>= 1) {
            a  += __shfl_xor_sync(0xffffffffu, a,  o);
            a2 += __shfl_xor_sync(0xffffffffu, a2, o);
        }
        if (t == 0) { ws[0] = a; ws2[0] = a2; }
    }
    __syncthreads();
    float mean = ws[0] * (1.0f / DM);
    float var  = ws2[0] * (1.0f / DM) - mean * mean;
    out[bb * DM + t] = (v - mean) * rsqrtf(var + 1e-5f) * g[t] + b[t];
}

// ---------------- final logits ----------------
__global__ void logits_kernel(const float* __restrict__ hid,
                              const float* __restrict__ W2,
                              const float* __restrict__ b2,
                              float* __restrict__ out)
{
    int id = blockIdx.x * blockDim.x + threadIdx.x;
    if (id >= Bz * NC) return;
    int b = id / NC, c = id % NC;
    float acc = b2[c];
    const float* hp = hid + b * (DM / 2);
    for (int k = 0; k < DM / 2; ++k) acc += hp[k] * W2[k * NC + c];
    out[id] = acc;
}

// ---------------- launch ----------------
extern "C" void kernel_launch(void* const* d_in, const int* in_sizes, int n_in,
                              void* d_out, int out_size)
{
    const float* x      = (const float*)d_in[0];
    const float* pw     = (const float*)d_in[1];
    const float* pb     = (const float*)d_in[2];
    const float* pos    = (const float*)d_in[3];
    const float* Win    = (const float*)d_in[4];
    const float* conv_w = (const float*)d_in[5];
    const float* conv_b = (const float*)d_in[6];
    const float* Wx     = (const float*)d_in[7];
    const float* Wdt    = (const float*)d_in[8];
    const float* bdt    = (const float*)d_in[9];
    const float* A_log  = (const float*)d_in[10];
    const float* Dp     = (const float*)d_in[11];
    const float* Wout   = (const float*)d_in[12];
    const float* ln_g   = (const float*)d_in[13];
    const float* ln_b   = (const float*)d_in[14];
    const float* norm_g = (const float*)d_in[15];
    const float* norm_b = (const float*)d_in[16];
    const float* W1     = (const float*)d_in[17];
    const float* b1     = (const float*)d_in[18];
    const float* W2     = (const float*)d_in[19];
    const float* b2     = (const float*)d_in[20];

    float *h, *ln, *xz, *xc, *dbc, *dbcp, *dt, *y, *pool, *hid;
    cudaGetSymbolAddress((void**)&h,    g_h);
    cudaGetSymbolAddress((void**)&ln,   g_ln);
    cudaGetSymbolAddress((void**)&xz,   g_xz);
    cudaGetSymbolAddress((void**)&xc,   g_xc);
    cudaGetSymbolAddress((void**)&dbc,  g_dbc);
    cudaGetSymbolAddress((void**)&dbcp, g_dbcp);
    cudaGetSymbolAddress((void**)&dt,   g_dt);
    cudaGetSymbolAddress((void**)&y,    g_y);
    cudaGetSymbolAddress((void**)&pool, g_pool);
    cudaGetSymbolAddress((void**)&hid,  g_hid);

    patch_kernel<<<BL, DM>>>(x, pw, pb, pos, h);

    for (int i = 0; i < NL; ++i) {
        layernorm_kernel<<<BL, DM>>>(h, ln, ln_g + i * DM, ln_b + i * DM);

        // xz = ln @ Win[i]   [6272,512]@[512,2048]
        gemm2_kernel<128, 0><<<dim3(16, 49), 256>>>(
            ln, DM, Win + (size_t)i * DM * 2 * DI, 2 * DI,
            xz, 2 * DI, DM, nullptr, 0);

        conv_silu_kernel<<<(BL * DI / 4 + 255) / 256, 256>>>(
            xz, conv_w + (size_t)i * DI * DC, conv_b + (size_t)i * DI, xc);

        // dbc = xc @ Wx[i]   [6272,1024]@[1024,64]  split-K x4
        gemm2_kernel<64, 0><<<dim3(1, 49, 4), 256>>>(
            xc, DI, Wx + (size_t)i * DI * 64, 64,
            dbcp, 64, DI / 4, nullptr, (size_t)BL * 64);
        reduce4_kernel<<<(BL * 64 / 4 + 255) / 256, 256>>>(dbcp, dbc);

        // dt = softplus(dt_lo @ Wdt[i] + bdt[i])  [6272,32]@[32,1024]
        gemm2_kernel<128, 2><<<dim3(8, 49), 256>>>(
            dbc, 64, Wdt + (size_t)i * DTR * DI, DI,
            dt, DI, DTR, bdt + (size_t)i * DI, 0);

        scan_kernel<<<dim3(Bz, DI / 256), 256>>>(
            xc, dt, dbc, xz,
            A_log + (size_t)i * DI * DS, Dp + (size_t)i * DI, y);

        // h += y @ Wout[i]   [6272,1024]@[1024,512]
        gemm2_kernel<128, 1><<<dim3(4, 49), 256>>>(
            y, DI, Wout + (size_t)i * DI * DM, DM,
            h, DM, DI, nullptr, 0);
    }

    pool_ln_kernel<<<Bz, DM>>>(h, pool, norm_g, norm_b);

    // hid = gelu(pool @ W1 + b1)  [128,512]@[512,256]
    gemm2_kernel<128, 3><<<dim3(2, 1), 256>>>(
        pool, DM, W1, DM / 2, hid, DM / 2, DM, b1, 0);

    logits_kernel<<<(Bz * NC + 255) / 256, 256>>>(hid, W2, b2, (float*)d_out);
}

// round 4
// speedup vs baseline: 1.5378x; 1.5130x over previous
#include <cuda_runtime.h>
#include <cuda_bf16.h>
#include <math.h>
#include <stdint.h>

// ---------------- Problem constants ----------------
#define Bz 128
#define IMG 28
#define GRID7 7
#define L 49
#define DM 512
#define NL 8
#define DS 16
#define DC 4
#define DI 1024
#define DTR 32
#define NC 10
#define BL (Bz * L)          // 6272

typedef unsigned long long ull;
typedef __nv_bfloat16 bf16;

// ================= helpers =================
__device__ __forceinline__ uint32_t s2u(const void* p) {
    uint32_t a;
    asm("{ .reg .u64 t; cvta.to.shared.u64 t, %1; cvt.u32.u64 %0, t; }" : "=r"(a) : "l"(p));
    return a;
}
__device__ __forceinline__ void ldsm4(uint32_t& r0, uint32_t& r1, uint32_t& r2, uint32_t& r3, uint32_t addr) {
    asm volatile("ldmatrix.sync.aligned.m8n8.x4.shared.b16 {%0,%1,%2,%3}, [%4];"
                 : "=r"(r0), "=r"(r1), "=r"(r2), "=r"(r3) : "r"(addr));
}
__device__ __forceinline__ void ldsm2(uint32_t& r0, uint32_t& r1, uint32_t addr) {
    asm volatile("ldmatrix.sync.aligned.m8n8.x2.shared.b16 {%0,%1}, [%2];"
                 : "=r"(r0), "=r"(r1) : "r"(addr));
}
__device__ __forceinline__ void mma16816(float* c, const uint32_t* a, const uint32_t* b) {
    asm volatile("mma.sync.aligned.m16n8k16.row.col.f32.bf16.bf16.f32 "
                 "{%0,%1,%2,%3}, {%4,%5,%6,%7}, {%8,%9}, {%0,%1,%2,%3};"
                 : "+f"(c[0]), "+f"(c[1]), "+f"(c[2]), "+f"(c[3])
                 : "r"(a[0]), "r"(a[1]), "r"(a[2]), "r"(a[3]), "r"(b[0]), "r"(b[1]));
}
// FFMA2 helpers (SIMT gemm)
__device__ __forceinline__ ull pack2(float lo, float hi) {
    ull r; asm("mov.b64 %0, {%1, %2};" : "=l"(r) : "f"(lo), "f"(hi)); return r;
}
__device__ __forceinline__ void unpack2(ull v, float& lo, float& hi) {
    asm("mov.b64 {%0, %1}, %2;" : "=f"(lo), "=f"(hi) : "l"(v));
}
__device__ __forceinline__ void fma2(ull& d, ull a, ull b) {
    asm("fma.rn.f32x2 %0, %1, %2, %0;" : "+l"(d) : "l"(a), "l"(b));
}
__device__ __forceinline__ void hilo(float v, bf16& h, bf16& l) {
    h = __float2bfloat16(v);
    l = __float2bfloat16(v - __bfloat162float(h));
}

// ---------------- Scratch ----------------
__device__ float g_h   [BL * DM];
__device__ float g_xz  [BL * 2 * DI];
__device__ float g_xc  [BL * DI];
__device__ float g_dbc [BL * 64];
__device__ float g_dbcp[4 * BL * 64];
__device__ float g_dt  [BL * DI];
__device__ float g_pool[Bz * DM];
__device__ float g_hid [Bz * (DM / 2)];
__device__ bf16  g_lnH [BL * DM];
__device__ bf16  g_lnL [BL * DM];
__device__ bf16  g_yH  [BL * DI];
__device__ bf16  g_yL  [BL * DI];
__device__ bf16  g_WinH [NL * 2 * DI * DM];   // [l][N=2048][K=512]
__device__ bf16  g_WinL [NL * 2 * DI * DM];
__device__ bf16  g_WoutH[NL * DM * DI];       // [l][N=512][K=1024]
__device__ bf16  g_WoutL[NL * DM * DI];

// ---------------- Patch embed + pos ----------------
__global__ void patch_kernel(const float* __restrict__ x,
                             const float* __restrict__ pw,
                             const float* __restrict__ pb,
                             const float* __restrict__ pos,
                             float* __restrict__ out)
{
    int bl = blockIdx.x;
    int b = bl / L, l = bl % L;
    int gr = l / GRID7, gc = l % GRID7;
    __shared__ float p[16];
    int t = threadIdx.x;
    if (t < 16) {
        int pr = t / 4, pc = t % 4;
        p[t] = x[b * (IMG * IMG) + (gr * 4 + pr) * IMG + gc * 4 + pc];
    }
    __syncthreads();
    float acc = pb[t] + pos[l * DM + t];
    const float* w = pw + t * 16;
#pragma unroll
    for (int k = 0; k < 16; ++k) acc += p[k] * w[k];
    out[bl * DM + t] = acc;
}

// ---------------- weight prep: W[K,N] -> W^T hi/lo bf16 [N][K] ----------------
__global__ void prep_w_kernel(const float* __restrict__ W,
                              bf16* __restrict__ outH, bf16* __restrict__ outL,
                              int K, int N)
{
    __shared__ float sm[32][33];
    int n0 = blockIdx.x * 32, k0 = blockIdx.y * 32, l = blockIdx.z;
    const float* Wl = W + (size_t)l * K * N;
    bf16* oH = outH + (size_t)l * N * K;
    bf16* oL = outL + (size_t)l * N * K;
    int tid = threadIdx.x;
#pragma unroll
    for (int i = 0; i < 4; ++i) {
        int idx = tid + i * 256;
        int kk = idx >> 5, nn = idx & 31;
        sm[kk][nn] = Wl[(size_t)(k0 + kk) * N + n0 + nn];
    }
    __syncthreads();
#pragma unroll
    for (int i = 0; i < 4; ++i) {
        int idx = tid + i * 256;
        int nn = idx >> 5, kk = idx & 31;
        bf16 h, lo; hilo(sm[kk][nn], h, lo);
        size_t o = (size_t)(n0 + nn) * K + k0 + kk;
        oH[o] = h; oL[o] = lo;
    }
}

// ---------------- LayerNorm -> bf16 hi/lo ----------------
__global__ void layernorm_bf_kernel(const float* __restrict__ in,
                                    bf16* __restrict__ oH, bf16* __restrict__ oL,
                                    const float* __restrict__ g,
                                    const float* __restrict__ b)
{
    __shared__ float ws[16], ws2[16];
    int r = blockIdx.x;
    int t = threadIdx.x;           // 512
    float v = in[(size_t)r * DM + t];
    float s = v, s2 = v * v;
#pragma unroll
    for (int o = 16; o; o >>= 1) {
        s  += __shfl_xor_sync(0xffffffffu, s,  o);
        s2 += __shfl_xor_sync(0xffffffffu, s2, o);
    }
    if ((t & 31) == 0) { ws[t >> 5] = s; ws2[t >> 5] = s2; }
    __syncthreads();
    if (t < 32) {
        float a  = (t < 16) ? ws[t]  : 0.0f;
        float a2 = (t < 16) ? ws2[t] : 0.0f;
#pragma unroll
        for (int o = 8; o; o >>= 1) {
            a  += __shfl_xor_sync(0xffffffffu, a,  o);
            a2 += __shfl_xor_sync(0xffffffffu, a2, o);
        }
        if (t == 0) { ws[0] = a; ws2[0] = a2; }
    }
    __syncthreads();
    float mean = ws[0] * (1.0f / DM);
    float var  = ws2[0] * (1.0f / DM) - mean * mean;
    float nv = (v - mean) * rsqrtf(var + 1e-5f) * g[t] + b[t];
    bf16 h, lo; hilo(nv, h, lo);
    oH[(size_t)r * DM + t] = h;
    oL[(size_t)r * DM + t] = lo;
}

// ---------------- tensor-core GEMM via mma.sync (3-term bf16 hi/lo) ----------------
// C[M,N] = A[M,K] @ B^T[N,K];  CTA tile 128x128, 8 warps (2x4), warp tile 64x32.
// EPI: 0 = store, 1 = C += acc
#define SSTR 40   // smem row stride in bf16 (32 + 8 pad)

template <int EPI>
__global__ __launch_bounds__(256, 1) void gemm_mma_kernel(
    const bf16* __restrict__ Ah, const bf16* __restrict__ Al, int lda,
    const bf16* __restrict__ Bh, const bf16* __restrict__ Bl,
    float* __restrict__ C, int ldc, int K)
{
    __shared__ bf16 sAh[128 * SSTR], sAl[128 * SSTR];
    __shared__ bf16 sBh[128 * SSTR], sBl[128 * SSTR];

    int tid = threadIdx.x;
    int wid = tid >> 5, lane = tid & 31;
    int rb = blockIdx.y, nb = blockIdx.x;
    int warp_m = wid >> 2;        // 0..1 -> 64 rows
    int warp_n = wid & 3;         // 0..3 -> 32 cols

    uint32_t uAh = s2u(sAh), uAl = s2u(sAl), uBh = s2u(sBh), uBl = s2u(sBl);

    float acc[4][4][4];
#pragma unroll
    for (int mi = 0; mi < 4; ++mi)
#pragma unroll
        for (int ni = 0; ni < 4; ++ni)
#pragma unroll
            for (int q = 0; q < 4; ++q) acc[mi][ni][q] = 0.0f;

    // per-lane ldmatrix row/col offsets
    int a_m = (lane & 7) + ((lane & 8) ? 8 : 0);
    int a_k = (lane & 16) ? 8 : 0;
    int b_n = lane & 7;
    int b_k = (lane & 8) ? 8 : 0;

    const bf16* gAh = Ah + (size_t)(rb * 128) * lda;
    const bf16* gAl = Al + (size_t)(rb * 128) * lda;
    const bf16* gBh = Bh + (size_t)(nb * 128) * K;
    const bf16* gBl = Bl + (size_t)(nb * 128) * K;

    for (int k0 = 0; k0 < K; k0 += 32) {
#pragma unroll
        for (int i = 0; i < 2; ++i) {
            int idx = tid + i * 256;          // 0..511
            int r = idx >> 2, sgm = idx & 3;  // row, 8-bf16 segment
            int soff = r * SSTR + sgm * 8;
            size_t gaoff = (size_t)r * lda + k0 + sgm * 8;
            size_t gboff = (size_t)r * K + k0 + sgm * 8;
            *(uint4*)&sAh[soff] = *(const uint4*)&gAh[gaoff];
            *(uint4*)&sAl[soff] = *(const uint4*)&gAl[gaoff];
            *(uint4*)&sBh[soff] = *(const uint4*)&gBh[gboff];
            *(uint4*)&sBl[soff] = *(const uint4*)&gBl[gboff];
        }
        __syncthreads();

#pragma unroll
        for (int ks = 0; ks < 2; ++ks) {
            int kk = ks * 16;
            // B fragments for this warp's 32 cols
            uint32_t bh[4][2], blr[4][2];
#pragma unroll
            for (int ni = 0; ni < 4; ++ni) {
                int row = warp_n * 32 + ni * 8 + b_n;
                uint32_t off = (uint32_t)(row * SSTR + kk + b_k) * 2;
                ldsm2(bh[ni][0],  bh[ni][1],  uBh + off);
                ldsm2(blr[ni][0], blr[ni][1], uBl + off);
            }
#pragma unroll
            for (int mi = 0; mi < 4; ++mi) {
                int row = warp_m * 64 + mi * 16 + a_m;
                uint32_t off = (uint32_t)(row * SSTR + kk + a_k) * 2;
                uint32_t ah[4], al[4];
                ldsm4(ah[0], ah[1], ah[2], ah[3], uAh + off);
                ldsm4(al[0], al[1], al[2], al[3], uAl + off);
#pragma unroll
                for (int ni = 0; ni < 4; ++ni) {
                    mma16816(acc[mi][ni], ah, bh[ni]);
                    mma16816(acc[mi][ni], ah, blr[ni]);
                    mma16816(acc[mi][ni], al, bh[ni]);
                }
            }
        }
        __syncthreads();
    }

    // epilogue
    int g = lane >> 2, cpair = (lane & 3) * 2;
#pragma unroll
    for (int mi = 0; mi < 4; ++mi) {
        int r0 = rb * 128 + warp_m * 64 + mi * 16 + g;
        int r1 = r0 + 8;
#pragma unroll
        for (int ni = 0; ni < 4; ++ni) {
            int col = nb * 128 + warp_n * 32 + ni * 8 + cpair;
            float* c0 = C + (size_t)r0 * ldc + col;
            float* c1 = C + (size_t)r1 * ldc + col;
            if (EPI == 0) {
                *(float2*)c0 = make_float2(acc[mi][ni][0], acc[mi][ni][1]);
                *(float2*)c1 = make_float2(acc[mi][ni][2], acc[mi][ni][3]);
            } else {
                float2 o0 = *(float2*)c0, o1 = *(float2*)c1;
                o0.x += acc[mi][ni][0]; o0.y += acc[mi][ni][1];
                o1.x += acc[mi][ni][2]; o1.y += acc[mi][ni][3];
                *(float2*)c0 = o0;
                *(float2*)c1 = o1;
            }
        }
    }
}

// ---------------- SIMT FFMA2 GEMM (small GEMMs) ----------------
template <int BN_T, int EPI>
__global__ __launch_bounds__(256) void gemm2_kernel(
    const float* __restrict__ A, int lda,
    const float* __restrict__ Bm_, int ldb,
    float* __restrict__ C, int ldc,
    int K, const float* __restrict__ bias, size_t splitC_stride)
{
    constexpr int TN = BN_T / 16;
    __shared__ float As[16][130];
    __shared__ float Bs[16][BN_T];

    int tid = threadIdx.x;
    int bm = blockIdx.y * 128;
    int bn = blockIdx.x * BN_T;
    int z  = blockIdx.z;
    A   += (size_t)z * K;
    Bm_ += (size_t)z * K * ldb;
    C   += (size_t)z * splitC_stride;

    int m_a = tid >> 1, k_a = (tid & 1) * 8;
    int k_b = tid >> 4;
    int n_b = (tid & 15) * TN;
    int tx = tid & 15, ty = tid >> 4;

    ull acc[4][TN];
#pragma unroll
    for (int p = 0; p < 4; ++p)
#pragma unroll
        for (int j = 0; j < TN; ++j) acc[p][j] = 0ull;

    const float* Aptr = A + (size_t)(bm + m_a) * lda + k_a;
    const float* Bptr = Bm_ + (size_t)k_b * ldb + bn + n_b;

    float4 ra0 = *(const float4*)(Aptr);
    float4 ra1 = *(const float4*)(Aptr + 4);
    float4 rb0 = *(const float4*)(Bptr);
    float4 rb1;
    if constexpr (TN == 8) rb1 = *(const float4*)(Bptr + 4);

    int ntiles = K / 16;
    for (int kt = 0; kt < ntiles; ++kt) {
        As[k_a + 0][m_a] = ra0.x; As[k_a + 1][m_a] = ra0.y;
        As[k_a + 2][m_a] = ra0.z; As[k_a + 3][m_a] = ra0.w;
        As[k_a + 4][m_a] = ra1.x; As[k_a + 5][m_a] = ra1.y;
        As[k_a + 6][m_a] = ra1.z; As[k_a + 7][m_a] = ra1.w;
        *(float4*)&Bs[k_b][n_b] = rb0;
        if constexpr (TN == 8) *(float4*)&Bs[k_b][n_b + 4] = rb1;
        __syncthreads();

        if (kt + 1 < ntiles) {
            const float* Ap = Aptr + (kt + 1) * 16;
            ra0 = *(const float4*)(Ap);
            ra1 = *(const float4*)(Ap + 4);
            const float* Bp = Bptr + (size_t)(kt + 1) * 16 * ldb;
            rb0 = *(const float4*)(Bp);
            if constexpr (TN == 8) rb1 = *(const float4*)(Bp + 4);
        }

#pragma unroll
        for (int kk = 0; kk < 16; ++kk) {
            ull a2[4];
            const ull* ap = (const ull*)&As[kk][ty * 8];
            a2[0] = ap[0]; a2[1] = ap[1]; a2[2] = ap[2]; a2[3] = ap[3];
            float bf[TN];
            {
                float4 t0 = *(const float4*)&Bs[kk][tx * TN];
                bf[0] = t0.x; bf[1] = t0.y; bf[2] = t0.z; bf[3] = t0.w;
                if constexpr (TN == 8) {
                    float4 t1 = *(const float4*)&Bs[kk][tx * TN + 4];
                    bf[4] = t1.x; bf[5] = t1.y; bf[6] = t1.z; bf[7] = t1.w;
                }
            }
#pragma unroll
            for (int j = 0; j < TN; ++j) {
                ull bb = pack2(bf[j], bf[j]);
#pragma unroll
                for (int p = 0; p < 4; ++p) fma2(acc[p][j], a2[p], bb);
            }
        }
        __syncthreads();
    }

    float cf[8][TN];
#pragma unroll
    for (int p = 0; p < 4; ++p)
#pragma unroll
        for (int j = 0; j < TN; ++j) unpack2(acc[p][j], cf[2 * p][j], cf[2 * p + 1][j]);

#pragma unroll
    for (int i = 0; i < 8; ++i) {
        int m = bm + ty * 8 + i;
        float* cp = C + (size_t)m * ldc + bn + tx * TN;
        if (EPI == 0) {
#pragma unroll
            for (int j = 0; j < TN; j += 4)
                *(float4*)(cp + j) = make_float4(cf[i][j], cf[i][j + 1], cf[i][j + 2], cf[i][j + 3]);
        } else if (EPI == 1) {
#pragma unroll
            for (int j = 0; j < TN; j += 4) {
                float4 o = *(const float4*)(cp + j);
                o.x += cf[i][j]; o.y += cf[i][j + 1]; o.z += cf[i][j + 2]; o.w += cf[i][j + 3];
                *(float4*)(cp + j) = o;
            }
        } else if (EPI == 2) {
#pragma unroll
            for (int j = 0; j < TN; ++j) {
                float v = cf[i][j] + bias[bn + tx * TN + j];
                cp[j] = fmaxf(v, 0.0f) + log1pf(__expf(-fabsf(v)));
            }
        } else {
#pragma unroll
            for (int j = 0; j < TN; ++j) {
                float v = cf[i][j] + bias[bn + tx * TN + j];
                cp[j] = 0.5f * v * (1.0f + erff(v * 0.70710678118654752f));
            }
        }
    }
}

// ---------------- split-K reduce ----------------
__global__ void reduce4_kernel(const float* __restrict__ p, float* __restrict__ out)
{
    int i = blockIdx.x * 256 + threadIdx.x;
    const int n4 = BL * 64 / 4;
    if (i >= n4) return;
    const float4* p4 = (const float4*)p;
    float4 a = p4[i], b = p4[i + n4], c = p4[i + 2 * n4], d = p4[i + 3 * n4];
    a.x += b.x + c.x + d.x; a.y += b.y + c.y + d.y;
    a.z += b.z + c.z + d.z; a.w += b.w + c.w + d.w;
    ((float4*)out)[i] = a;
}

// ---------------- causal conv1d + silu ----------------
__global__ void conv_silu_kernel(const float* __restrict__ xz,
                                 const float* __restrict__ w,
                                 const float* __restrict__ cb,
                                 float* __restrict__ out)
{
    int id = blockIdx.x * 256 + threadIdx.x;
    if (id >= BL * DI / 4) return;
    int dq = id % (DI / 4);
    int bl = id / (DI / 4);
    int d = dq * 4;
    int t = bl % L;
    int b = bl / L;
    float4 w0 = ((const float4*)w)[d + 0];
    float4 w1 = ((const float4*)w)[d + 1];
    float4 w2 = ((const float4*)w)[d + 2];
    float4 w3 = ((const float4*)w)[d + 3];
    float4 acc = *(const float4*)&cb[d];
    const float* base = xz + (size_t)(b * L) * (2 * DI) + d;
    if (t - 3 >= 0) {
        float4 xv = *(const float4*)(base + (size_t)(t - 3) * (2 * DI));
        acc.x += w0.x * xv.x; acc.y += w1.x * xv.y; acc.z += w2.x * xv.z; acc.w += w3.x * xv.w;
    }
    if (t - 2 >= 0) {
        float4 xv = *(const float4*)(base + (size_t)(t - 2) * (2 * DI));
        acc.x += w0.y * xv.x; acc.y += w1.y * xv.y; acc.z += w2.y * xv.z; acc.w += w3.y * xv.w;
    }
    if (t - 1 >= 0) {
        float4 xv = *(const float4*)(base + (size_t)(t - 1) * (2 * DI));
        acc.x += w0.z * xv.x; acc.y += w1.z * xv.y; acc.z += w2.z * xv.z; acc.w += w3.z * xv.w;
    }
    {
        float4 xv = *(const float4*)(base + (size_t)t * (2 * DI));
        acc.x += w0.w * xv.x; acc.y += w1.w * xv.y; acc.z += w2.w * xv.z; acc.w += w3.w * xv.w;
    }
    acc.x = acc.x / (1.0f + __expf(-acc.x));
    acc.y = acc.y / (1.0f + __expf(-acc.y));
    acc.z = acc.z / (1.0f + __expf(-acc.z));
    acc.w = acc.w / (1.0f + __expf(-acc.w));
    *(float4*)&out[(size_t)bl * DI + d] = acc;
}

// ---------------- selective scan + gate -> bf16 hi/lo y ----------------
__global__ void scan_kernel(const float* __restrict__ xc,
                            const float* __restrict__ dt,
                            const float* __restrict__ dbc,
                            const float* __restrict__ xz,
                            const float* __restrict__ A_log,
                            const float* __restrict__ Dp,
                            bf16* __restrict__ yH, bf16* __restrict__ yL)
{
    int bb = blockIdx.x;
    int d = blockIdx.y * 256 + threadIdx.x;
    float A[DS], h[DS];
#pragma unroll
    for (int n = 0; n < DS; ++n) { A[n] = -__expf(A_log[d * DS + n]); h[n] = 0.0f; }
    float Dpd = Dp[d];
    __shared__ float Bs[DS], Cs[DS];
    for (int t = 0; t < L; ++t) {
        __syncthreads();
        if (threadIdx.x < 32) {
            int n = threadIdx.x;
            float v = dbc[(size_t)(bb * L + t) * 64 + 32 + n];
            if (n < DS) Bs[n] = v; else Cs[n - DS] = v;
        }
        __syncthreads();
        size_t idx = (size_t)(bb * L + t) * DI + d;
        float dtv = dt[idx];
        float xv  = xc[idx];
        float dx  = dtv * xv;
        float yv = 0.0f;
#pragma unroll
        for (int n = 0; n < DS; ++n) {
            float dA = __expf(dtv * A[n]);
            h[n] = dA * h[n] + dx * Bs[n];
            yv += h[n] * Cs[n];
        }
        yv += Dpd * xv;
        float z = xz[(size_t)(bb * L + t) * (2 * DI) + DI + d];
        yv *= z / (1.0f + __expf(-z));
        bf16 hh, ll; hilo(yv, hh, ll);
        yH[idx] = hh;
        yL[idx] = ll;
    }
}

// ---------------- mean-pool over L + LayerNorm ----------------
__global__ void pool_ln_kernel(const float* __restrict__ hin,
                               float* __restrict__ out,
                               const float* __restrict__ g,
                               const float* __restrict__ b)
{
    __shared__ float ws[16], ws2[16];
    int bb = blockIdx.x;
    int t = threadIdx.x;
    float s = 0.0f;
    for (int tt = 0; tt < L; ++tt) s += hin[(size_t)(bb * L + tt) * DM + t];
    float v = s * (1.0f / L);
    float sm = v, s2 = v * v;
#pragma unroll
    for (int o = 16; o; o >>= 1) {
        sm += __shfl_xor_sync(0xffffffffu, sm, o);
        s2 += __shfl_xor_sync(0xffffffffu, s2, o);
    }
    if ((t & 31) == 0) { ws[t >> 5] = sm; ws2[t >> 5] = s2; }
    __syncthreads();
    if (t < 32) {
        float a  = (t < 16) ? ws[t]  : 0.0f;
        float a2 = (t < 16) ? ws2[t] : 0.0f;
#pragma unroll
        for (int o = 8; o; o >>= 1) {
            a  += __shfl_xor_sync(0xffffffffu, a,  o);
            a2 += __shfl_xor_sync(0xffffffffu, a2, o);
        }
        if (t == 0) { ws[0] = a; ws2[0] = a2; }
    }
    __syncthreads();
    float mean = ws[0] * (1.0f / DM);
    float var  = ws2[0] * (1.0f / DM) - mean * mean;
    out[bb * DM + t] = (v - mean) * rsqrtf(var + 1e-5f) * g[t] + b[t];
}

// ---------------- final logits ----------------
__global__ void logits_kernel(const float* __restrict__ hid,
                              const float* __restrict__ W2,
                              const float* __restrict__ b2,
                              float* __restrict__ out)
{
    int id = blockIdx.x * blockDim.x + threadIdx.x;
    if (id >= Bz * NC) return;
    int b = id / NC, c = id % NC;
    float acc = b2[c];
    const float* hp = hid + b * (DM / 2);
    for (int k = 0; k < DM / 2; ++k) acc += hp[k] * W2[k * NC + c];
    out[id] = acc;
}

// ---------------- launch ----------------
extern "C" void kernel_launch(void* const* d_in, const int* in_sizes, int n_in,
                              void* d_out, int out_size)
{
    const float* x      = (const float*)d_in[0];
    const float* pw     = (const float*)d_in[1];
    const float* pb     = (const float*)d_in[2];
    const float* pos    = (const float*)d_in[3];
    const float* Win    = (const float*)d_in[4];
    const float* conv_w = (const float*)d_in[5];
    const float* conv_b = (const float*)d_in[6];
    const float* Wx     = (const float*)d_in[7];
    const float* Wdt    = (const float*)d_in[8];
    const float* bdt    = (const float*)d_in[9];
    const float* A_log  = (const float*)d_in[10];
    const float* Dp     = (const float*)d_in[11];
    const float* Wout   = (const float*)d_in[12];
    const float* ln_g   = (const float*)d_in[13];
    const float* ln_b   = (const float*)d_in[14];
    const float* norm_g = (const float*)d_in[15];
    const float* norm_b = (const float*)d_in[16];
    const float* W1     = (const float*)d_in[17];
    const float* b1     = (const float*)d_in[18];
    const float* W2     = (const float*)d_in[19];
    const float* b2     = (const float*)d_in[20];

    float *h, *xz, *xc, *dbc, *dbcp, *dt, *pool, *hid;
    bf16 *lnH, *lnL, *yH, *yL, *WinH, *WinL, *WoutH, *WoutL;
    cudaGetSymbolAddress((void**)&h,    g_h);
    cudaGetSymbolAddress((void**)&xz,   g_xz);
    cudaGetSymbolAddress((void**)&xc,   g_xc);
    cudaGetSymbolAddress((void**)&dbc,  g_dbc);
    cudaGetSymbolAddress((void**)&dbcp, g_dbcp);
    cudaGetSymbolAddress((void**)&dt,   g_dt);
    cudaGetSymbolAddress((void**)&pool, g_pool);
    cudaGetSymbolAddress((void**)&hid,  g_hid);
    cudaGetSymbolAddress((void**)&lnH,  g_lnH);
    cudaGetSymbolAddress((void**)&lnL,  g_lnL);
    cudaGetSymbolAddress((void**)&yH,   g_yH);
    cudaGetSymbolAddress((void**)&yL,   g_yL);
    cudaGetSymbolAddress((void**)&WinH, g_WinH);
    cudaGetSymbolAddress((void**)&WinL, g_WinL);
    cudaGetSymbolAddress((void**)&WoutH, g_WoutH);
    cudaGetSymbolAddress((void**)&WoutL, g_WoutL);

    // weight prep: W^T bf16 hi/lo
    prep_w_kernel<<<dim3(64, 16, NL), 256>>>(Win,  WinH,  WinL,  DM, 2 * DI);
    prep_w_kernel<<<dim3(16, 32, NL), 256>>>(Wout, WoutH, WoutL, DI, DM);

    patch_kernel<<<BL, DM>>>(x, pw, pb, pos, h);

    for (int i = 0; i < NL; ++i) {
        layernorm_bf_kernel<<<BL, DM>>>(h, lnH, lnL, ln_g + i * DM, ln_b + i * DM);

        // xz = ln @ Win[i]   [6272,512]@[512,2048] — tensor cores
        gemm_mma_kernel<0><<<dim3(16, 49), 256>>>(
            lnH, lnL, DM,
            WinH + (size_t)i * 2 * DI * DM, WinL + (size_t)i * 2 * DI * DM,
            xz, 2 * DI, DM);

        conv_silu_kernel<<<(BL * DI / 4 + 255) / 256, 256>>>(
            xz, conv_w + (size_t)i * DI * DC, conv_b + (size_t)i * DI, xc);

        // dbc = xc @ Wx[i]  split-K x4 SIMT
        gemm2_kernel<64, 0><<<dim3(1, 49, 4), 256>>>(
            xc, DI, Wx + (size_t)i * DI * 64, 64,
            dbcp, 64, DI / 4, nullptr, (size_t)BL * 64);
        reduce4_kernel<<<(BL * 64 / 4 + 255) / 256, 256>>>(dbcp, dbc);

        // dt = softplus(dt_lo @ Wdt[i] + bdt[i]) SIMT
        gemm2_kernel<128, 2><<<dim3(8, 49), 256>>>(
            dbc, 64, Wdt + (size_t)i * DTR * DI, DI,
            dt, DI, DTR, bdt + (size_t)i * DI, 0);

        scan_kernel<<<dim3(Bz, DI / 256), 256>>>(
            xc, dt, dbc, xz,
            A_log + (size_t)i * DI * DS, Dp + (size_t)i * DI, yH, yL);

        // h += y @ Wout[i]   [6272,1024]@[1024,512] — tensor cores
        gemm_mma_kernel<1><<<dim3(4, 49), 256>>>(
            yH, yL, DI,
            WoutH + (size_t)i * DM * DI, WoutL + (size_t)i * DM * DI,
            h, DM, DI);
    }

    pool_ln_kernel<<<Bz, DM>>>(h, pool, norm_g, norm_b);

    gemm2_kernel<128, 3><<<dim3(2, 1), 256>>>(
        pool, DM, W1, DM / 2, hid, DM / 2, DM, b1, 0);

    logits_kernel<<<(Bz * NC + 255) / 256, 256>>>(hid, W2, b2, (float*)d_out);
}

// round 5
// speedup vs baseline: 1.8750x; 1.2193x over previous
#include <cuda_runtime.h>
#include <cuda_bf16.h>
#include <math.h>
#include <stdint.h>

// ---------------- Problem constants ----------------
#define Bz 128
#define IMG 28
#define GRID7 7
#define L 49
#define DM 512
#define NL 8
#define DS 16
#define DC 4
#define DI 1024
#define DTR 32
#define NC 10
#define BL (Bz * L)          // 6272

typedef unsigned long long ull;
typedef __nv_bfloat16 bf16;

// ================= helpers =================
__device__ __forceinline__ uint32_t s2u(const void* p) {
    uint32_t a;
    asm("{ .reg .u64 t; cvta.to.shared.u64 t, %1; cvt.u32.u64 %0, t; }" : "=r"(a) : "l"(p));
    return a;
}
__device__ __forceinline__ void cpa16(uint32_t s, const void* g) {
    asm volatile("cp.async.cg.shared.global [%0], [%1], 16;" :: "r"(s), "l"(g));
}
__device__ __forceinline__ void cp_commit() {
    asm volatile("cp.async.commit_group;" ::: "memory");
}
__device__ __forceinline__ void ldsm4(uint32_t& r0, uint32_t& r1, uint32_t& r2, uint32_t& r3, uint32_t addr) {
    asm volatile("ldmatrix.sync.aligned.m8n8.x4.shared.b16 {%0,%1,%2,%3}, [%4];"
                 : "=r"(r0), "=r"(r1), "=r"(r2), "=r"(r3) : "r"(addr));
}
__device__ __forceinline__ void ldsm2(uint32_t& r0, uint32_t& r1, uint32_t addr) {
    asm volatile("ldmatrix.sync.aligned.m8n8.x2.shared.b16 {%0,%1}, [%2];"
                 : "=r"(r0), "=r"(r1) : "r"(addr));
}
__device__ __forceinline__ void mma16816(float* c, const uint32_t* a, const uint32_t* b) {
    asm volatile("mma.sync.aligned.m16n8k16.row.col.f32.bf16.bf16.f32 "
                 "{%0,%1,%2,%3}, {%4,%5,%6,%7}, {%8,%9}, {%0,%1,%2,%3};"
                 : "+f"(c[0]), "+f"(c[1]), "+f"(c[2]), "+f"(c[3])
                 : "r"(a[0]), "r"(a[1]), "r"(a[2]), "r"(a[3]), "r"(b[0]), "r"(b[1]));
}
// FFMA2 helpers (SIMT gemm)
__device__ __forceinline__ ull pack2(float lo, float hi) {
    ull r; asm("mov.b64 %0, {%1, %2};" : "=l"(r) : "f"(lo), "f"(hi)); return r;
}
__device__ __forceinline__ void unpack2(ull v, float& lo, float& hi) {
    asm("mov.b64 {%0, %1}, %2;" : "=f"(lo), "=f"(hi) : "l"(v));
}
__device__ __forceinline__ void fma2(ull& d, ull a, ull b) {
    asm("fma.rn.f32x2 %0, %1, %2, %0;" : "+l"(d) : "l"(a), "l"(b));
}
__device__ __forceinline__ void hilo(float v, bf16& h, bf16& l) {
    h = __float2bfloat16(v);
    l = __float2bfloat16(v - __bfloat162float(h));
}

// ---------------- Scratch ----------------
__device__ float g_h   [BL * DM];
__device__ float g_xz  [BL * 2 * DI];
__device__ float g_xc  [BL * DI];
__device__ float g_dbc [BL * 64];
__device__ float g_dbcp[4 * BL * 64];
__device__ float g_dt  [BL * DI];
__device__ float g_pool[Bz * DM];
__device__ float g_hid [Bz * (DM / 2)];
__device__ bf16  g_lnH [BL * DM];
__device__ bf16  g_lnL [BL * DM];
__device__ bf16  g_xcH [BL * DI];
__device__ bf16  g_xcL [BL * DI];
__device__ bf16  g_yH  [BL * DI];
__device__ bf16  g_yL  [BL * DI];
__device__ bf16  g_WinH [NL * 2 * DI * DM];
__device__ bf16  g_WinL [NL * 2 * DI * DM];
__device__ bf16  g_WoutH[NL * DM * DI];
__device__ bf16  g_WoutL[NL * DM * DI];
__device__ bf16  g_WxH  [NL * 64 * DI];
__device__ bf16  g_WxL  [NL * 64 * DI];

// ---------------- Patch embed + pos ----------------
__global__ void patch_kernel(const float* __restrict__ x,
                             const float* __restrict__ pw,
                             const float* __restrict__ pb,
                             const float* __restrict__ pos,
                             float* __restrict__ out)
{
    int bl = blockIdx.x;
    int b = bl / L, l = bl % L;
    int gr = l / GRID7, gc = l % GRID7;
    __shared__ float p[16];
    int t = threadIdx.x;
    if (t < 16) {
        int pr = t / 4, pc = t % 4;
        p[t] = x[b * (IMG * IMG) + (gr * 4 + pr) * IMG + gc * 4 + pc];
    }
    __syncthreads();
    float acc = pb[t] + pos[l * DM + t];
    const float* w = pw + t * 16;
#pragma unroll
    for (int k = 0; k < 16; ++k) acc += p[k] * w[k];
    out[bl * DM + t] = acc;
}

// ---------------- weight prep: W[K,N] -> W^T hi/lo bf16 [N][K] ----------------
__global__ void prep_w_kernel(const float* __restrict__ W,
                              bf16* __restrict__ outH, bf16* __restrict__ outL,
                              int K, int N)
{
    __shared__ float sm[32][33];
    int n0 = blockIdx.x * 32, k0 = blockIdx.y * 32, l = blockIdx.z;
    const float* Wl = W + (size_t)l * K * N;
    bf16* oH = outH + (size_t)l * N * K;
    bf16* oL = outL + (size_t)l * N * K;
    int tid = threadIdx.x;
#pragma unroll
    for (int i = 0; i < 4; ++i) {
        int idx = tid + i * 256;
        int kk = idx >> 5, nn = idx & 31;
        sm[kk][nn] = Wl[(size_t)(k0 + kk) * N + n0 + nn];
    }
    __syncthreads();
#pragma unroll
    for (int i = 0; i < 4; ++i) {
        int idx = tid + i * 256;
        int nn = idx >> 5, kk = idx & 31;
        bf16 h, lo; hilo(sm[kk][nn], h, lo);
        size_t o = (size_t)(n0 + nn) * K + k0 + kk;
        oH[o] = h; oL[o] = lo;
    }
}

// ---------------- LayerNorm -> bf16 hi/lo ----------------
__global__ void layernorm_bf_kernel(const float* __restrict__ in,
                                    bf16* __restrict__ oH, bf16* __restrict__ oL,
                                    const float* __restrict__ g,
                                    const float* __restrict__ b)
{
    __shared__ float ws[16], ws2[16];
    int r = blockIdx.x;
    int t = threadIdx.x;           // 512
    float v = in[(size_t)r * DM + t];
    float s = v, s2 = v * v;
#pragma unroll
    for (int o = 16; o; o >>= 1) {
        s  += __shfl_xor_sync(0xffffffffu, s,  o);
        s2 += __shfl_xor_sync(0xffffffffu, s2, o);
    }
    if ((t & 31) == 0) { ws[t >> 5] = s; ws2[t >> 5] = s2; }
    __syncthreads();
    if (t < 32) {
        float a  = (t < 16) ? ws[t]  : 0.0f;
        float a2 = (t < 16) ? ws2[t] : 0.0f;
#pragma unroll
        for (int o = 8; o; o >>= 1) {
            a  += __shfl_xor_sync(0xffffffffu, a,  o);
            a2 += __shfl_xor_sync(0xffffffffu, a2, o);
        }
        if (t == 0) { ws[0] = a; ws2[0] = a2; }
    }
    __syncthreads();
    float mean = ws[0] * (1.0f / DM);
    float var  = ws2[0] * (1.0f / DM) - mean * mean;
    float nv = (v - mean) * rsqrtf(var + 1e-5f) * g[t] + b[t];
    bf16 h, lo; hilo(nv, h, lo);
    oH[(size_t)r * DM + t] = h;
    oL[(size_t)r * DM + t] = lo;
}

// ---------------- tensor-core GEMM (cp.async double-buffered, 3-term bf16 hi/lo) ----------------
// C[M, N] = A[M,K+] @ B^T[N,K+];  CTA tile 128 x BN, 8 warps (2 x 4), warp tile 64 x BN/4.
// EPI: 0 = store, 1 = C += acc.  blockIdx.z = split-K slice (A,B col offset z*K; C += z*splitStride)
#define SSTR 40   // smem row stride in bf16 (32 + 8 pad); 80B, 16B-aligned, ldmatrix conflict-free

template <int BN, int EPI>
__global__ __launch_bounds__(256) void gemm_mma2_kernel(
    const bf16* __restrict__ Ah, const bf16* __restrict__ Al, int lda,
    const bf16* __restrict__ Bh, const bf16* __restrict__ Bl, int ldb,
    float* __restrict__ C, int ldc, int K, size_t splitStride)
{
    constexpr int NI = BN / 32;            // per-warp 8-col tiles
    constexpr int A_SZ = 128 * SSTR;
    constexpr int B_SZ = BN * SSTR;
    constexpr int STAGE = 2 * A_SZ + 2 * B_SZ;
    extern __shared__ bf16 dsm[];

    int tid = threadIdx.x;
    int wid = tid >> 5, lane = tid & 31;
    int rb = blockIdx.y, nb = blockIdx.x, z = blockIdx.z;
    int warp_m = wid >> 2;
    int warp_n = wid & 3;

    const bf16* gAh = Ah + (size_t)(rb * 128) * lda + (size_t)z * K;
    const bf16* gAl = Al + (size_t)(rb * 128) * lda + (size_t)z * K;
    const bf16* gBh = Bh + (size_t)(nb * BN) * ldb + (size_t)z * K;
    const bf16* gBl = Bl + (size_t)(nb * BN) * ldb + (size_t)z * K;
    C += (size_t)z * splitStride;

    float acc[4][NI][4];
#pragma unroll
    for (int mi = 0; mi < 4; ++mi)
#pragma unroll
        for (int ni = 0; ni < NI; ++ni)
#pragma unroll
            for (int q = 0; q < 4; ++q) acc[mi][ni][q] = 0.0f;

    int a_m = (lane & 7) + ((lane & 8) ? 8 : 0);
    int a_k = (lane & 16) ? 8 : 0;
    int b_n = lane & 7;
    int b_k = (lane & 8) ? 8 : 0;

    int NCH = K / 32;

    // issue chunk loads into stage s
    auto load_chunk = [&](int k0, int s) {
        bf16* sA_h = dsm + s * STAGE;
        bf16* sA_l = sA_h + A_SZ;
        bf16* sB_h = sA_l + A_SZ;
        bf16* sB_l = sB_h + B_SZ;
#pragma unroll
        for (int i = 0; i < 2; ++i) {
            int idx = tid + i * 256;           // 0..511
            int r = idx >> 2, sg = idx & 3;
            int so = r * SSTR + sg * 8;
            size_t go = (size_t)r * lda + k0 + sg * 8;
            cpa16(s2u(sA_h + so), gAh + go);
            cpa16(s2u(sA_l + so), gAl + go);
        }
#pragma unroll
        for (int i = 0; i < BN / 64; ++i) {
            int idx = tid + i * 256;           // 0..BN*4-1
            int r = idx >> 2, sg = idx & 3;
            int so = r * SSTR + sg * 8;
            size_t go = (size_t)r * ldb + k0 + sg * 8;
            cpa16(s2u(sB_h + so), gBh + go);
            cpa16(s2u(sB_l + so), gBl + go);
        }
        cp_commit();
    };

    load_chunk(0, 0);

    for (int c = 0; c < NCH; ++c) {
        if (c + 1 < NCH) {
            load_chunk((c + 1) * 32, (c + 1) & 1);
            asm volatile("cp.async.wait_group 1;" ::: "memory");
        } else {
            asm volatile("cp.async.wait_group 0;" ::: "memory");
        }
        __syncthreads();

        bf16* sA_h = dsm + (c & 1) * STAGE;
        bf16* sA_l = sA_h + A_SZ;
        bf16* sB_h = sA_l + A_SZ;
        bf16* sB_l = sB_h + B_SZ;
        uint32_t uAh = s2u(sA_h), uAl = s2u(sA_l), uBh = s2u(sB_h), uBl = s2u(sB_l);

#pragma unroll
        for (int ks = 0; ks < 2; ++ks) {
            int kk = ks * 16;
            uint32_t bh[NI][2], blr[NI][2];
#pragma unroll
            for (int ni = 0; ni < NI; ++ni) {
                int row = warp_n * (BN / 4) + ni * 8 + b_n;
                uint32_t off = (uint32_t)(row * SSTR + kk + b_k) * 2;
                ldsm2(bh[ni][0],  bh[ni][1],  uBh + off);
                ldsm2(blr[ni][0], blr[ni][1], uBl + off);
            }
#pragma unroll
            for (int mi = 0; mi < 4; ++mi) {
                int row = warp_m * 64 + mi * 16 + a_m;
                uint32_t off = (uint32_t)(row * SSTR + kk + a_k) * 2;
                uint32_t ah[4], al[4];
                ldsm4(ah[0], ah[1], ah[2], ah[3], uAh + off);
                ldsm4(al[0], al[1], al[2], al[3], uAl + off);
#pragma unroll
                for (int ni = 0; ni < NI; ++ni) {
                    mma16816(acc[mi][ni], ah, bh[ni]);
                    mma16816(acc[mi][ni], ah, blr[ni]);
                    mma16816(acc[mi][ni], al, bh[ni]);
                }
            }
        }
        __syncthreads();
    }

    // epilogue
    int g = lane >> 2, cpair = (lane & 3) * 2;
#pragma unroll
    for (int mi = 0; mi < 4; ++mi) {
        int r0 = rb * 128 + warp_m * 64 + mi * 16 + g;
        int r1 = r0 + 8;
#pragma unroll
        for (int ni = 0; ni < NI; ++ni) {
            int col = nb * BN + warp_n * (BN / 4) + ni * 8 + cpair;
            float* c0 = C + (size_t)r0 * ldc + col;
            float* c1 = C + (size_t)r1 * ldc + col;
            if (EPI == 0) {
                *(float2*)c0 = make_float2(acc[mi][ni][0], acc[mi][ni][1]);
                *(float2*)c1 = make_float2(acc[mi][ni][2], acc[mi][ni][3]);
            } else {
                float2 o0 = *(float2*)c0, o1 = *(float2*)c1;
                o0.x += acc[mi][ni][0]; o0.y += acc[mi][ni][1];
                o1.x += acc[mi][ni][2]; o1.y += acc[mi][ni][3];
                *(float2*)c0 = o0;
                *(float2*)c1 = o1;
            }
        }
    }
}

#define SMEM_MMA_128 (2 * (2 * 128 * SSTR + 2 * 128 * SSTR) * 2)   // 81920 B
#define SMEM_MMA_64  (2 * (2 * 128 * SSTR + 2 * 64  * SSTR) * 2)   // 61440 B

// ---------------- SIMT FFMA2 GEMM (small GEMMs) ----------------
template <int BN_T, int EPI>
__global__ __launch_bounds__(256) void gemm2_kernel(
    const float* __restrict__ A, int lda,
    const float* __restrict__ Bm_, int ldb,
    float* __restrict__ C, int ldc,
    int K, const float* __restrict__ bias, size_t splitC_stride)
{
    constexpr int TN = BN_T / 16;
    __shared__ float As[16][130];
    __shared__ float Bs[16][BN_T];

    int tid = threadIdx.x;
    int bm = blockIdx.y * 128;
    int bn = blockIdx.x * BN_T;
    int z  = blockIdx.z;
    A   += (size_t)z * K;
    Bm_ += (size_t)z * K * ldb;
    C   += (size_t)z * splitC_stride;

    int m_a = tid >> 1, k_a = (tid & 1) * 8;
    int k_b = tid >> 4;
    int n_b = (tid & 15) * TN;
    int tx = tid & 15, ty = tid >> 4;

    ull acc[4][TN];
#pragma unroll
    for (int p = 0; p < 4; ++p)
#pragma unroll
        for (int j = 0; j < TN; ++j) acc[p][j] = 0ull;

    const float* Aptr = A + (size_t)(bm + m_a) * lda + k_a;
    const float* Bptr = Bm_ + (size_t)k_b * ldb + bn + n_b;

    float4 ra0 = *(const float4*)(Aptr);
    float4 ra1 = *(const float4*)(Aptr + 4);
    float4 rb0 = *(const float4*)(Bptr);
    float4 rb1;
    if constexpr (TN == 8) rb1 = *(const float4*)(Bptr + 4);

    int ntiles = K / 16;
    for (int kt = 0; kt < ntiles; ++kt) {
        As[k_a + 0][m_a] = ra0.x; As[k_a + 1][m_a] = ra0.y;
        As[k_a + 2][m_a] = ra0.z; As[k_a + 3][m_a] = ra0.w;
        As[k_a + 4][m_a] = ra1.x; As[k_a + 5][m_a] = ra1.y;
        As[k_a + 6][m_a] = ra1.z; As[k_a + 7][m_a] = ra1.w;
        *(float4*)&Bs[k_b][n_b] = rb0;
        if constexpr (TN == 8) *(float4*)&Bs[k_b][n_b + 4] = rb1;
        __syncthreads();

        if (kt + 1 < ntiles) {
            const float* Ap = Aptr + (kt + 1) * 16;
            ra0 = *(const float4*)(Ap);
            ra1 = *(const float4*)(Ap + 4);
            const float* Bp = Bptr + (size_t)(kt + 1) * 16 * ldb;
            rb0 = *(const float4*)(Bp);
            if constexpr (TN == 8) rb1 = *(const float4*)(Bp + 4);
        }

#pragma unroll
        for (int kk = 0; kk < 16; ++kk) {
            ull a2[4];
            const ull* ap = (const ull*)&As[kk][ty * 8];
            a2[0] = ap[0]; a2[1] = ap[1]; a2[2] = ap[2]; a2[3] = ap[3];
            float bf[TN];
            {
                float4 t0 = *(const float4*)&Bs[kk][tx * TN];
                bf[0] = t0.x; bf[1] = t0.y; bf[2] = t0.z; bf[3] = t0.w;
                if constexpr (TN == 8) {
                    float4 t1 = *(const float4*)&Bs[kk][tx * TN + 4];
                    bf[4] = t1.x; bf[5] = t1.y; bf[6] = t1.z; bf[7] = t1.w;
                }
            }
#pragma unroll
            for (int j = 0; j < TN; ++j) {
                ull bb = pack2(bf[j], bf[j]);
#pragma unroll
                for (int p = 0; p < 4; ++p) fma2(acc[p][j], a2[p], bb);
            }
        }
        __syncthreads();
    }

    float cf[8][TN];
#pragma unroll
    for (int p = 0; p < 4; ++p)
#pragma unroll
        for (int j = 0; j < TN; ++j) unpack2(acc[p][j], cf[2 * p][j], cf[2 * p + 1][j]);

#pragma unroll
    for (int i = 0; i < 8; ++i) {
        int m = bm + ty * 8 + i;
        float* cp = C + (size_t)m * ldc + bn + tx * TN;
        if (EPI == 0) {
#pragma unroll
            for (int j = 0; j < TN; j += 4)
                *(float4*)(cp + j) = make_float4(cf[i][j], cf[i][j + 1], cf[i][j + 2], cf[i][j + 3]);
        } else if (EPI == 1) {
#pragma unroll
            for (int j = 0; j < TN; j += 4) {
                float4 o = *(const float4*)(cp + j);
                o.x += cf[i][j]; o.y += cf[i][j + 1]; o.z += cf[i][j + 2]; o.w += cf[i][j + 3];
                *(float4*)(cp + j) = o;
            }
        } else if (EPI == 2) {
#pragma unroll
            for (int j = 0; j < TN; ++j) {
                float v = cf[i][j] + bias[bn + tx * TN + j];
                cp[j] = fmaxf(v, 0.0f) + log1pf(__expf(-fabsf(v)));
            }
        } else {
#pragma unroll
            for (int j = 0; j < TN; ++j) {
                float v = cf[i][j] + bias[bn + tx * TN + j];
                cp[j] = 0.5f * v * (1.0f + erff(v * 0.70710678118654752f));
            }
        }
    }
}

// ---------------- split-K reduce ----------------
__global__ void reduce4_kernel(const float* __restrict__ p, float* __restrict__ out)
{
    int i = blockIdx.x * 256 + threadIdx.x;
    const int n4 = BL * 64 / 4;
    if (i >= n4) return;
    const float4* p4 = (const float4*)p;
    float4 a = p4[i], b = p4[i + n4], c = p4[i + 2 * n4], d = p4[i + 3 * n4];
    a.x += b.x + c.x + d.x; a.y += b.y + c.y + d.y;
    a.z += b.z + c.z + d.z; a.w += b.w + c.w + d.w;
    ((float4*)out)[i] = a;
}

// ---------------- causal conv1d + silu -> fp32 + bf16 hi/lo ----------------
__global__ void conv_silu_kernel(const float* __restrict__ xz,
                                 const float* __restrict__ w,
                                 const float* __restrict__ cb,
                                 float* __restrict__ out,
                                 bf16* __restrict__ oH, bf16* __restrict__ oL)
{
    int id = blockIdx.x * 256 + threadIdx.x;
    if (id >= BL * DI / 4) return;
    int dq = id % (DI / 4);
    int bl = id / (DI / 4);
    int d = dq * 4;
    int t = bl % L;
    int b = bl / L;
    float4 w0 = ((const float4*)w)[d + 0];
    float4 w1 = ((const float4*)w)[d + 1];
    float4 w2 = ((const float4*)w)[d + 2];
    float4 w3 = ((const float4*)w)[d + 3];
    float4 acc = *(const float4*)&cb[d];
    const float* base = xz + (size_t)(b * L) * (2 * DI) + d;
    if (t - 3 >= 0) {
        float4 xv = *(const float4*)(base + (size_t)(t - 3) * (2 * DI));
        acc.x += w0.x * xv.x; acc.y += w1.x * xv.y; acc.z += w2.x * xv.z; acc.w += w3.x * xv.w;
    }
    if (t - 2 >= 0) {
        float4 xv = *(const float4*)(base + (size_t)(t - 2) * (2 * DI));
        acc.x += w0.y * xv.x; acc.y += w1.y * xv.y; acc.z += w2.y * xv.z; acc.w += w3.y * xv.w;
    }
    if (t - 1 >= 0) {
        float4 xv = *(const float4*)(base + (size_t)(t - 1) * (2 * DI));
        acc.x += w0.z * xv.x; acc.y += w1.z * xv.y; acc.z += w2.z * xv.z; acc.w += w3.z * xv.w;
    }
    {
        float4 xv = *(const float4*)(base + (size_t)t * (2 * DI));
        acc.x += w0.w * xv.x; acc.y += w1.w * xv.y; acc.z += w2.w * xv.z; acc.w += w3.w * xv.w;
    }
    acc.x = acc.x / (1.0f + __expf(-acc.x));
    acc.y = acc.y / (1.0f + __expf(-acc.y));
    acc.z = acc.z / (1.0f + __expf(-acc.z));
    acc.w = acc.w / (1.0f + __expf(-acc.w));
    size_t o = (size_t)bl * DI + d;
    *(float4*)&out[o] = acc;
    union { bf16 v[4]; uint2 u; } ph, pl;
    hilo(acc.x, ph.v[0], pl.v[0]);
    hilo(acc.y, ph.v[1], pl.v[1]);
    hilo(acc.z, ph.v[2], pl.v[2]);
    hilo(acc.w, ph.v[3], pl.v[3]);
    *(uint2*)&oH[o] = ph.u;
    *(uint2*)&oL[o] = pl.u;
}

// ---------------- selective scan + gate -> bf16 hi/lo y ----------------
__global__ void scan_kernel(const float* __restrict__ xc,
                            const float* __restrict__ dt,
                            const float* __restrict__ dbc,
                            const float* __restrict__ xz,
                            const float* __restrict__ A_log,
                            const float* __restrict__ Dp,
                            bf16* __restrict__ yH, bf16* __restrict__ yL)
{
    int bb = blockIdx.x;
    int d = blockIdx.y * 256 + threadIdx.x;
    float A[DS], h[DS];
#pragma unroll
    for (int n = 0; n < DS; ++n) { A[n] = -__expf(A_log[d * DS + n]); h[n] = 0.0f; }
    float Dpd = Dp[d];
    __shared__ float Bs[DS], Cs[DS];
    for (int t = 0; t < L; ++t) {
        __syncthreads();
        if (threadIdx.x < 32) {
            int n = threadIdx.x;
            float v = dbc[(size_t)(bb * L + t) * 64 + 32 + n];
            if (n < DS) Bs[n] = v; else Cs[n - DS] = v;
        }
        __syncthreads();
        size_t idx = (size_t)(bb * L + t) * DI + d;
        float dtv = dt[idx];
        float xv  = xc[idx];
        float dx  = dtv * xv;
        float yv = 0.0f;
#pragma unroll
        for (int n = 0; n < DS; ++n) {
            float dA = __expf(dtv * A[n]);
            h[n] = dA * h[n] + dx * Bs[n];
            yv += h[n] * Cs[n];
        }
        yv += Dpd * xv;
        float z = xz[(size_t)(bb * L + t) * (2 * DI) + DI + d];
        yv *= z / (1.0f + __expf(-z));
        bf16 hh, ll; hilo(yv, hh, ll);
        yH[idx] = hh;
        yL[idx] = ll;
    }
}

// ---------------- mean-pool over L + LayerNorm ----------------
__global__ void pool_ln_kernel(const float* __restrict__ hin,
                               float* __restrict__ out,
                               const float* __restrict__ g,
                               const float* __restrict__ b)
{
    __shared__ float ws[16], ws2[16];
    int bb = blockIdx.x;
    int t = threadIdx.x;
    float s = 0.0f;
    for (int tt = 0; tt < L; ++tt) s += hin[(size_t)(bb * L + tt) * DM + t];
    float v = s * (1.0f / L);
    float sm = v, s2 = v * v;
#pragma unroll
    for (int o = 16; o; o >>= 1) {
        sm += __shfl_xor_sync(0xffffffffu, sm, o);
        s2 += __shfl_xor_sync(0xffffffffu, s2, o);
    }
    if ((t & 31) == 0) { ws[t >> 5] = sm; ws2[t >> 5] = s2; }
    __syncthreads();
    if (t < 32) {
        float a  = (t < 16) ? ws[t]  : 0.0f;
        float a2 = (t < 16) ? ws2[t] : 0.0f;
#pragma unroll
        for (int o = 8; o; o >>= 1) {
            a  += __shfl_xor_sync(0xffffffffu, a,  o);
            a2 += __shfl_xor_sync(0xffffffffu, a2, o);
        }
        if (t == 0) { ws[0] = a; ws2[0] = a2; }
    }
    __syncthreads();
    float mean = ws[0] * (1.0f / DM);
    float var  = ws2[0] * (1.0f / DM) - mean * mean;
    out[bb * DM + t] = (v - mean) * rsqrtf(var + 1e-5f) * g[t] + b[t];
}

// ---------------- final logits ----------------
__global__ void logits_kernel(const float* __restrict__ hid,
                              const float* __restrict__ W2,
                              const float* __restrict__ b2,
                              float* __restrict__ out)
{
    int id = blockIdx.x * blockDim.x + threadIdx.x;
    if (id >= Bz * NC) return;
    int b = id / NC, c = id % NC;
    float acc = b2[c];
    const float* hp = hid + b * (DM / 2);
    for (int k = 0; k < DM / 2; ++k) acc += hp[k] * W2[k * NC + c];
    out[id] = acc;
}

// ---------------- launch ----------------
extern "C" void kernel_launch(void* const* d_in, const int* in_sizes, int n_in,
                              void* d_out, int out_size)
{
    const float* x      = (const float*)d_in[0];
    const float* pw     = (const float*)d_in[1];
    const float* pb     = (const float*)d_in[2];
    const float* pos    = (const float*)d_in[3];
    const float* Win    = (const float*)d_in[4];
    const float* conv_w = (const float*)d_in[5];
    const float* conv_b = (const float*)d_in[6];
    const float* Wx     = (const float*)d_in[7];
    const float* Wdt    = (const float*)d_in[8];
    const float* bdt    = (const float*)d_in[9];
    const float* A_log  = (const float*)d_in[10];
    const float* Dp     = (const float*)d_in[11];
    const float* Wout   = (const float*)d_in[12];
    const float* ln_g   = (const float*)d_in[13];
    const float* ln_b   = (const float*)d_in[14];
    const float* norm_g = (const float*)d_in[15];
    const float* norm_b = (const float*)d_in[16];
    const float* W1     = (const float*)d_in[17];
    const float* b1     = (const float*)d_in[18];
    const float* W2     = (const float*)d_in[19];
    const float* b2     = (const float*)d_in[20];

    float *h, *xz, *xc, *dbc, *dbcp, *dt, *pool, *hid;
    bf16 *lnH, *lnL, *xcH, *xcL, *yH, *yL, *WinH, *WinL, *WoutH, *WoutL, *WxH, *WxL;
    cudaGetSymbolAddress((void**)&h,    g_h);
    cudaGetSymbolAddress((void**)&xz,   g_xz);
    cudaGetSymbolAddress((void**)&xc,   g_xc);
    cudaGetSymbolAddress((void**)&dbc,  g_dbc);
    cudaGetSymbolAddress((void**)&dbcp, g_dbcp);
    cudaGetSymbolAddress((void**)&dt,   g_dt);
    cudaGetSymbolAddress((void**)&pool, g_pool);
    cudaGetSymbolAddress((void**)&hid,  g_hid);
    cudaGetSymbolAddress((void**)&lnH,  g_lnH);
    cudaGetSymbolAddress((void**)&lnL,  g_lnL);
    cudaGetSymbolAddress((void**)&xcH,  g_xcH);
    cudaGetSymbolAddress((void**)&xcL,  g_xcL);
    cudaGetSymbolAddress((void**)&yH,   g_yH);
    cudaGetSymbolAddress((void**)&yL,   g_yL);
    cudaGetSymbolAddress((void**)&WinH, g_WinH);
    cudaGetSymbolAddress((void**)&WinL, g_WinL);
    cudaGetSymbolAddress((void**)&WoutH, g_WoutH);
    cudaGetSymbolAddress((void**)&WoutL, g_WoutL);
    cudaGetSymbolAddress((void**)&WxH,  g_WxH);
    cudaGetSymbolAddress((void**)&WxL,  g_WxL);

    // opt-in >48KB dynamic smem (skip during capture; attributes persist)
    cudaStreamCaptureStatus cst = cudaStreamCaptureStatusNone;
    cudaStreamIsCapturing(0, &cst);
    if (cst == cudaStreamCaptureStatusNone) {
        cudaFuncSetAttribute(gemm_mma2_kernel<128, 0>, cudaFuncAttributeMaxDynamicSharedMemorySize, SMEM_MMA_128);
        cudaFuncSetAttribute(gemm_mma2_kernel<128, 1>, cudaFuncAttributeMaxDynamicSharedMemorySize, SMEM_MMA_128);
        cudaFuncSetAttribute(gemm_mma2_kernel<64, 0>,  cudaFuncAttributeMaxDynamicSharedMemorySize, SMEM_MMA_64);
    }

    // weight prep: W^T bf16 hi/lo
    prep_w_kernel<<<dim3(64, 16, NL), 256>>>(Win,  WinH,  WinL,  DM, 2 * DI);
    prep_w_kernel<<<dim3(16, 32, NL), 256>>>(Wout, WoutH, WoutL, DI, DM);
    prep_w_kernel<<<dim3(2, 32, NL), 256>>>(Wx,   WxH,   WxL,   DI, 64);

    patch_kernel<<<BL, DM>>>(x, pw, pb, pos, h);

    for (int i = 0; i < NL; ++i) {
        layernorm_bf_kernel<<<BL, DM>>>(h, lnH, lnL, ln_g + i * DM, ln_b + i * DM);

        // xz = ln @ Win[i]   [6272,512]@[512,2048]
        gemm_mma2_kernel<128, 0><<<dim3(16, 49), 256, SMEM_MMA_128>>>(
            lnH, lnL, DM,
            WinH + (size_t)i * 2 * DI * DM, WinL + (size_t)i * 2 * DI * DM, DM,
            xz, 2 * DI, DM, 0);

        conv_silu_kernel<<<(BL * DI / 4 + 255) / 256, 256>>>(
            xz, conv_w + (size_t)i * DI * DC, conv_b + (size_t)i * DI, xc, xcH, xcL);

        // dbc = xc @ Wx[i]   [6272,1024]@[1024,64] — tensor, split-K x4
        gemm_mma2_kernel<64, 0><<<dim3(1, 49, 4), 256, SMEM_MMA_64>>>(
            xcH, xcL, DI,
            WxH + (size_t)i * 64 * DI, WxL + (size_t)i * 64 * DI, DI,
            dbcp, 64, DI / 4, (size_t)BL * 64);
        reduce4_kernel<<<(BL * 64 / 4 + 255) / 256, 256>>>(dbcp, dbc);

        // dt = softplus(dt_lo @ Wdt[i] + bdt[i])  SIMT (K=32)
        gemm2_kernel<128, 2><<<dim3(8, 49), 256>>>(
            dbc, 64, Wdt + (size_t)i * DTR * DI, DI,
            dt, DI, DTR, bdt + (size_t)i * DI, 0);

        scan_kernel<<<dim3(Bz, DI / 256), 256>>>(
            xc, dt, dbc, xz,
            A_log + (size_t)i * DI * DS, Dp + (size_t)i * DI, yH, yL);

        // h += y @ Wout[i]   [6272,1024]@[1024,512]
        gemm_mma2_kernel<128, 1><<<dim3(4, 49), 256, SMEM_MMA_128>>>(
            yH, yL, DI,
            WoutH + (size_t)i * DM * DI, WoutL + (size_t)i * DM * DI, DI,
            h, DM, DI, 0);
    }

    pool_ln_kernel<<<Bz, DM>>>(h, pool, norm_g, norm_b);

    gemm2_kernel<128, 3><<<dim3(2, 1), 256>>>(
        pool, DM, W1, DM / 2, hid, DM / 2, DM, b1, 0);

    logits_kernel<<<(Bz * NC + 255) / 256, 256>>>(hid, W2, b2, (float*)d_out);
}

// round 6
// speedup vs baseline: 2.3172x; 1.2358x over previous
#include <cuda_runtime.h>
#include <cuda_fp16.h>
#include <math.h>
#include <stdint.h>

// ---------------- Problem constants ----------------
#define Bz 128
#define IMG 28
#define GRID7 7
#define L 49
#define DM 512
#define NL 8
#define DS 16
#define DC 4
#define DI 1024
#define DTR 32
#define NC 10
#define BL (Bz * L)          // 6272

typedef unsigned long long ull;

// ================= helpers =================
__device__ __forceinline__ uint32_t s2u(const void* p) {
    uint32_t a;
    asm("{ .reg .u64 t; cvta.to.shared.u64 t, %1; cvt.u32.u64 %0, t; }" : "=r"(a) : "l"(p));
    return a;
}
__device__ __forceinline__ void cpa16(uint32_t s, const void* g) {
    asm volatile("cp.async.cg.shared.global [%0], [%1], 16;" :: "r"(s), "l"(g));
}
__device__ __forceinline__ void cp_commit() {
    asm volatile("cp.async.commit_group;" ::: "memory");
}
__device__ __forceinline__ void ldsm4(uint32_t& r0, uint32_t& r1, uint32_t& r2, uint32_t& r3, uint32_t addr) {
    asm volatile("ldmatrix.sync.aligned.m8n8.x4.shared.b16 {%0,%1,%2,%3}, [%4];"
                 : "=r"(r0), "=r"(r1), "=r"(r2), "=r"(r3) : "r"(addr));
}
__device__ __forceinline__ void ldsm2(uint32_t& r0, uint32_t& r1, uint32_t addr) {
    asm volatile("ldmatrix.sync.aligned.m8n8.x2.shared.b16 {%0,%1}, [%2];"
                 : "=r"(r0), "=r"(r1) : "r"(addr));
}
__device__ __forceinline__ void mma16816h(float* c, const uint32_t* a, const uint32_t* b) {
    asm volatile("mma.sync.aligned.m16n8k16.row.col.f32.f16.f16.f32 "
                 "{%0,%1,%2,%3}, {%4,%5,%6,%7}, {%8,%9}, {%0,%1,%2,%3};"
                 : "+f"(c[0]), "+f"(c[1]), "+f"(c[2]), "+f"(c[3])
                 : "r"(a[0]), "r"(a[1]), "r"(a[2]), "r"(a[3]), "r"(b[0]), "r"(b[1]));
}
// FFMA2 helpers (SIMT gemm)
__device__ __forceinline__ ull pack2(float lo, float hi) {
    ull r; asm("mov.b64 %0, {%1, %2};" : "=l"(r) : "f"(lo), "f"(hi)); return r;
}
__device__ __forceinline__ void unpack2(ull v, float& lo, float& hi) {
    asm("mov.b64 {%0, %1}, %2;" : "=f"(lo), "=f"(hi) : "l"(v));
}
__device__ __forceinline__ void fma2(ull& d, ull a, ull b) {
    asm("fma.rn.f32x2 %0, %1, %2, %0;" : "+l"(d) : "l"(a), "l"(b));
}
__device__ __forceinline__ void hiloh(float v, __half& h, __half& l) {
    h = __float2half_rn(v);
    l = __float2half_rn(v - __half2float(h));
}

// ---------------- Scratch ----------------
__device__ float  g_h   [BL * DM];
__device__ float  g_xz  [BL * 2 * DI];
__device__ float  g_xc  [BL * DI];
__device__ float  g_dbc [BL * 64];
__device__ float  g_dbcp[4 * BL * 64];
__device__ float  g_dt  [BL * DI];
__device__ float  g_pool[Bz * DM];
__device__ float  g_hid [Bz * (DM / 2)];
__device__ __half g_lnF [BL * DM];
__device__ __half g_xcF [BL * DI];
__device__ __half g_yF  [BL * DI];
__device__ __half g_WinH [NL * 2 * DI * DM];
__device__ __half g_WinL [NL * 2 * DI * DM];
__device__ __half g_WoutH[NL * DM * DI];
__device__ __half g_WoutL[NL * DM * DI];
__device__ __half g_WxH  [NL * 64 * DI];
__device__ __half g_WxL  [NL * 64 * DI];

// ---------------- Patch embed + pos (one block per image) ----------------
__global__ __launch_bounds__(512) void patch2_kernel(
    const float* __restrict__ x,
    const float* __restrict__ pw,
    const float* __restrict__ pb,
    const float* __restrict__ pos,
    float* __restrict__ out)
{
    __shared__ float img[IMG * IMG];
    int b = blockIdx.x;
    int t = threadIdx.x;           // 512 = output channel
    for (int i = t; i < IMG * IMG; i += 512) img[i] = x[b * (IMG * IMG) + i];
    float w[16];
#pragma unroll
    for (int k = 0; k < 16; ++k) w[k] = pw[t * 16 + k];
    float pbt = pb[t];
    __syncthreads();
    for (int l = 0; l < L; ++l) {
        int gr = l / GRID7, gc = l % GRID7;
        float acc = pbt + pos[l * DM + t];
#pragma unroll
        for (int pr = 0; pr < 4; ++pr)
#pragma unroll
            for (int pc = 0; pc < 4; ++pc)
                acc += img[(gr * 4 + pr) * IMG + gc * 4 + pc] * w[pr * 4 + pc];
        out[(size_t)(b * L + l) * DM + t] = acc;
    }
}

// ---------------- weight prep: W[K,N] -> W^T hi/lo fp16 [N][K] ----------------
__global__ void prep_w_kernel(const float* __restrict__ W,
                              __half* __restrict__ outH, __half* __restrict__ outL,
                              int K, int N)
{
    __shared__ float sm[32][33];
    int n0 = blockIdx.x * 32, k0 = blockIdx.y * 32, l = blockIdx.z;
    const float* Wl = W + (size_t)l * K * N;
    __half* oH = outH + (size_t)l * N * K;
    __half* oL = outL + (size_t)l * N * K;
    int tid = threadIdx.x;
#pragma unroll
    for (int i = 0; i < 4; ++i) {
        int idx = tid + i * 256;
        int kk = idx >> 5, nn = idx & 31;
        sm[kk][nn] = Wl[(size_t)(k0 + kk) * N + n0 + nn];
    }
    __syncthreads();
#pragma unroll
    for (int i = 0; i < 4; ++i) {
        int idx = tid + i * 256;
        int nn = idx >> 5, kk = idx & 31;
        __half h, lo; hiloh(sm[kk][nn], h, lo);
        size_t o = (size_t)(n0 + nn) * K + k0 + kk;
        oH[o] = h; oL[o] = lo;
    }
}

// ---------------- LayerNorm -> fp16 ----------------
__global__ void layernorm_f_kernel(const float* __restrict__ in,
                                   __half* __restrict__ oF,
                                   const float* __restrict__ g,
                                   const float* __restrict__ b)
{
    __shared__ float ws[16], ws2[16];
    int r = blockIdx.x;
    int t = threadIdx.x;           // 512
    float v = in[(size_t)r * DM + t];
    float s = v, s2 = v * v;
#pragma unroll
    for (int o = 16; o; o >>= 1) {
        s  += __shfl_xor_sync(0xffffffffu, s,  o);
        s2 += __shfl_xor_sync(0xffffffffu, s2, o);
    }
    if ((t & 31) == 0) { ws[t >> 5] = s; ws2[t >> 5] = s2; }
    __syncthreads();
    if (t < 32) {
        float a  = (t < 16) ? ws[t]  : 0.0f;
        float a2 = (t < 16) ? ws2[t] : 0.0f;
#pragma unroll
        for (int o = 8; o; o >>= 1) {
            a  += __shfl_xor_sync(0xffffffffu, a,  o);
            a2 += __shfl_xor_sync(0xffffffffu, a2, o);
        }
        if (t == 0) { ws[0] = a; ws2[0] = a2; }
    }
    __syncthreads();
    float mean = ws[0] * (1.0f / DM);
    float var  = ws2[0] * (1.0f / DM) - mean * mean;
    float nv = (v - mean) * rsqrtf(var + 1e-5f) * g[t] + b[t];
    oF[(size_t)r * DM + t] = __float2half_rn(nv);
}

// ---------------- tensor-core GEMM (fp16 A, fp16 hi/lo B, cp.async 2-stage) ----------------
// C[M,N] = A[M,K+] @ B^T[N,K+];  CTA tile 128 x BN, 8 warps (2 x 4), warp tile 64 x BN/4.
// EPI: 0 = store, 1 = C += acc.  blockIdx.z = split-K slice.
#define SSTR 40   // smem row stride in halves (32 + 8 pad)

template <int BN, int EPI>
__global__ __launch_bounds__(256) void gemm_mma2_kernel(
    const __half* __restrict__ A, int lda,
    const __half* __restrict__ Bh, const __half* __restrict__ Bl, int ldb,
    float* __restrict__ C, int ldc, int K, size_t splitStride)
{
    constexpr int NI = BN / 32;
    constexpr int A_SZ = 128 * SSTR;
    constexpr int B_SZ = BN * SSTR;
    constexpr int STAGE = A_SZ + 2 * B_SZ;
    extern __shared__ __half dsm[];

    int tid = threadIdx.x;
    int wid = tid >> 5, lane = tid & 31;
    int rb = blockIdx.y, nb = blockIdx.x, z = blockIdx.z;
    int warp_m = wid >> 2;
    int warp_n = wid & 3;

    const __half* gA  = A  + (size_t)(rb * 128) * lda + (size_t)z * K;
    const __half* gBh = Bh + (size_t)(nb * BN) * ldb + (size_t)z * K;
    const __half* gBl = Bl + (size_t)(nb * BN) * ldb + (size_t)z * K;
    C += (size_t)z * splitStride;

    float acc[4][NI][4];
#pragma unroll
    for (int mi = 0; mi < 4; ++mi)
#pragma unroll
        for (int ni = 0; ni < NI; ++ni)
#pragma unroll
            for (int q = 0; q < 4; ++q) acc[mi][ni][q] = 0.0f;

    int a_m = (lane & 7) + ((lane & 8) ? 8 : 0);
    int a_k = (lane & 16) ? 8 : 0;
    int b_n = lane & 7;
    int b_k = (lane & 8) ? 8 : 0;

    int NCH = K / 32;

    auto load_chunk = [&](int k0, int s) {
        __half* sA  = dsm + s * STAGE;
        __half* sBh = sA + A_SZ;
        __half* sBl = sBh + B_SZ;
#pragma unroll
        for (int i = 0; i < 2; ++i) {
            int idx = tid + i * 256;           // 0..511 (128 rows x 4 segs)
            int r = idx >> 2, sg = idx & 3;
            cpa16(s2u(sA + r * SSTR + sg * 8), gA + (size_t)r * lda + k0 + sg * 8);
        }
#pragma unroll
        for (int i = 0; i < BN / 64; ++i) {
            int idx = tid + i * 256;
            int r = idx >> 2, sg = idx & 3;
            int so = r * SSTR + sg * 8;
            size_t go = (size_t)r * ldb + k0 + sg * 8;
            cpa16(s2u(sBh + so), gBh + go);
            cpa16(s2u(sBl + so), gBl + go);
        }
        cp_commit();
    };

    load_chunk(0, 0);

    for (int c = 0; c < NCH; ++c) {
        if (c + 1 < NCH) {
            load_chunk((c + 1) * 32, (c + 1) & 1);
            asm volatile("cp.async.wait_group 1;" ::: "memory");
        } else {
            asm volatile("cp.async.wait_group 0;" ::: "memory");
        }
        __syncthreads();

        __half* sA  = dsm + (c & 1) * STAGE;
        __half* sBh = sA + A_SZ;
        __half* sBl = sBh + B_SZ;
        uint32_t uA = s2u(sA), uBh = s2u(sBh), uBl = s2u(sBl);

#pragma unroll
        for (int ks = 0; ks < 2; ++ks) {
            int kk = ks * 16;
            uint32_t bh[NI][2], blr[NI][2];
#pragma unroll
            for (int ni = 0; ni < NI; ++ni) {
                int row = warp_n * (BN / 4) + ni * 8 + b_n;
                uint32_t off = (uint32_t)(row * SSTR + kk + b_k) * 2;
                ldsm2(bh[ni][0],  bh[ni][1],  uBh + off);
                ldsm2(blr[ni][0], blr[ni][1], uBl + off);
            }
#pragma unroll
            for (int mi = 0; mi < 4; ++mi) {
                int row = warp_m * 64 + mi * 16 + a_m;
                uint32_t off = (uint32_t)(row * SSTR + kk + a_k) * 2;
                uint32_t ah[4];
                ldsm4(ah[0], ah[1], ah[2], ah[3], uA + off);
#pragma unroll
                for (int ni = 0; ni < NI; ++ni) {
                    mma16816h(acc[mi][ni], ah, bh[ni]);
                    mma16816h(acc[mi][ni], ah, blr[ni]);
                }
            }
        }
        __syncthreads();
    }

    int g = lane >> 2, cpair = (lane & 3) * 2;
#pragma unroll
    for (int mi = 0; mi < 4; ++mi) {
        int r0 = rb * 128 + warp_m * 64 + mi * 16 + g;
        int r1 = r0 + 8;
#pragma unroll
        for (int ni = 0; ni < NI; ++ni) {
            int col = nb * BN + warp_n * (BN / 4) + ni * 8 + cpair;
            float* c0 = C + (size_t)r0 * ldc + col;
            float* c1 = C + (size_t)r1 * ldc + col;
            if (EPI == 0) {
                *(float2*)c0 = make_float2(acc[mi][ni][0], acc[mi][ni][1]);
                *(float2*)c1 = make_float2(acc[mi][ni][2], acc[mi][ni][3]);
            } else {
                float2 o0 = *(float2*)c0, o1 = *(float2*)c1;
                o0.x += acc[mi][ni][0]; o0.y += acc[mi][ni][1];
                o1.x += acc[mi][ni][2]; o1.y += acc[mi][ni][3];
                *(float2*)c0 = o0;
                *(float2*)c1 = o1;
            }
        }
    }
}

#define SMEM_MMA_128 (2 * (128 * SSTR + 2 * 128 * SSTR) * 2)   // 61440 B
#define SMEM_MMA_64  (2 * (128 * SSTR + 2 * 64  * SSTR) * 2)   // 40960 B

// ---------------- SIMT FFMA2 GEMM (small GEMMs) ----------------
template <int BN_T, int EPI>
__global__ __launch_bounds__(256) void gemm2_kernel(
    const float* __restrict__ A, int lda,
    const float* __restrict__ Bm_, int ldb,
    float* __restrict__ C, int ldc,
    int K, const float* __restrict__ bias, size_t splitC_stride)
{
    constexpr int TN = BN_T / 16;
    __shared__ float As[16][130];
    __shared__ float Bs[16][BN_T];

    int tid = threadIdx.x;
    int bm = blockIdx.y * 128;
    int bn = blockIdx.x * BN_T;
    int z  = blockIdx.z;
    A   += (size_t)z * K;
    Bm_ += (size_t)z * K * ldb;
    C   += (size_t)z * splitC_stride;

    int m_a = tid >> 1, k_a = (tid & 1) * 8;
    int k_b = tid >> 4;
    int n_b = (tid & 15) * TN;
    int tx = tid & 15, ty = tid >> 4;

    ull acc[4][TN];
#pragma unroll
    for (int p = 0; p < 4; ++p)
#pragma unroll
        for (int j = 0; j < TN; ++j) acc[p][j] = 0ull;

    const float* Aptr = A + (size_t)(bm + m_a) * lda + k_a;
    const float* Bptr = Bm_ + (size_t)k_b * ldb + bn + n_b;

    float4 ra0 = *(const float4*)(Aptr);
    float4 ra1 = *(const float4*)(Aptr + 4);
    float4 rb0 = *(const float4*)(Bptr);
    float4 rb1;
    if constexpr (TN == 8) rb1 = *(const float4*)(Bptr + 4);

    int ntiles = K / 16;
    for (int kt = 0; kt < ntiles; ++kt) {
        As[k_a + 0][m_a] = ra0.x; As[k_a + 1][m_a] = ra0.y;
        As[k_a + 2][m_a] = ra0.z; As[k_a + 3][m_a] = ra0.w;
        As[k_a + 4][m_a] = ra1.x; As[k_a + 5][m_a] = ra1.y;
        As[k_a + 6][m_a] = ra1.z; As[k_a + 7][m_a] = ra1.w;
        *(float4*)&Bs[k_b][n_b] = rb0;
        if constexpr (TN == 8) *(float4*)&Bs[k_b][n_b + 4] = rb1;
        __syncthreads();

        if (kt + 1 < ntiles) {
            const float* Ap = Aptr + (kt + 1) * 16;
            ra0 = *(const float4*)(Ap);
            ra1 = *(const float4*)(Ap + 4);
            const float* Bp = Bptr + (size_t)(kt + 1) * 16 * ldb;
            rb0 = *(const float4*)(Bp);
            if constexpr (TN == 8) rb1 = *(const float4*)(Bp + 4);
        }

#pragma unroll
        for (int kk = 0; kk < 16; ++kk) {
            ull a2[4];
            const ull* ap = (const ull*)&As[kk][ty * 8];
            a2[0] = ap[0]; a2[1] = ap[1]; a2[2] = ap[2]; a2[3] = ap[3];
            float bf[TN];
            {
                float4 t0 = *(const float4*)&Bs[kk][tx * TN];
                bf[0] = t0.x; bf[1] = t0.y; bf[2] = t0.z; bf[3] = t0.w;
                if constexpr (TN == 8) {
                    float4 t1 = *(const float4*)&Bs[kk][tx * TN + 4];
                    bf[4] = t1.x; bf[5] = t1.y; bf[6] = t1.z; bf[7] = t1.w;
                }
            }
#pragma unroll
            for (int j = 0; j < TN; ++j) {
                ull bb = pack2(bf[j], bf[j]);
#pragma unroll
                for (int p = 0; p < 4; ++p) fma2(acc[p][j], a2[p], bb);
            }
        }
        __syncthreads();
    }

    float cf[8][TN];
#pragma unroll
    for (int p = 0; p < 4; ++p)
#pragma unroll
        for (int j = 0; j < TN; ++j) unpack2(acc[p][j], cf[2 * p][j], cf[2 * p + 1][j]);

#pragma unroll
    for (int i = 0; i < 8; ++i) {
        int m = bm + ty * 8 + i;
        float* cp = C + (size_t)m * ldc + bn + tx * TN;
        if (EPI == 0) {
#pragma unroll
            for (int j = 0; j < TN; j += 4)
                *(float4*)(cp + j) = make_float4(cf[i][j], cf[i][j + 1], cf[i][j + 2], cf[i][j + 3]);
        } else if (EPI == 1) {
#pragma unroll
            for (int j = 0; j < TN; j += 4) {
                float4 o = *(const float4*)(cp + j);
                o.x += cf[i][j]; o.y += cf[i][j + 1]; o.z += cf[i][j + 2]; o.w += cf[i][j + 3];
                *(float4*)(cp + j) = o;
            }
        } else if (EPI == 2) {
#pragma unroll
            for (int j = 0; j < TN; ++j) {
                float v = cf[i][j] + bias[bn + tx * TN + j];
                cp[j] = fmaxf(v, 0.0f) + log1pf(__expf(-fabsf(v)));
            }
        } else {
#pragma unroll
            for (int j = 0; j < TN; ++j) {
                float v = cf[i][j] + bias[bn + tx * TN + j];
                cp[j] = 0.5f * v * (1.0f + erff(v * 0.70710678118654752f));
            }
        }
    }
}

// ---------------- split-K reduce ----------------
__global__ void reduce4_kernel(const float* __restrict__ p, float* __restrict__ out)
{
    int i = blockIdx.x * 256 + threadIdx.x;
    const int n4 = BL * 64 / 4;
    if (i >= n4) return;
    const float4* p4 = (const float4*)p;
    float4 a = p4[i], b = p4[i + n4], c = p4[i + 2 * n4], d = p4[i + 3 * n4];
    a.x += b.x + c.x + d.x; a.y += b.y + c.y + d.y;
    a.z += b.z + c.z + d.z; a.w += b.w + c.w + d.w;
    ((float4*)out)[i] = a;
}

// ---------------- causal conv1d + silu -> fp32 + fp16 ----------------
__global__ void conv_silu_kernel(const float* __restrict__ xz,
                                 const float* __restrict__ w,
                                 const float* __restrict__ cb,
                                 float* __restrict__ out,
                                 __half* __restrict__ oF)
{
    int id = blockIdx.x * 256 + threadIdx.x;
    if (id >= BL * DI / 4) return;
    int dq = id % (DI / 4);
    int bl = id / (DI / 4);
    int d = dq * 4;
    int t = bl % L;
    int b = bl / L;
    float4 w0 = ((const float4*)w)[d + 0];
    float4 w1 = ((const float4*)w)[d + 1];
    float4 w2 = ((const float4*)w)[d + 2];
    float4 w3 = ((const float4*)w)[d + 3];
    float4 acc = *(const float4*)&cb[d];
    const float* base = xz + (size_t)(b * L) * (2 * DI) + d;
    if (t - 3 >= 0) {
        float4 xv = *(const float4*)(base + (size_t)(t - 3) * (2 * DI));
        acc.x += w0.x * xv.x; acc.y += w1.x * xv.y; acc.z += w2.x * xv.z; acc.w += w3.x * xv.w;
    }
    if (t - 2 >= 0) {
        float4 xv = *(const float4*)(base + (size_t)(t - 2) * (2 * DI));
        acc.x += w0.y * xv.x; acc.y += w1.y * xv.y; acc.z += w2.y * xv.z; acc.w += w3.y * xv.w;
    }
    if (t - 1 >= 0) {
        float4 xv = *(const float4*)(base + (size_t)(t - 1) * (2 * DI));
        acc.x += w0.z * xv.x; acc.y += w1.z * xv.y; acc.z += w2.z * xv.z; acc.w += w3.z * xv.w;
    }
    {
        float4 xv = *(const float4*)(base + (size_t)t * (2 * DI));
        acc.x += w0.w * xv.x; acc.y += w1.w * xv.y; acc.z += w2.w * xv.z; acc.w += w3.w * xv.w;
    }
    acc.x = acc.x / (1.0f + __expf(-acc.x));
    acc.y = acc.y / (1.0f + __expf(-acc.y));
    acc.z = acc.z / (1.0f + __expf(-acc.z));
    acc.w = acc.w / (1.0f + __expf(-acc.w));
    size_t o = (size_t)bl * DI + d;
    *(float4*)&out[o] = acc;
    union { __half v[4]; uint2 u; } pf;
    pf.v[0] = __float2half_rn(acc.x);
    pf.v[1] = __float2half_rn(acc.y);
    pf.v[2] = __float2half_rn(acc.z);
    pf.v[3] = __float2half_rn(acc.w);
    *(uint2*)&oF[o] = pf.u;
}

// ---------------- selective scan + gate -> fp16 y ----------------
__global__ void scan_kernel(const float* __restrict__ xc,
                            const float* __restrict__ dt,
                            const float* __restrict__ dbc,
                            const float* __restrict__ xz,
                            const float* __restrict__ A_log,
                            const float* __restrict__ Dp,
                            __half* __restrict__ yF)
{
    int bb = blockIdx.x;
    int d = blockIdx.y * 256 + threadIdx.x;
    float A[DS], h[DS];
#pragma unroll
    for (int n = 0; n < DS; ++n) { A[n] = -__expf(A_log[d * DS + n]); h[n] = 0.0f; }
    float Dpd = Dp[d];
    __shared__ float Bs[DS], Cs[DS];
    for (int t = 0; t < L; ++t) {
        __syncthreads();
        if (threadIdx.x < 32) {
            int n = threadIdx.x;
            float v = dbc[(size_t)(bb * L + t) * 64 + 32 + n];
            if (n < DS) Bs[n] = v; else Cs[n - DS] = v;
        }
        __syncthreads();
        size_t idx = (size_t)(bb * L + t) * DI + d;
        float dtv = dt[idx];
        float xv  = xc[idx];
        float dx  = dtv * xv;
        float yv = 0.0f;
#pragma unroll
        for (int n = 0; n < DS; ++n) {
            float dA = __expf(dtv * A[n]);
            h[n] = dA * h[n] + dx * Bs[n];
            yv += h[n] * Cs[n];
        }
        yv += Dpd * xv;
        float z = xz[(size_t)(bb * L + t) * (2 * DI) + DI + d];
        yv *= z / (1.0f + __expf(-z));
        yF[idx] = __float2half_rn(yv);
    }
}

// ---------------- mean-pool over L + LayerNorm ----------------
__global__ void pool_ln_kernel(const float* __restrict__ hin,
                               float* __restrict__ out,
                               const float* __restrict__ g,
                               const float* __restrict__ b)
{
    __shared__ float ws[16], ws2[16];
    int bb = blockIdx.x;
    int t = threadIdx.x;
    float s = 0.0f;
    for (int tt = 0; tt < L; ++tt) s += hin[(size_t)(bb * L + tt) * DM + t];
    float v = s * (1.0f / L);
    float sm = v, s2 = v * v;
#pragma unroll
    for (int o = 16; o; o >>= 1) {
        sm += __shfl_xor_sync(0xffffffffu, sm, o);
        s2 += __shfl_xor_sync(0xffffffffu, s2, o);
    }
    if ((t & 31) == 0) { ws[t >> 5] = sm; ws2[t >> 5] = s2; }
    __syncthreads();
    if (t < 32) {
        float a  = (t < 16) ? ws[t]  : 0.0f;
        float a2 = (t < 16) ? ws2[t] : 0.0f;
#pragma unroll
        for (int o = 8; o; o >>= 1) {
            a  += __shfl_xor_sync(0xffffffffu, a,  o);
            a2 += __shfl_xor_sync(0xffffffffu, a2, o);
        }
        if (t == 0) { ws[0] = a; ws2[0] = a2; }
    }
    __syncthreads();
    float mean = ws[0] * (1.0f / DM);
    float var  = ws2[0] * (1.0f / DM) - mean * mean;
    out[bb * DM + t] = (v - mean) * rsqrtf(var + 1e-5f) * g[t] + b[t];
}

// ---------------- final logits ----------------
__global__ void logits_kernel(const float* __restrict__ hid,
                              const float* __restrict__ W2,
                              const float* __restrict__ b2,
                              float* __restrict__ out)
{
    int id = blockIdx.x * blockDim.x + threadIdx.x;
    if (id >= Bz * NC) return;
    int b = id / NC, c = id % NC;
    float acc = b2[c];
    const float* hp = hid + b * (DM / 2);
    for (int k = 0; k < DM / 2; ++k) acc += hp[k] * W2[k * NC + c];
    out[id] = acc;
}

// ---------------- launch ----------------
extern "C" void kernel_launch(void* const* d_in, const int* in_sizes, int n_in,
                              void* d_out, int out_size)
{
    const float* x      = (const float*)d_in[0];
    const float* pw     = (const float*)d_in[1];
    const float* pb     = (const float*)d_in[2];
    const float* pos    = (const float*)d_in[3];
    const float* Win    = (const float*)d_in[4];
    const float* conv_w = (const float*)d_in[5];
    const float* conv_b = (const float*)d_in[6];
    const float* Wx     = (const float*)d_in[7];
    const float* Wdt    = (const float*)d_in[8];
    const float* bdt    = (const float*)d_in[9];
    const float* A_log  = (const float*)d_in[10];
    const float* Dp     = (const float*)d_in[11];
    const float* Wout   = (const float*)d_in[12];
    const float* ln_g   = (const float*)d_in[13];
    const float* ln_b   = (const float*)d_in[14];
    const float* norm_g = (const float*)d_in[15];
    const float* norm_b = (const float*)d_in[16];
    const float* W1     = (const float*)d_in[17];
    const float* b1     = (const float*)d_in[18];
    const float* W2     = (const float*)d_in[19];
    const float* b2     = (const float*)d_in[20];

    float *h, *xz, *xc, *dbc, *dbcp, *dt, *pool, *hid;
    __half *lnF, *xcF, *yF, *WinH, *WinL, *WoutH, *WoutL, *WxH, *WxL;
    cudaGetSymbolAddress((void**)&h,    g_h);
    cudaGetSymbolAddress((void**)&xz,   g_xz);
    cudaGetSymbolAddress((void**)&xc,   g_xc);
    cudaGetSymbolAddress((void**)&dbc,  g_dbc);
    cudaGetSymbolAddress((void**)&dbcp, g_dbcp);
    cudaGetSymbolAddress((void**)&dt,   g_dt);
    cudaGetSymbolAddress((void**)&pool, g_pool);
    cudaGetSymbolAddress((void**)&hid,  g_hid);
    cudaGetSymbolAddress((void**)&lnF,  g_lnF);
    cudaGetSymbolAddress((void**)&xcF,  g_xcF);
    cudaGetSymbolAddress((void**)&yF,   g_yF);
    cudaGetSymbolAddress((void**)&WinH, g_WinH);
    cudaGetSymbolAddress((void**)&WinL, g_WinL);
    cudaGetSymbolAddress((void**)&WoutH, g_WoutH);
    cudaGetSymbolAddress((void**)&WoutL, g_WoutL);
    cudaGetSymbolAddress((void**)&WxH,  g_WxH);
    cudaGetSymbolAddress((void**)&WxL,  g_WxL);

    // opt-in >48KB dynamic smem (skip during capture; attributes persist)
    cudaStreamCaptureStatus cst = cudaStreamCaptureStatusNone;
    cudaStreamIsCapturing(0, &cst);
    if (cst == cudaStreamCaptureStatusNone) {
        cudaFuncSetAttribute(gemm_mma2_kernel<128, 0>, cudaFuncAttributeMaxDynamicSharedMemorySize, SMEM_MMA_128);
        cudaFuncSetAttribute(gemm_mma2_kernel<128, 1>, cudaFuncAttributeMaxDynamicSharedMemorySize, SMEM_MMA_128);
    }

    // weight prep: W^T fp16 hi/lo
    prep_w_kernel<<<dim3(64, 16, NL), 256>>>(Win,  WinH,  WinL,  DM, 2 * DI);
    prep_w_kernel<<<dim3(16, 32, NL), 256>>>(Wout, WoutH, WoutL, DI, DM);
    prep_w_kernel<<<dim3(2, 32, NL), 256>>>(Wx,   WxH,   WxL,   DI, 64);

    patch2_kernel<<<Bz, 512>>>(x, pw, pb, pos, h);

    for (int i = 0; i < NL; ++i) {
        layernorm_f_kernel<<<BL, DM>>>(h, lnF, ln_g + i * DM, ln_b + i * DM);

        // xz = ln @ Win[i]   [6272,512]@[512,2048]
        gemm_mma2_kernel<128, 0><<<dim3(16, 49), 256, SMEM_MMA_128>>>(
            lnF, DM,
            WinH + (size_t)i * 2 * DI * DM, WinL + (size_t)i * 2 * DI * DM, DM,
            xz, 2 * DI, DM, 0);

        conv_silu_kernel<<<(BL * DI / 4 + 255) / 256, 256>>>(
            xz, conv_w + (size_t)i * DI * DC, conv_b + (size_t)i * DI, xc, xcF);

        // dbc = xc @ Wx[i]   [6272,1024]@[1024,64] — tensor, split-K x4
        gemm_mma2_kernel<64, 0><<<dim3(1, 49, 4), 256, SMEM_MMA_64>>>(
            xcF, DI,
            WxH + (size_t)i * 64 * DI, WxL + (size_t)i * 64 * DI, DI,
            dbcp, 64, DI / 4, (size_t)BL * 64);
        reduce4_kernel<<<(BL * 64 / 4 + 255) / 256, 256>>>(dbcp, dbc);

        // dt = softplus(dt_lo @ Wdt[i] + bdt[i])  SIMT (K=32)
        gemm2_kernel<128, 2><<<dim3(8, 49), 256>>>(
            dbc, 64, Wdt + (size_t)i * DTR * DI, DI,
            dt, DI, DTR, bdt + (size_t)i * DI, 0);

        scan_kernel<<<dim3(Bz, DI / 256), 256>>>(
            xc, dt, dbc, xz,
            A_log + (size_t)i * DI * DS, Dp + (size_t)i * DI, yF);

        // h += y @ Wout[i]   [6272,1024]@[1024,512]
        gemm_mma2_kernel<128, 1><<<dim3(4, 49), 256, SMEM_MMA_128>>>(
            yF, DI,
            WoutH + (size_t)i * DM * DI, WoutL + (size_t)i * DM * DI, DI,
            h, DM, DI, 0);
    }

    pool_ln_kernel<<<Bz, DM>>>(h, pool, norm_g, norm_b);

    gemm2_kernel<128, 3><<<dim3(2, 1), 256>>>(
        pool, DM, W1, DM / 2, hid, DM / 2, DM, b1, 0);

    logits_kernel<<<(Bz * NC + 255) / 256, 256>>>(hid, W2, b2, (float*)d_out);
}

// round 7
// speedup vs baseline: 2.5755x; 1.1114x over previous
#include <cuda_runtime.h>
#include <cuda_fp16.h>
#include <math.h>
#include <stdint.h>

// ---------------- Problem constants ----------------
#define Bz 128
#define IMG 28
#define GRID7 7
#define L 49
#define DM 512
#define NL 8
#define DS 16
#define DC 4
#define DI 1024
#define DTR 32
#define NC 10
#define BL (Bz * L)          // 6272

typedef unsigned long long ull;

// ================= helpers =================
__device__ __forceinline__ uint32_t s2u(const void* p) {
    uint32_t a;
    asm("{ .reg .u64 t; cvta.to.shared.u64 t, %1; cvt.u32.u64 %0, t; }" : "=r"(a) : "l"(p));
    return a;
}
__device__ __forceinline__ void cpa16(uint32_t s, const void* g) {
    asm volatile("cp.async.cg.shared.global [%0], [%1], 16;" :: "r"(s), "l"(g));
}
__device__ __forceinline__ void cp_commit() {
    asm volatile("cp.async.commit_group;" ::: "memory");
}
__device__ __forceinline__ void ldsm4(uint32_t& r0, uint32_t& r1, uint32_t& r2, uint32_t& r3, uint32_t addr) {
    asm volatile("ldmatrix.sync.aligned.m8n8.x4.shared.b16 {%0,%1,%2,%3}, [%4];"
                 : "=r"(r0), "=r"(r1), "=r"(r2), "=r"(r3) : "r"(addr));
}
__device__ __forceinline__ void ldsm2(uint32_t& r0, uint32_t& r1, uint32_t addr) {
    asm volatile("ldmatrix.sync.aligned.m8n8.x2.shared.b16 {%0,%1}, [%2];"
                 : "=r"(r0), "=r"(r1) : "r"(addr));
}
__device__ __forceinline__ void mma16816h(float* c, const uint32_t* a, const uint32_t* b) {
    asm volatile("mma.sync.aligned.m16n8k16.row.col.f32.f16.f16.f32 "
                 "{%0,%1,%2,%3}, {%4,%5,%6,%7}, {%8,%9}, {%0,%1,%2,%3};"
                 : "+f"(c[0]), "+f"(c[1]), "+f"(c[2]), "+f"(c[3])
                 : "r"(a[0]), "r"(a[1]), "r"(a[2]), "r"(a[3]), "r"(b[0]), "r"(b[1]));
}
// FFMA2 helpers (SIMT gemm)
__device__ __forceinline__ ull pack2(float lo, float hi) {
    ull r; asm("mov.b64 %0, {%1, %2};" : "=l"(r) : "f"(lo), "f"(hi)); return r;
}
__device__ __forceinline__ void unpack2(ull v, float& lo, float& hi) {
    asm("mov.b64 {%0, %1}, %2;" : "=f"(lo), "=f"(hi) : "l"(v));
}
__device__ __forceinline__ void fma2(ull& d, ull a, ull b) {
    asm("fma.rn.f32x2 %0, %1, %2, %0;" : "+l"(d) : "l"(a), "l"(b));
}

// ---------------- Scratch ----------------
__device__ float  g_h   [BL * DM];
__device__ float  g_xz  [BL * 2 * DI];
__device__ float  g_xc  [BL * DI];
__device__ float  g_dbc [BL * 64];
__device__ float  g_dbcp[4 * BL * 64];
__device__ float  g_pool[Bz * DM];
__device__ float  g_hid [Bz * (DM / 2)];
__device__ __half g_lnF [BL * DM];
__device__ __half g_xcF [BL * DI];
__device__ __half g_yF  [BL * DI];
__device__ __half g_WinF [NL * 2 * DI * DM];   // [l][N=2048][K=512]
__device__ __half g_WoutF[NL * DM * DI];       // [l][N=512][K=1024]
__device__ __half g_WxF  [NL * 64 * DI];       // [l][N=64][K=1024]

// ---------------- Patch embed + pos (one block per image) ----------------
__global__ __launch_bounds__(512) void patch2_kernel(
    const float* __restrict__ x,
    const float* __restrict__ pw,
    const float* __restrict__ pb,
    const float* __restrict__ pos,
    float* __restrict__ out)
{
    __shared__ float img[IMG * IMG];
    int b = blockIdx.x;
    int t = threadIdx.x;           // 512 = output channel
    for (int i = t; i < IMG * IMG; i += 512) img[i] = x[b * (IMG * IMG) + i];
    float w[16];
#pragma unroll
    for (int k = 0; k < 16; ++k) w[k] = pw[t * 16 + k];
    float pbt = pb[t];
    __syncthreads();
    for (int l = 0; l < L; ++l) {
        int gr = l / GRID7, gc = l % GRID7;
        float acc = pbt + pos[l * DM + t];
#pragma unroll
        for (int pr = 0; pr < 4; ++pr)
#pragma unroll
            for (int pc = 0; pc < 4; ++pc)
                acc += img[(gr * 4 + pr) * IMG + gc * 4 + pc] * w[pr * 4 + pc];
        out[(size_t)(b * L + l) * DM + t] = acc;
    }
}

// ---------------- weight prep: W[K,N] -> W^T fp16 [N][K] ----------------
__global__ void prep_w_kernel(const float* __restrict__ W,
                              __half* __restrict__ outF,
                              int K, int N)
{
    __shared__ float sm[32][33];
    int n0 = blockIdx.x * 32, k0 = blockIdx.y * 32, l = blockIdx.z;
    const float* Wl = W + (size_t)l * K * N;
    __half* oF = outF + (size_t)l * N * K;
    int tid = threadIdx.x;
#pragma unroll
    for (int i = 0; i < 4; ++i) {
        int idx = tid + i * 256;
        int kk = idx >> 5, nn = idx & 31;
        sm[kk][nn] = Wl[(size_t)(k0 + kk) * N + n0 + nn];
    }
    __syncthreads();
#pragma unroll
    for (int i = 0; i < 4; ++i) {
        int idx = tid + i * 256;
        int nn = idx >> 5, kk = idx & 31;
        oF[(size_t)(n0 + nn) * K + k0 + kk] = __float2half_rn(sm[kk][nn]);
    }
}

// ---------------- LayerNorm -> fp16 ----------------
__global__ void layernorm_f_kernel(const float* __restrict__ in,
                                   __half* __restrict__ oF,
                                   const float* __restrict__ g,
                                   const float* __restrict__ b)
{
    __shared__ float ws[16], ws2[16];
    int r = blockIdx.x;
    int t = threadIdx.x;           // 512
    float v = in[(size_t)r * DM + t];
    float s = v, s2 = v * v;
#pragma unroll
    for (int o = 16; o; o >>= 1) {
        s  += __shfl_xor_sync(0xffffffffu, s,  o);
        s2 += __shfl_xor_sync(0xffffffffu, s2, o);
    }
    if ((t & 31) == 0) { ws[t >> 5] = s; ws2[t >> 5] = s2; }
    __syncthreads();
    if (t < 32) {
        float a  = (t < 16) ? ws[t]  : 0.0f;
        float a2 = (t < 16) ? ws2[t] : 0.0f;
#pragma unroll
        for (int o = 8; o; o >>= 1) {
            a  += __shfl_xor_sync(0xffffffffu, a,  o);
            a2 += __shfl_xor_sync(0xffffffffu, a2, o);
        }
        if (t == 0) { ws[0] = a; ws2[0] = a2; }
    }
    __syncthreads();
    float mean = ws[0] * (1.0f / DM);
    float var  = ws2[0] * (1.0f / DM) - mean * mean;
    float nv = (v - mean) * rsqrtf(var + 1e-5f) * g[t] + b[t];
    oF[(size_t)r * DM + t] = __float2half_rn(nv);
}

// ---------------- tensor-core GEMM (plain fp16, cp.async 2-stage) ----------------
// C[M,N] = A[M,K+] @ B^T[N,K+];  CTA tile 128 x BN, 8 warps (2 x 4), warp tile 64 x BN/4.
// EPI: 0 = store, 1 = C += acc.  blockIdx.z = split-K slice.
#define SSTR 40   // smem row stride in halves (32 + 8 pad)

template <int BN, int EPI>
__global__ __launch_bounds__(256) void gemm_mma2_kernel(
    const __half* __restrict__ A, int lda,
    const __half* __restrict__ B, int ldb,
    float* __restrict__ C, int ldc, int K, size_t splitStride)
{
    constexpr int NI = BN / 32;
    constexpr int A_SZ = 128 * SSTR;
    constexpr int B_SZ = BN * SSTR;
    constexpr int STAGE = A_SZ + B_SZ;
    extern __shared__ __half dsm[];

    int tid = threadIdx.x;
    int wid = tid >> 5, lane = tid & 31;
    int rb = blockIdx.y, nb = blockIdx.x, z = blockIdx.z;
    int warp_m = wid >> 2;
    int warp_n = wid & 3;

    const __half* gA = A + (size_t)(rb * 128) * lda + (size_t)z * K;
    const __half* gB = B + (size_t)(nb * BN) * ldb + (size_t)z * K;
    C += (size_t)z * splitStride;

    float acc[4][NI][4];
#pragma unroll
    for (int mi = 0; mi < 4; ++mi)
#pragma unroll
        for (int ni = 0; ni < NI; ++ni)
#pragma unroll
            for (int q = 0; q < 4; ++q) acc[mi][ni][q] = 0.0f;

    int a_m = (lane & 7) + ((lane & 8) ? 8 : 0);
    int a_k = (lane & 16) ? 8 : 0;
    int b_n = lane & 7;
    int b_k = (lane & 8) ? 8 : 0;

    int NCH = K / 32;

    auto load_chunk = [&](int k0, int s) {
        __half* sA = dsm + s * STAGE;
        __half* sB = sA + A_SZ;
#pragma unroll
        for (int i = 0; i < 2; ++i) {
            int idx = tid + i * 256;           // 0..511 (128 rows x 4 segs)
            int r = idx >> 2, sg = idx & 3;
            cpa16(s2u(sA + r * SSTR + sg * 8), gA + (size_t)r * lda + k0 + sg * 8);
        }
#pragma unroll
        for (int i = 0; i < BN / 64; ++i) {
            int idx = tid + i * 256;
            int r = idx >> 2, sg = idx & 3;
            cpa16(s2u(sB + r * SSTR + sg * 8), gB + (size_t)r * ldb + k0 + sg * 8);
        }
        cp_commit();
    };

    load_chunk(0, 0);

    for (int c = 0; c < NCH; ++c) {
        if (c + 1 < NCH) {
            load_chunk((c + 1) * 32, (c + 1) & 1);
            asm volatile("cp.async.wait_group 1;" ::: "memory");
        } else {
            asm volatile("cp.async.wait_group 0;" ::: "memory");
        }
        __syncthreads();

        __half* sA = dsm + (c & 1) * STAGE;
        __half* sB = sA + A_SZ;
        uint32_t uA = s2u(sA), uB = s2u(sB);

#pragma unroll
        for (int ks = 0; ks < 2; ++ks) {
            int kk = ks * 16;
            uint32_t bh[NI][2];
#pragma unroll
            for (int ni = 0; ni < NI; ++ni) {
                int row = warp_n * (BN / 4) + ni * 8 + b_n;
                uint32_t off = (uint32_t)(row * SSTR + kk + b_k) * 2;
                ldsm2(bh[ni][0], bh[ni][1], uB + off);
            }
#pragma unroll
            for (int mi = 0; mi < 4; ++mi) {
                int row = warp_m * 64 + mi * 16 + a_m;
                uint32_t off = (uint32_t)(row * SSTR + kk + a_k) * 2;
                uint32_t ah[4];
                ldsm4(ah[0], ah[1], ah[2], ah[3], uA + off);
#pragma unroll
                for (int ni = 0; ni < NI; ++ni)
                    mma16816h(acc[mi][ni], ah, bh[ni]);
            }
        }
        __syncthreads();
    }

    int g = lane >> 2, cpair = (lane & 3) * 2;
#pragma unroll
    for (int mi = 0; mi < 4; ++mi) {
        int r0 = rb * 128 + warp_m * 64 + mi * 16 + g;
        int r1 = r0 + 8;
#pragma unroll
        for (int ni = 0; ni < NI; ++ni) {
            int col = nb * BN + warp_n * (BN / 4) + ni * 8 + cpair;
            float* c0 = C + (size_t)r0 * ldc + col;
            float* c1 = C + (size_t)r1 * ldc + col;
            if (EPI == 0) {
                *(float2*)c0 = make_float2(acc[mi][ni][0], acc[mi][ni][1]);
                *(float2*)c1 = make_float2(acc[mi][ni][2], acc[mi][ni][3]);
            } else {
                float2 o0 = *(float2*)c0, o1 = *(float2*)c1;
                o0.x += acc[mi][ni][0]; o0.y += acc[mi][ni][1];
                o1.x += acc[mi][ni][2]; o1.y += acc[mi][ni][3];
                *(float2*)c0 = o0;
                *(float2*)c1 = o1;
            }
        }
    }
}

#define SMEM_MMA_128 (2 * (128 * SSTR + 128 * SSTR) * 2)   // 40960 B
#define SMEM_MMA_64  (2 * (128 * SSTR + 64  * SSTR) * 2)   // 30720 B

// ---------------- SIMT FFMA2 GEMM (final MLP) ----------------
template <int BN_T, int EPI>
__global__ __launch_bounds__(256) void gemm2_kernel(
    const float* __restrict__ A, int lda,
    const float* __restrict__ Bm_, int ldb,
    float* __restrict__ C, int ldc,
    int K, const float* __restrict__ bias, size_t splitC_stride)
{
    constexpr int TN = BN_T / 16;
    __shared__ float As[16][130];
    __shared__ float Bs[16][BN_T];

    int tid = threadIdx.x;
    int bm = blockIdx.y * 128;
    int bn = blockIdx.x * BN_T;
    int z  = blockIdx.z;
    A   += (size_t)z * K;
    Bm_ += (size_t)z * K * ldb;
    C   += (size_t)z * splitC_stride;

    int m_a = tid >> 1, k_a = (tid & 1) * 8;
    int k_b = tid >> 4;
    int n_b = (tid & 15) * TN;
    int tx = tid & 15, ty = tid >> 4;

    ull acc[4][TN];
#pragma unroll
    for (int p = 0; p < 4; ++p)
#pragma unroll
        for (int j = 0; j < TN; ++j) acc[p][j] = 0ull;

    const float* Aptr = A + (size_t)(bm + m_a) * lda + k_a;
    const float* Bptr = Bm_ + (size_t)k_b * ldb + bn + n_b;

    float4 ra0 = *(const float4*)(Aptr);
    float4 ra1 = *(const float4*)(Aptr + 4);
    float4 rb0 = *(const float4*)(Bptr);
    float4 rb1;
    if constexpr (TN == 8) rb1 = *(const float4*)(Bptr + 4);

    int ntiles = K / 16;
    for (int kt = 0; kt < ntiles; ++kt) {
        As[k_a + 0][m_a] = ra0.x; As[k_a + 1][m_a] = ra0.y;
        As[k_a + 2][m_a] = ra0.z; As[k_a + 3][m_a] = ra0.w;
        As[k_a + 4][m_a] = ra1.x; As[k_a + 5][m_a] = ra1.y;
        As[k_a + 6][m_a] = ra1.z; As[k_a + 7][m_a] = ra1.w;
        *(float4*)&Bs[k_b][n_b] = rb0;
        if constexpr (TN == 8) *(float4*)&Bs[k_b][n_b + 4] = rb1;
        __syncthreads();

        if (kt + 1 < ntiles) {
            const float* Ap = Aptr + (kt + 1) * 16;
            ra0 = *(const float4*)(Ap);
            ra1 = *(const float4*)(Ap + 4);
            const float* Bp = Bptr + (size_t)(kt + 1) * 16 * ldb;
            rb0 = *(const float4*)(Bp);
            if constexpr (TN == 8) rb1 = *(const float4*)(Bp + 4);
        }

#pragma unroll
        for (int kk = 0; kk < 16; ++kk) {
            ull a2[4];
            const ull* ap = (const ull*)&As[kk][ty * 8];
            a2[0] = ap[0]; a2[1] = ap[1]; a2[2] = ap[2]; a2[3] = ap[3];
            float bf[TN];
            {
                float4 t0 = *(const float4*)&Bs[kk][tx * TN];
                bf[0] = t0.x; bf[1] = t0.y; bf[2] = t0.z; bf[3] = t0.w;
                if constexpr (TN == 8) {
                    float4 t1 = *(const float4*)&Bs[kk][tx * TN + 4];
                    bf[4] = t1.x; bf[5] = t1.y; bf[6] = t1.z; bf[7] = t1.w;
                }
            }
#pragma unroll
            for (int j = 0; j < TN; ++j) {
                ull bb = pack2(bf[j], bf[j]);
#pragma unroll
                for (int p = 0; p < 4; ++p) fma2(acc[p][j], a2[p], bb);
            }
        }
        __syncthreads();
    }

    float cf[8][TN];
#pragma unroll
    for (int p = 0; p < 4; ++p)
#pragma unroll
        for (int j = 0; j < TN; ++j) unpack2(acc[p][j], cf[2 * p][j], cf[2 * p + 1][j]);

#pragma unroll
    for (int i = 0; i < 8; ++i) {
        int m = bm + ty * 8 + i;
        float* cp = C + (size_t)m * ldc + bn + tx * TN;
        if (EPI == 0) {
#pragma unroll
            for (int j = 0; j < TN; j += 4)
                *(float4*)(cp + j) = make_float4(cf[i][j], cf[i][j + 1], cf[i][j + 2], cf[i][j + 3]);
        } else if (EPI == 1) {
#pragma unroll
            for (int j = 0; j < TN; j += 4) {
                float4 o = *(const float4*)(cp + j);
                o.x += cf[i][j]; o.y += cf[i][j + 1]; o.z += cf[i][j + 2]; o.w += cf[i][j + 3];
                *(float4*)(cp + j) = o;
            }
        } else if (EPI == 2) {
#pragma unroll
            for (int j = 0; j < TN; ++j) {
                float v = cf[i][j] + bias[bn + tx * TN + j];
                cp[j] = fmaxf(v, 0.0f) + log1pf(__expf(-fabsf(v)));
            }
        } else {
#pragma unroll
            for (int j = 0; j < TN; ++j) {
                float v = cf[i][j] + bias[bn + tx * TN + j];
                cp[j] = 0.5f * v * (1.0f + erff(v * 0.70710678118654752f));
            }
        }
    }
}

// ---------------- split-K reduce ----------------
__global__ void reduce4_kernel(const float* __restrict__ p, float* __restrict__ out)
{
    int i = blockIdx.x * 256 + threadIdx.x;
    const int n4 = BL * 64 / 4;
    if (i >= n4) return;
    const float4* p4 = (const float4*)p;
    float4 a = p4[i], b = p4[i + n4], c = p4[i + 2 * n4], d = p4[i + 3 * n4];
    a.x += b.x + c.x + d.x; a.y += b.y + c.y + d.y;
    a.z += b.z + c.z + d.z; a.w += b.w + c.w + d.w;
    ((float4*)out)[i] = a;
}

// ---------------- causal conv1d + silu -> fp32 + fp16 ----------------
__global__ void conv_silu_kernel(const float* __restrict__ xz,
                                 const float* __restrict__ w,
                                 const float* __restrict__ cb,
                                 float* __restrict__ out,
                                 __half* __restrict__ oF)
{
    int id = blockIdx.x * 256 + threadIdx.x;
    if (id >= BL * DI / 4) return;
    int dq = id % (DI / 4);
    int bl = id / (DI / 4);
    int d = dq * 4;
    int t = bl % L;
    int b = bl / L;
    float4 w0 = ((const float4*)w)[d + 0];
    float4 w1 = ((const float4*)w)[d + 1];
    float4 w2 = ((const float4*)w)[d + 2];
    float4 w3 = ((const float4*)w)[d + 3];
    float4 acc = *(const float4*)&cb[d];
    const float* base = xz + (size_t)(b * L) * (2 * DI) + d;
    if (t - 3 >= 0) {
        float4 xv = *(const float4*)(base + (size_t)(t - 3) * (2 * DI));
        acc.x += w0.x * xv.x; acc.y += w1.x * xv.y; acc.z += w2.x * xv.z; acc.w += w3.x * xv.w;
    }
    if (t - 2 >= 0) {
        float4 xv = *(const float4*)(base + (size_t)(t - 2) * (2 * DI));
        acc.x += w0.y * xv.x; acc.y += w1.y * xv.y; acc.z += w2.y * xv.z; acc.w += w3.y * xv.w;
    }
    if (t - 1 >= 0) {
        float4 xv = *(const float4*)(base + (size_t)(t - 1) * (2 * DI));
        acc.x += w0.z * xv.x; acc.y += w1.z * xv.y; acc.z += w2.z * xv.z; acc.w += w3.z * xv.w;
    }
    {
        float4 xv = *(const float4*)(base + (size_t)t * (2 * DI));
        acc.x += w0.w * xv.x; acc.y += w1.w * xv.y; acc.z += w2.w * xv.z; acc.w += w3.w * xv.w;
    }
    acc.x = acc.x / (1.0f + __expf(-acc.x));
    acc.y = acc.y / (1.0f + __expf(-acc.y));
    acc.z = acc.z / (1.0f + __expf(-acc.z));
    acc.w = acc.w / (1.0f + __expf(-acc.w));
    size_t o = (size_t)bl * DI + d;
    *(float4*)&out[o] = acc;
    union { __half v[4]; uint2 u; } pf;
    pf.v[0] = __float2half_rn(acc.x);
    pf.v[1] = __float2half_rn(acc.y);
    pf.v[2] = __float2half_rn(acc.z);
    pf.v[3] = __float2half_rn(acc.w);
    *(uint2*)&oF[o] = pf.u;
}

// ---------------- selective scan (dt fused) + gate -> fp16 y ----------------
__global__ __launch_bounds__(256) void scan_kernel(
    const float* __restrict__ xc,
    const float* __restrict__ dbc,
    const float* __restrict__ xz,
    const float* __restrict__ Wdt,   // [DTR, DI]
    const float* __restrict__ bdt,   // [DI]
    const float* __restrict__ A_log,
    const float* __restrict__ Dp,
    __half* __restrict__ yF)
{
    int bb = blockIdx.x;
    int d = blockIdx.y * 256 + threadIdx.x;
    float A[DS], h[DS], wdt[DTR];
#pragma unroll
    for (int n = 0; n < DS; ++n) { A[n] = -__expf(A_log[d * DS + n]); h[n] = 0.0f; }
#pragma unroll
    for (int k = 0; k < DTR; ++k) wdt[k] = Wdt[k * DI + d];
    float bdtd = bdt[d];
    float Dpd = Dp[d];
    __shared__ float Ls[DTR], Bs[DS], Cs[DS];   // dt_lo | B | C
    for (int t = 0; t < L; ++t) {
        __syncthreads();
        if (threadIdx.x < 64) {
            int n = threadIdx.x;
            float v = dbc[(size_t)(bb * L + t) * 64 + n];
            if (n < DTR) Ls[n] = v;
            else if (n < DTR + DS) Bs[n - DTR] = v;
            else Cs[n - DTR - DS] = v;
        }
        __syncthreads();
        float dtv = bdtd;
#pragma unroll
        for (int k = 0; k < DTR; ++k) dtv += Ls[k] * wdt[k];
        dtv = fmaxf(dtv, 0.0f) + log1pf(__expf(-fabsf(dtv)));   // softplus
        size_t idx = (size_t)(bb * L + t) * DI + d;
        float xv  = xc[idx];
        float dx  = dtv * xv;
        float yv = 0.0f;
#pragma unroll
        for (int n = 0; n < DS; ++n) {
            float dA = __expf(dtv * A[n]);
            h[n] = dA * h[n] + dx * Bs[n];
            yv += h[n] * Cs[n];
        }
        yv += Dpd * xv;
        float z = xz[(size_t)(bb * L + t) * (2 * DI) + DI + d];
        yv *= z / (1.0f + __expf(-z));
        yF[idx] = __float2half_rn(yv);
    }
}

// ---------------- mean-pool over L + LayerNorm ----------------
__global__ void pool_ln_kernel(const float* __restrict__ hin,
                               float* __restrict__ out,
                               const float* __restrict__ g,
                               const float* __restrict__ b)
{
    __shared__ float ws[16], ws2[16];
    int bb = blockIdx.x;
    int t = threadIdx.x;
    float s = 0.0f;
    for (int tt = 0; tt < L; ++tt) s += hin[(size_t)(bb * L + tt) * DM + t];
    float v = s * (1.0f / L);
    float sm = v, s2 = v * v;
#pragma unroll
    for (int o = 16; o; o >>= 1) {
        sm += __shfl_xor_sync(0xffffffffu, sm, o);
        s2 += __shfl_xor_sync(0xffffffffu, s2, o);
    }
    if ((t & 31) == 0) { ws[t >> 5] = sm; ws2[t >> 5] = s2; }
    __syncthreads();
    if (t < 32) {
        float a  = (t < 16) ? ws[t]  : 0.0f;
        float a2 = (t < 16) ? ws2[t] : 0.0f;
#pragma unroll
        for (int o = 8; o; o >>= 1) {
            a  += __shfl_xor_sync(0xffffffffu, a,  o);
            a2 += __shfl_xor_sync(0xffffffffu, a2, o);
        }
        if (t == 0) { ws[0] = a; ws2[0] = a2; }
    }
    __syncthreads();
    float mean = ws[0] * (1.0f / DM);
    float var  = ws2[0] * (1.0f / DM) - mean * mean;
    out[bb * DM + t] = (v - mean) * rsqrtf(var + 1e-5f) * g[t] + b[t];
}

// ---------------- final logits ----------------
__global__ void logits_kernel(const float* __restrict__ hid,
                              const float* __restrict__ W2,
                              const float* __restrict__ b2,
                              float* __restrict__ out)
{
    int id = blockIdx.x * blockDim.x + threadIdx.x;
    if (id >= Bz * NC) return;
    int b = id / NC, c = id % NC;
    float acc = b2[c];
    const float* hp = hid + b * (DM / 2);
    for (int k = 0; k < DM / 2; ++k) acc += hp[k] * W2[k * NC + c];
    out[id] = acc;
}

// ---------------- launch ----------------
extern "C" void kernel_launch(void* const* d_in, const int* in_sizes, int n_in,
                              void* d_out, int out_size)
{
    const float* x      = (const float*)d_in[0];
    const float* pw     = (const float*)d_in[1];
    const float* pb     = (const float*)d_in[2];
    const float* pos    = (const float*)d_in[3];
    const float* Win    = (const float*)d_in[4];
    const float* conv_w = (const float*)d_in[5];
    const float* conv_b = (const float*)d_in[6];
    const float* Wx     = (const float*)d_in[7];
    const float* Wdt    = (const float*)d_in[8];
    const float* bdt    = (const float*)d_in[9];
    const float* A_log  = (const float*)d_in[10];
    const float* Dp     = (const float*)d_in[11];
    const float* Wout   = (const float*)d_in[12];
    const float* ln_g   = (const float*)d_in[13];
    const float* ln_b   = (const float*)d_in[14];
    const float* norm_g = (const float*)d_in[15];
    const float* norm_b = (const float*)d_in[16];
    const float* W1     = (const float*)d_in[17];
    const float* b1     = (const float*)d_in[18];
    const float* W2     = (const float*)d_in[19];
    const float* b2     = (const float*)d_in[20];

    float *h, *xz, *xc, *dbc, *dbcp, *pool, *hid;
    __half *lnF, *xcF, *yF, *WinF, *WoutF, *WxF;
    cudaGetSymbolAddress((void**)&h,    g_h);
    cudaGetSymbolAddress((void**)&xz,   g_xz);
    cudaGetSymbolAddress((void**)&xc,   g_xc);
    cudaGetSymbolAddress((void**)&dbc,  g_dbc);
    cudaGetSymbolAddress((void**)&dbcp, g_dbcp);
    cudaGetSymbolAddress((void**)&pool, g_pool);
    cudaGetSymbolAddress((void**)&hid,  g_hid);
    cudaGetSymbolAddress((void**)&lnF,  g_lnF);
    cudaGetSymbolAddress((void**)&xcF,  g_xcF);
    cudaGetSymbolAddress((void**)&yF,   g_yF);
    cudaGetSymbolAddress((void**)&WinF, g_WinF);
    cudaGetSymbolAddress((void**)&WoutF, g_WoutF);
    cudaGetSymbolAddress((void**)&WxF,  g_WxF);

    // weight prep: W^T fp16
    prep_w_kernel<<<dim3(64, 16, NL), 256>>>(Win,  WinF,  DM, 2 * DI);
    prep_w_kernel<<<dim3(16, 32, NL), 256>>>(Wout, WoutF, DI, DM);
    prep_w_kernel<<<dim3(2, 32, NL), 256>>>(Wx,   WxF,   DI, 64);

    patch2_kernel<<<Bz, 512>>>(x, pw, pb, pos, h);

    for (int i = 0; i < NL; ++i) {
        layernorm_f_kernel<<<BL, DM>>>(h, lnF, ln_g + i * DM, ln_b + i * DM);

        // xz = ln @ Win[i]   [6272,512]@[512,2048]
        gemm_mma2_kernel<128, 0><<<dim3(16, 49), 256, SMEM_MMA_128>>>(
            lnF, DM, WinF + (size_t)i * 2 * DI * DM, DM,
            xz, 2 * DI, DM, 0);

        conv_silu_kernel<<<(BL * DI / 4 + 255) / 256, 256>>>(
            xz, conv_w + (size_t)i * DI * DC, conv_b + (size_t)i * DI, xc, xcF);

        // dbc = xc @ Wx[i]   [6272,1024]@[1024,64] — tensor, split-K x4
        gemm_mma2_kernel<64, 0><<<dim3(1, 49, 4), 256, SMEM_MMA_64>>>(
            xcF, DI, WxF + (size_t)i * 64 * DI, DI,
            dbcp, 64, DI / 4, (size_t)BL * 64);
        reduce4_kernel<<<(BL * 64 / 4 + 255) / 256, 256>>>(dbcp, dbc);

        // scan (dt fused) + gate
        scan_kernel<<<dim3(Bz, DI / 256), 256>>>(
            xc, dbc, xz,
            Wdt + (size_t)i * DTR * DI, bdt + (size_t)i * DI,
            A_log + (size_t)i * DI * DS, Dp + (size_t)i * DI, yF);

        // h += y @ Wout[i]   [6272,1024]@[1024,512]
        gemm_mma2_kernel<128, 1><<<dim3(4, 49), 256, SMEM_MMA_128>>>(
            yF, DI, WoutF + (size_t)i * DM * DI, DI,
            h, DM, DI, 0);
    }

    pool_ln_kernel<<<Bz, DM>>>(h, pool, norm_g, norm_b);

    gemm2_kernel<128, 3><<<dim3(2, 1), 256>>>(
        pool, DM, W1, DM / 2, hid, DM / 2, DM, b1, 0);

    logits_kernel<<<(Bz * NC + 255) / 256, 256>>>(hid, W2, b2, (float*)d_out);
}

// round 8
// speedup vs baseline: 2.8796x; 1.1181x over previous
#include <cuda_runtime.h>
#include <cuda_fp16.h>
#include <math.h>
#include <stdint.h>

// ---------------- Problem constants ----------------
#define Bz 128
#define IMG 28
#define GRID7 7
#define L 49
#define DM 512
#define NL 8
#define DS 16
#define DC 4
#define DI 1024
#define DTR 32
#define NC 10
#define BL (Bz * L)          // 6272

typedef unsigned long long ull;

// ================= helpers =================
__device__ __forceinline__ uint32_t s2u(const void* p) {
    uint32_t a;
    asm("{ .reg .u64 t; cvta.to.shared.u64 t, %1; cvt.u32.u64 %0, t; }" : "=r"(a) : "l"(p));
    return a;
}
__device__ __forceinline__ void cpa16(uint32_t s, const void* g) {
    asm volatile("cp.async.cg.shared.global [%0], [%1], 16;" :: "r"(s), "l"(g));
}
__device__ __forceinline__ void cp_commit() {
    asm volatile("cp.async.commit_group;" ::: "memory");
}
__device__ __forceinline__ void ldsm4(uint32_t& r0, uint32_t& r1, uint32_t& r2, uint32_t& r3, uint32_t addr) {
    asm volatile("ldmatrix.sync.aligned.m8n8.x4.shared.b16 {%0,%1,%2,%3}, [%4];"
                 : "=r"(r0), "=r"(r1), "=r"(r2), "=r"(r3) : "r"(addr));
}
__device__ __forceinline__ void ldsm2(uint32_t& r0, uint32_t& r1, uint32_t addr) {
    asm volatile("ldmatrix.sync.aligned.m8n8.x2.shared.b16 {%0,%1}, [%2];"
                 : "=r"(r0), "=r"(r1) : "r"(addr));
}
__device__ __forceinline__ void mma16816h(float* c, const uint32_t* a, const uint32_t* b) {
    asm volatile("mma.sync.aligned.m16n8k16.row.col.f32.f16.f16.f32 "
                 "{%0,%1,%2,%3}, {%4,%5,%6,%7}, {%8,%9}, {%0,%1,%2,%3};"
                 : "+f"(c[0]), "+f"(c[1]), "+f"(c[2]), "+f"(c[3])
                 : "r"(a[0]), "r"(a[1]), "r"(a[2]), "r"(a[3]), "r"(b[0]), "r"(b[1]));
}
// FFMA2 helpers (SIMT gemm)
__device__ __forceinline__ ull pack2(float lo, float hi) {
    ull r; asm("mov.b64 %0, {%1, %2};" : "=l"(r) : "f"(lo), "f"(hi)); return r;
}
__device__ __forceinline__ void unpack2(ull v, float& lo, float& hi) {
    asm("mov.b64 {%0, %1}, %2;" : "=f"(lo), "=f"(hi) : "l"(v));
}
__device__ __forceinline__ void fma2(ull& d, ull a, ull b) {
    asm("fma.rn.f32x2 %0, %1, %2, %0;" : "+l"(d) : "l"(a), "l"(b));
}

// ---------------- Scratch ----------------
__device__ float  g_h   [BL * DM];
__device__ float  g_xz  [BL * 2 * DI];
__device__ float  g_xc  [BL * DI];
__device__ float  g_dbc [BL * 64];
__device__ float  g_dbcp[8 * BL * 64];
__device__ float  g_pool[Bz * DM];
__device__ float  g_hid [Bz * (DM / 2)];
__device__ __half g_lnF [BL * DM];
__device__ __half g_xcF [BL * DI];
__device__ __half g_yF  [BL * DI];
__device__ __half g_WinF [NL * 2 * DI * DM];   // [l][N=2048][K=512]
__device__ __half g_WoutF[NL * DM * DI];       // [l][N=512][K=1024]
__device__ __half g_WxF  [NL * 64 * DI];       // [l][N=64][K=1024]

// ---------------- Patch embed + pos (one block per image x grid-row) ----------------
__global__ __launch_bounds__(512) void patch3_kernel(
    const float* __restrict__ x,
    const float* __restrict__ pw,
    const float* __restrict__ pb,
    const float* __restrict__ pos,
    float* __restrict__ out)
{
    __shared__ float rows[4 * IMG];
    int b = blockIdx.x;
    int gr = blockIdx.y;           // 0..6
    int t = threadIdx.x;           // output channel
    if (t < 4 * IMG) rows[t] = x[b * (IMG * IMG) + (gr * 4) * IMG + t];
    float w[16];
#pragma unroll
    for (int k = 0; k < 16; ++k) w[k] = pw[t * 16 + k];
    float pbt = pb[t];
    __syncthreads();
#pragma unroll
    for (int gc = 0; gc < GRID7; ++gc) {
        int l = gr * GRID7 + gc;
        float acc = pbt + pos[l * DM + t];
#pragma unroll
        for (int pr = 0; pr < 4; ++pr)
#pragma unroll
            for (int pc = 0; pc < 4; ++pc)
                acc += rows[pr * IMG + gc * 4 + pc] * w[pr * 4 + pc];
        out[(size_t)(b * L + l) * DM + t] = acc;
    }
}

// ---------------- weight prep: W[K,N] -> W^T fp16 [N][K] ----------------
__global__ void prep_w_kernel(const float* __restrict__ W,
                              __half* __restrict__ outF,
                              int K, int N)
{
    __shared__ float sm[32][33];
    int n0 = blockIdx.x * 32, k0 = blockIdx.y * 32, l = blockIdx.z;
    const float* Wl = W + (size_t)l * K * N;
    __half* oF = outF + (size_t)l * N * K;
    int tid = threadIdx.x;
#pragma unroll
    for (int i = 0; i < 4; ++i) {
        int idx = tid + i * 256;
        int kk = idx >> 5, nn = idx & 31;
        sm[kk][nn] = Wl[(size_t)(k0 + kk) * N + n0 + nn];
    }
    __syncthreads();
#pragma unroll
    for (int i = 0; i < 4; ++i) {
        int idx = tid + i * 256;
        int nn = idx >> 5, kk = idx & 31;
        oF[(size_t)(n0 + nn) * K + k0 + kk] = __float2half_rn(sm[kk][nn]);
    }
}

// ---------------- LayerNorm -> fp16 ----------------
__global__ void layernorm_f_kernel(const float* __restrict__ in,
                                   __half* __restrict__ oF,
                                   const float* __restrict__ g,
                                   const float* __restrict__ b)
{
    __shared__ float ws[16], ws2[16];
    int r = blockIdx.x;
    int t = threadIdx.x;           // 512
    float v = in[(size_t)r * DM + t];
    float s = v, s2 = v * v;
#pragma unroll
    for (int o = 16; o; o >>= 1) {
        s  += __shfl_xor_sync(0xffffffffu, s,  o);
        s2 += __shfl_xor_sync(0xffffffffu, s2, o);
    }
    if ((t & 31) == 0) { ws[t >> 5] = s; ws2[t >> 5] = s2; }
    __syncthreads();
    if (t < 32) {
        float a  = (t < 16) ? ws[t]  : 0.0f;
        float a2 = (t < 16) ? ws2[t] : 0.0f;
#pragma unroll
        for (int o = 8; o; o >>= 1) {
            a  += __shfl_xor_sync(0xffffffffu, a,  o);
            a2 += __shfl_xor_sync(0xffffffffu, a2, o);
        }
        if (t == 0) { ws[0] = a; ws2[0] = a2; }
    }
    __syncthreads();
    float mean = ws[0] * (1.0f / DM);
    float var  = ws2[0] * (1.0f / DM) - mean * mean;
    float nv = (v - mean) * rsqrtf(var + 1e-5f) * g[t] + b[t];
    oF[(size_t)r * DM + t] = __float2half_rn(nv);
}

// ---------------- tensor-core GEMM (fp16, cp.async 3-stage, 1 barrier/chunk) ----------------
// C[M,N] = A[M,K+] @ B^T[N,K+];  CTA tile 128 x BN, 8 warps (2 x 4), warp tile 64 x BN/4.
// EPI: 0 = store, 1 = C += acc.  blockIdx.z = split-K slice.
#define SSTR 40   // smem row stride in halves (32 + 8 pad)

template <int BN, int EPI>
__global__ __launch_bounds__(256) void gemm_mma3_kernel(
    const __half* __restrict__ A, int lda,
    const __half* __restrict__ B, int ldb,
    float* __restrict__ C, int ldc, int K, size_t splitStride)
{
    constexpr int NI = BN / 32;
    constexpr int A_SZ = 128 * SSTR;
    constexpr int B_SZ = BN * SSTR;
    constexpr int STAGE = A_SZ + B_SZ;
    extern __shared__ __half dsm[];

    int tid = threadIdx.x;
    int wid = tid >> 5, lane = tid & 31;
    int rb = blockIdx.y, nb = blockIdx.x, z = blockIdx.z;
    int warp_m = wid >> 2;
    int warp_n = wid & 3;

    const __half* gA = A + (size_t)(rb * 128) * lda + (size_t)z * K;
    const __half* gB = B + (size_t)(nb * BN) * ldb + (size_t)z * K;
    C += (size_t)z * splitStride;

    float acc[4][NI][4];
#pragma unroll
    for (int mi = 0; mi < 4; ++mi)
#pragma unroll
        for (int ni = 0; ni < NI; ++ni)
#pragma unroll
            for (int q = 0; q < 4; ++q) acc[mi][ni][q] = 0.0f;

    int a_m = (lane & 7) + ((lane & 8) ? 8 : 0);
    int a_k = (lane & 16) ? 8 : 0;
    int b_n = lane & 7;
    int b_k = (lane & 8) ? 8 : 0;

    int NCH = K / 32;

    auto load_chunk = [&](int k0, int s) {
        __half* sA = dsm + s * STAGE;
        __half* sB = sA + A_SZ;
#pragma unroll
        for (int i = 0; i < 2; ++i) {
            int idx = tid + i * 256;           // 0..511 (128 rows x 4 segs)
            int r = idx >> 2, sg = idx & 3;
            cpa16(s2u(sA + r * SSTR + sg * 8), gA + (size_t)r * lda + k0 + sg * 8);
        }
#pragma unroll
        for (int i = 0; i < BN / 64; ++i) {
            int idx = tid + i * 256;
            int r = idx >> 2, sg = idx & 3;
            cpa16(s2u(sB + r * SSTR + sg * 8), gB + (size_t)r * ldb + k0 + sg * 8);
        }
        cp_commit();
    };

    load_chunk(0, 0);
    if (NCH > 1) load_chunk(32, 1);

    for (int c = 0; c < NCH; ++c) {
        if (c + 1 < NCH) {
            asm volatile("cp.async.wait_group 1;" ::: "memory");
        } else {
            asm volatile("cp.async.wait_group 0;" ::: "memory");
        }
        __syncthreads();
        if (c + 2 < NCH) load_chunk((c + 2) * 32, (c + 2) % 3);

        __half* sA = dsm + (c % 3) * STAGE;
        __half* sB = sA + A_SZ;
        uint32_t uA = s2u(sA), uB = s2u(sB);

#pragma unroll
        for (int ks = 0; ks < 2; ++ks) {
            int kk = ks * 16;
            uint32_t bh[NI][2];
#pragma unroll
            for (int ni = 0; ni < NI; ++ni) {
                int row = warp_n * (BN / 4) + ni * 8 + b_n;
                uint32_t off = (uint32_t)(row * SSTR + kk + b_k) * 2;
                ldsm2(bh[ni][0], bh[ni][1], uB + off);
            }
#pragma unroll
            for (int mi = 0; mi < 4; ++mi) {
                int row = warp_m * 64 + mi * 16 + a_m;
                uint32_t off = (uint32_t)(row * SSTR + kk + a_k) * 2;
                uint32_t ah[4];
                ldsm4(ah[0], ah[1], ah[2], ah[3], uA + off);
#pragma unroll
                for (int ni = 0; ni < NI; ++ni)
                    mma16816h(acc[mi][ni], ah, bh[ni]);
            }
        }
    }

    __syncthreads();   // all MMAs done before anyone exits (smem safety not needed; cheap)

    int g = lane >> 2, cpair = (lane & 3) * 2;
#pragma unroll
    for (int mi = 0; mi < 4; ++mi) {
        int r0 = rb * 128 + warp_m * 64 + mi * 16 + g;
        int r1 = r0 + 8;
#pragma unroll
        for (int ni = 0; ni < NI; ++ni) {
            int col = nb * BN + warp_n * (BN / 4) + ni * 8 + cpair;
            float* c0 = C + (size_t)r0 * ldc + col;
            float* c1 = C + (size_t)r1 * ldc + col;
            if (EPI == 0) {
                *(float2*)c0 = make_float2(acc[mi][ni][0], acc[mi][ni][1]);
                *(float2*)c1 = make_float2(acc[mi][ni][2], acc[mi][ni][3]);
            } else {
                float2 o0 = *(float2*)c0, o1 = *(float2*)c1;
                o0.x += acc[mi][ni][0]; o0.y += acc[mi][ni][1];
                o1.x += acc[mi][ni][2]; o1.y += acc[mi][ni][3];
                *(float2*)c0 = o0;
                *(float2*)c1 = o1;
            }
        }
    }
}

#define SMEM_MMA_128 (3 * (128 * SSTR + 128 * SSTR) * 2)   // 61440 B (needs attribute)
#define SMEM_MMA_64  (3 * (128 * SSTR + 64  * SSTR) * 2)   // 46080 B

// ---------------- SIMT FFMA2 GEMM (final MLP) ----------------
template <int BN_T, int EPI>
__global__ __launch_bounds__(256) void gemm2_kernel(
    const float* __restrict__ A, int lda,
    const float* __restrict__ Bm_, int ldb,
    float* __restrict__ C, int ldc,
    int K, const float* __restrict__ bias, size_t splitC_stride)
{
    constexpr int TN = BN_T / 16;
    __shared__ float As[16][130];
    __shared__ float Bs[16][BN_T];

    int tid = threadIdx.x;
    int bm = blockIdx.y * 128;
    int bn = blockIdx.x * BN_T;
    int z  = blockIdx.z;
    A   += (size_t)z * K;
    Bm_ += (size_t)z * K * ldb;
    C   += (size_t)z * splitC_stride;

    int m_a = tid >> 1, k_a = (tid & 1) * 8;
    int k_b = tid >> 4;
    int n_b = (tid & 15) * TN;
    int tx = tid & 15, ty = tid >> 4;

    ull acc[4][TN];
#pragma unroll
    for (int p = 0; p < 4; ++p)
#pragma unroll
        for (int j = 0; j < TN; ++j) acc[p][j] = 0ull;

    const float* Aptr = A + (size_t)(bm + m_a) * lda + k_a;
    const float* Bptr = Bm_ + (size_t)k_b * ldb + bn + n_b;

    float4 ra0 = *(const float4*)(Aptr);
    float4 ra1 = *(const float4*)(Aptr + 4);
    float4 rb0 = *(const float4*)(Bptr);
    float4 rb1;
    if constexpr (TN == 8) rb1 = *(const float4*)(Bptr + 4);

    int ntiles = K / 16;
    for (int kt = 0; kt < ntiles; ++kt) {
        As[k_a + 0][m_a] = ra0.x; As[k_a + 1][m_a] = ra0.y;
        As[k_a + 2][m_a] = ra0.z; As[k_a + 3][m_a] = ra0.w;
        As[k_a + 4][m_a] = ra1.x; As[k_a + 5][m_a] = ra1.y;
        As[k_a + 6][m_a] = ra1.z; As[k_a + 7][m_a] = ra1.w;
        *(float4*)&Bs[k_b][n_b] = rb0;
        if constexpr (TN == 8) *(float4*)&Bs[k_b][n_b + 4] = rb1;
        __syncthreads();

        if (kt + 1 < ntiles) {
            const float* Ap = Aptr + (kt + 1) * 16;
            ra0 = *(const float4*)(Ap);
            ra1 = *(const float4*)(Ap + 4);
            const float* Bp = Bptr + (size_t)(kt + 1) * 16 * ldb;
            rb0 = *(const float4*)(Bp);
            if constexpr (TN == 8) rb1 = *(const float4*)(Bp + 4);
        }

#pragma unroll
        for (int kk = 0; kk < 16; ++kk) {
            ull a2[4];
            const ull* ap = (const ull*)&As[kk][ty * 8];
            a2[0] = ap[0]; a2[1] = ap[1]; a2[2] = ap[2]; a2[3] = ap[3];
            float bf[TN];
            {
                float4 t0 = *(const float4*)&Bs[kk][tx * TN];
                bf[0] = t0.x; bf[1] = t0.y; bf[2] = t0.z; bf[3] = t0.w;
                if constexpr (TN == 8) {
                    float4 t1 = *(const float4*)&Bs[kk][tx * TN + 4];
                    bf[4] = t1.x; bf[5] = t1.y; bf[6] = t1.z; bf[7] = t1.w;
                }
            }
#pragma unroll
            for (int j = 0; j < TN; ++j) {
                ull bb = pack2(bf[j], bf[j]);
#pragma unroll
                for (int p = 0; p < 4; ++p) fma2(acc[p][j], a2[p], bb);
            }
        }
        __syncthreads();
    }

    float cf[8][TN];
#pragma unroll
    for (int p = 0; p < 4; ++p)
#pragma unroll
        for (int j = 0; j < TN; ++j) unpack2(acc[p][j], cf[2 * p][j], cf[2 * p + 1][j]);

#pragma unroll
    for (int i = 0; i < 8; ++i) {
        int m = bm + ty * 8 + i;
        float* cp = C + (size_t)m * ldc + bn + tx * TN;
        if (EPI == 0) {
#pragma unroll
            for (int j = 0; j < TN; j += 4)
                *(float4*)(cp + j) = make_float4(cf[i][j], cf[i][j + 1], cf[i][j + 2], cf[i][j + 3]);
        } else if (EPI == 1) {
#pragma unroll
            for (int j = 0; j < TN; j += 4) {
                float4 o = *(const float4*)(cp + j);
                o.x += cf[i][j]; o.y += cf[i][j + 1]; o.z += cf[i][j + 2]; o.w += cf[i][j + 3];
                *(float4*)(cp + j) = o;
            }
        } else if (EPI == 2) {
#pragma unroll
            for (int j = 0; j < TN; ++j) {
                float v = cf[i][j] + bias[bn + tx * TN + j];
                cp[j] = fmaxf(v, 0.0f) + log1pf(__expf(-fabsf(v)));
            }
        } else {
#pragma unroll
            for (int j = 0; j < TN; ++j) {
                float v = cf[i][j] + bias[bn + tx * TN + j];
                cp[j] = 0.5f * v * (1.0f + erff(v * 0.70710678118654752f));
            }
        }
    }
}

// ---------------- split-K reduce (8 partials) ----------------
__global__ void reduce8_kernel(const float* __restrict__ p, float* __restrict__ out)
{
    int i = blockIdx.x * 256 + threadIdx.x;
    const int n4 = BL * 64 / 4;
    if (i >= n4) return;
    const float4* p4 = (const float4*)p;
    float4 a = p4[i];
#pragma unroll
    for (int s = 1; s < 8; ++s) {
        float4 b = p4[i + s * n4];
        a.x += b.x; a.y += b.y; a.z += b.z; a.w += b.w;
    }
    ((float4*)out)[i] = a;
}

// ---------------- causal conv1d + silu -> fp32 + fp16 ----------------
__global__ void conv_silu_kernel(const float* __restrict__ xz,
                                 const float* __restrict__ w,
                                 const float* __restrict__ cb,
                                 float* __restrict__ out,
                                 __half* __restrict__ oF)
{
    int id = blockIdx.x * 256 + threadIdx.x;
    if (id >= BL * DI / 4) return;
    int dq = id % (DI / 4);
    int bl = id / (DI / 4);
    int d = dq * 4;
    int t = bl % L;
    int b = bl / L;
    float4 w0 = ((const float4*)w)[d + 0];
    float4 w1 = ((const float4*)w)[d + 1];
    float4 w2 = ((const float4*)w)[d + 2];
    float4 w3 = ((const float4*)w)[d + 3];
    float4 acc = *(const float4*)&cb[d];
    const float* base = xz + (size_t)(b * L) * (2 * DI) + d;
    if (t - 3 >= 0) {
        float4 xv = *(const float4*)(base + (size_t)(t - 3) * (2 * DI));
        acc.x += w0.x * xv.x; acc.y += w1.x * xv.y; acc.z += w2.x * xv.z; acc.w += w3.x * xv.w;
    }
    if (t - 2 >= 0) {
        float4 xv = *(const float4*)(base + (size_t)(t - 2) * (2 * DI));
        acc.x += w0.y * xv.x; acc.y += w1.y * xv.y; acc.z += w2.y * xv.z; acc.w += w3.y * xv.w;
    }
    if (t - 1 >= 0) {
        float4 xv = *(const float4*)(base + (size_t)(t - 1) * (2 * DI));
        acc.x += w0.z * xv.x; acc.y += w1.z * xv.y; acc.z += w2.z * xv.z; acc.w += w3.z * xv.w;
    }
    {
        float4 xv = *(const float4*)(base + (size_t)t * (2 * DI));
        acc.x += w0.w * xv.x; acc.y += w1.w * xv.y; acc.z += w2.w * xv.z; acc.w += w3.w * xv.w;
    }
    acc.x = acc.x / (1.0f + __expf(-acc.x));
    acc.y = acc.y / (1.0f + __expf(-acc.y));
    acc.z = acc.z / (1.0f + __expf(-acc.z));
    acc.w = acc.w / (1.0f + __expf(-acc.w));
    size_t o = (size_t)bl * DI + d;
    *(float4*)&out[o] = acc;
    union { __half v[4]; uint2 u; } pf;
    pf.v[0] = __float2half_rn(acc.x);
    pf.v[1] = __float2half_rn(acc.y);
    pf.v[2] = __float2half_rn(acc.z);
    pf.v[3] = __float2half_rn(acc.w);
    *(uint2*)&oF[o] = pf.u;
}

// ---------------- selective scan (dt fused, dbc preloaded) + gate -> fp16 y ----------------
__global__ __launch_bounds__(256) void scan_kernel(
    const float* __restrict__ xc,
    const float* __restrict__ dbc,
    const float* __restrict__ xz,
    const float* __restrict__ Wdt,   // [DTR, DI]
    const float* __restrict__ bdt,   // [DI]
    const float* __restrict__ A_log,
    const float* __restrict__ Dp,
    __half* __restrict__ yF)
{
    __shared__ float sdbc[L * 64];   // 12.25 KB: dt_lo|B|C for all 49 steps
    int bb = blockIdx.x;
    int d = blockIdx.y * 256 + threadIdx.x;

    {
        const float4* src = (const float4*)(dbc + (size_t)bb * L * 64);
        float4* dst = (float4*)sdbc;
        for (int i = threadIdx.x; i < L * 16; i += 256) dst[i] = src[i];
    }

    float A[DS], h[DS], wdt[DTR];
#pragma unroll
    for (int n = 0; n < DS; ++n) { A[n] = -__expf(A_log[d * DS + n]); h[n] = 0.0f; }
#pragma unroll
    for (int k = 0; k < DTR; ++k) wdt[k] = Wdt[k * DI + d];
    float bdtd = bdt[d];
    float Dpd = Dp[d];
    __syncthreads();

    for (int t = 0; t < L; ++t) {
        const float* row = sdbc + t * 64;
        float dtv = bdtd;
#pragma unroll
        for (int k = 0; k < DTR; ++k) dtv += row[k] * wdt[k];
        dtv = fmaxf(dtv, 0.0f) + log1pf(__expf(-fabsf(dtv)));   // softplus
        size_t idx = (size_t)(bb * L + t) * DI + d;
        float xv  = xc[idx];
        float dx  = dtv * xv;
        float yv = 0.0f;
#pragma unroll
        for (int n = 0; n < DS; ++n) {
            float dA = __expf(dtv * A[n]);
            h[n] = dA * h[n] + dx * row[32 + n];
            yv += h[n] * row[48 + n];
        }
        yv += Dpd * xv;
        float z = xz[(size_t)(bb * L + t) * (2 * DI) + DI + d];
        yv *= z / (1.0f + __expf(-z));
        yF[idx] = __float2half_rn(yv);
    }
}

// ---------------- mean-pool over L + LayerNorm ----------------
__global__ void pool_ln_kernel(const float* __restrict__ hin,
                               float* __restrict__ out,
                               const float* __restrict__ g,
                               const float* __restrict__ b)
{
    __shared__ float ws[16], ws2[16];
    int bb = blockIdx.x;
    int t = threadIdx.x;
    float s = 0.0f;
    for (int tt = 0; tt < L; ++tt) s += hin[(size_t)(bb * L + tt) * DM + t];
    float v = s * (1.0f / L);
    float sm = v, s2 = v * v;
#pragma unroll
    for (int o = 16; o; o >>= 1) {
        sm += __shfl_xor_sync(0xffffffffu, sm, o);
        s2 += __shfl_xor_sync(0xffffffffu, s2, o);
    }
    if ((t & 31) == 0) { ws[t >> 5] = sm; ws2[t >> 5] = s2; }
    __syncthreads();
    if (t < 32) {
        float a  = (t < 16) ? ws[t]  : 0.0f;
        float a2 = (t < 16) ? ws2[t] : 0.0f;
#pragma unroll
        for (int o = 8; o; o >>= 1) {
            a  += __shfl_xor_sync(0xffffffffu, a,  o);
            a2 += __shfl_xor_sync(0xffffffffu, a2, o);
        }
        if (t == 0) { ws[0] = a; ws2[0] = a2; }
    }
    __syncthreads();
    float mean = ws[0] * (1.0f / DM);
    float var  = ws2[0] * (1.0f / DM) - mean * mean;
    out[bb * DM + t] = (v - mean) * rsqrtf(var + 1e-5f) * g[t] + b[t];
}

// ---------------- final logits ----------------
__global__ void logits_kernel(const float* __restrict__ hid,
                              const float* __restrict__ W2,
                              const float* __restrict__ b2,
                              float* __restrict__ out)
{
    int id = blockIdx.x * blockDim.x + threadIdx.x;
    if (id >= Bz * NC) return;
    int b = id / NC, c = id % NC;
    float acc = b2[c];
    const float* hp = hid + b * (DM / 2);
    for (int k = 0; k < DM / 2; ++k) acc += hp[k] * W2[k * NC + c];
    out[id] = acc;
}

// ---------------- launch ----------------
extern "C" void kernel_launch(void* const* d_in, const int* in_sizes, int n_in,
                              void* d_out, int out_size)
{
    const float* x      = (const float*)d_in[0];
    const float* pw     = (const float*)d_in[1];
    const float* pb     = (const float*)d_in[2];
    const float* pos    = (const float*)d_in[3];
    const float* Win    = (const float*)d_in[4];
    const float* conv_w = (const float*)d_in[5];
    const float* conv_b = (const float*)d_in[6];
    const float* Wx     = (const float*)d_in[7];
    const float* Wdt    = (const float*)d_in[8];
    const float* bdt    = (const float*)d_in[9];
    const float* A_log  = (const float*)d_in[10];
    const float* Dp     = (const float*)d_in[11];
    const float* Wout   = (const float*)d_in[12];
    const float* ln_g   = (const float*)d_in[13];
    const float* ln_b   = (const float*)d_in[14];
    const float* norm_g = (const float*)d_in[15];
    const float* norm_b = (const float*)d_in[16];
    const float* W1     = (const float*)d_in[17];
    const float* b1     = (const float*)d_in[18];
    const float* W2     = (const float*)d_in[19];
    const float* b2     = (const float*)d_in[20];

    float *h, *xz, *xc, *dbc, *dbcp, *pool, *hid;
    __half *lnF, *xcF, *yF, *WinF, *WoutF, *WxF;
    cudaGetSymbolAddress((void**)&h,    g_h);
    cudaGetSymbolAddress((void**)&xz,   g_xz);
    cudaGetSymbolAddress((void**)&xc,   g_xc);
    cudaGetSymbolAddress((void**)&dbc,  g_dbc);
    cudaGetSymbolAddress((void**)&dbcp, g_dbcp);
    cudaGetSymbolAddress((void**)&pool, g_pool);
    cudaGetSymbolAddress((void**)&hid,  g_hid);
    cudaGetSymbolAddress((void**)&lnF,  g_lnF);
    cudaGetSymbolAddress((void**)&xcF,  g_xcF);
    cudaGetSymbolAddress((void**)&yF,   g_yF);
    cudaGetSymbolAddress((void**)&WinF, g_WinF);
    cudaGetSymbolAddress((void**)&WoutF, g_WoutF);
    cudaGetSymbolAddress((void**)&WxF,  g_WxF);

    // opt-in >48KB dynamic smem (skip during capture; attribute persists)
    cudaStreamCaptureStatus cst = cudaStreamCaptureStatusNone;
    cudaStreamIsCapturing(0, &cst);
    if (cst == cudaStreamCaptureStatusNone) {
        cudaFuncSetAttribute(gemm_mma3_kernel<128, 0>, cudaFuncAttributeMaxDynamicSharedMemorySize, SMEM_MMA_128);
    }

    // weight prep: W^T fp16
    prep_w_kernel<<<dim3(64, 16, NL), 256>>>(Win,  WinF,  DM, 2 * DI);
    prep_w_kernel<<<dim3(16, 32, NL), 256>>>(Wout, WoutF, DI, DM);
    prep_w_kernel<<<dim3(2, 32, NL), 256>>>(Wx,   WxF,   DI, 64);

    patch3_kernel<<<dim3(Bz, GRID7), 512>>>(x, pw, pb, pos, h);

    for (int i = 0; i < NL; ++i) {
        layernorm_f_kernel<<<BL, DM>>>(h, lnF, ln_g + i * DM, ln_b + i * DM);

        // xz = ln @ Win[i]   [6272,512]@[512,2048]
        gemm_mma3_kernel<128, 0><<<dim3(16, 49), 256, SMEM_MMA_128>>>(
            lnF, DM, WinF + (size_t)i * 2 * DI * DM, DM,
            xz, 2 * DI, DM, 0);

        conv_silu_kernel<<<(BL * DI / 4 + 255) / 256, 256>>>(
            xz, conv_w + (size_t)i * DI * DC, conv_b + (size_t)i * DI, xc, xcF);

        // dbc = xc @ Wx[i]   [6272,1024]@[1024,64] — tensor, split-K x8
        gemm_mma3_kernel<64, 0><<<dim3(1, 49, 8), 256, SMEM_MMA_64>>>(
            xcF, DI, WxF + (size_t)i * 64 * DI, DI,
            dbcp, 64, DI / 8, (size_t)BL * 64);
        reduce8_kernel<<<(BL * 64 / 4 + 255) / 256, 256>>>(dbcp, dbc);

        // scan (dt fused) + gate
        scan_kernel<<<dim3(Bz, DI / 256), 256>>>(
            xc, dbc, xz,
            Wdt + (size_t)i * DTR * DI, bdt + (size_t)i * DI,
            A_log + (size_t)i * DI * DS, Dp + (size_t)i * DI, yF);

        // h += y @ Wout[i]   [6272,1024]@[1024,512] — BN=64 for 392 CTAs
        gemm_mma3_kernel<64, 1><<<dim3(8, 49), 256, SMEM_MMA_64>>>(
            yF, DI, WoutF + (size_t)i * DM * DI, DI,
            h, DM, DI, 0);
    }

    pool_ln_kernel<<<Bz, DM>>>(h, pool, norm_g, norm_b);

    gemm2_kernel<128, 3><<<dim3(2, 1), 256>>>(
        pool, DM, W1, DM / 2, hid, DM / 2, DM, b1, 0);

    logits_kernel<<<(Bz * NC + 255) / 256, 256>>>(hid, W2, b2, (float*)d_out);
}

// round 9
// speedup vs baseline: 3.0791x; 1.0693x over previous
#include <cuda_runtime.h>
#include <cuda_fp16.h>
#include <math.h>
#include <stdint.h>

// ---------------- Problem constants ----------------
#define Bz 128
#define IMG 28
#define GRID7 7
#define L 49
#define DM 512
#define NL 8
#define DS 16
#define DC 4
#define DI 1024
#define DTR 32
#define NC 10
#define BL (Bz * L)          // 6272

typedef unsigned long long ull;

// ================= helpers =================
__device__ __forceinline__ uint32_t s2u(const void* p) {
    uint32_t a;
    asm("{ .reg .u64 t; cvta.to.shared.u64 t, %1; cvt.u32.u64 %0, t; }" : "=r"(a) : "l"(p));
    return a;
}
__device__ __forceinline__ void cpa16(uint32_t s, const void* g) {
    asm volatile("cp.async.cg.shared.global [%0], [%1], 16;" :: "r"(s), "l"(g));
}
__device__ __forceinline__ void cp_commit() {
    asm volatile("cp.async.commit_group;" ::: "memory");
}
__device__ __forceinline__ void ldsm4(uint32_t& r0, uint32_t& r1, uint32_t& r2, uint32_t& r3, uint32_t addr) {
    asm volatile("ldmatrix.sync.aligned.m8n8.x4.shared.b16 {%0,%1,%2,%3}, [%4];"
                 : "=r"(r0), "=r"(r1), "=r"(r2), "=r"(r3) : "r"(addr));
}
__device__ __forceinline__ void ldsm2(uint32_t& r0, uint32_t& r1, uint32_t addr) {
    asm volatile("ldmatrix.sync.aligned.m8n8.x2.shared.b16 {%0,%1}, [%2];"
                 : "=r"(r0), "=r"(r1) : "r"(addr));
}
__device__ __forceinline__ void mma16816h(float* c, const uint32_t* a, const uint32_t* b) {
    asm volatile("mma.sync.aligned.m16n8k16.row.col.f32.f16.f16.f32 "
                 "{%0,%1,%2,%3}, {%4,%5,%6,%7}, {%8,%9}, {%0,%1,%2,%3};"
                 : "+f"(c[0]), "+f"(c[1]), "+f"(c[2]), "+f"(c[3])
                 : "r"(a[0]), "r"(a[1]), "r"(a[2]), "r"(a[3]), "r"(b[0]), "r"(b[1]));
}
// FFMA2 helpers (SIMT gemm)
__device__ __forceinline__ ull pack2(float lo, float hi) {
    ull r; asm("mov.b64 %0, {%1, %2};" : "=l"(r) : "f"(lo), "f"(hi)); return r;
}
__device__ __forceinline__ void unpack2(ull v, float& lo, float& hi) {
    asm("mov.b64 {%0, %1}, %2;" : "=f"(lo), "=f"(hi) : "l"(v));
}
__device__ __forceinline__ void fma2(ull& d, ull a, ull b) {
    asm("fma.rn.f32x2 %0, %1, %2, %0;" : "+l"(d) : "l"(a), "l"(b));
}

// ---------------- Scratch ----------------
__device__ float  g_h   [BL * DM];
__device__ float  g_dbcp[8 * BL * 64];
__device__ float  g_pool[Bz * DM];
__device__ float  g_hid [Bz * (DM / 2)];
__device__ __half g_lnF [BL * DM];
__device__ __half g_xzF [BL * 2 * DI];
__device__ __half g_xcF [BL * DI];
__device__ __half g_yF  [BL * DI];
__device__ __half g_WinF [NL * 2 * DI * DM];   // [l][N=2048][K=512]
__device__ __half g_WoutF[NL * DM * DI];       // [l][N=512][K=1024]
__device__ __half g_WxF  [NL * 64 * DI];       // [l][N=64][K=1024]

// ---------------- Patch embed + pos (one block per image x grid-row) ----------------
__global__ __launch_bounds__(512) void patch3_kernel(
    const float* __restrict__ x,
    const float* __restrict__ pw,
    const float* __restrict__ pb,
    const float* __restrict__ pos,
    float* __restrict__ out)
{
    __shared__ float rows[4 * IMG];
    int b = blockIdx.x;
    int gr = blockIdx.y;           // 0..6
    int t = threadIdx.x;           // output channel
    if (t < 4 * IMG) rows[t] = x[b * (IMG * IMG) + (gr * 4) * IMG + t];
    float w[16];
#pragma unroll
    for (int k = 0; k < 16; ++k) w[k] = pw[t * 16 + k];
    float pbt = pb[t];
    __syncthreads();
#pragma unroll
    for (int gc = 0; gc < GRID7; ++gc) {
        int l = gr * GRID7 + gc;
        float acc = pbt + pos[l * DM + t];
#pragma unroll
        for (int pr = 0; pr < 4; ++pr)
#pragma unroll
            for (int pc = 0; pc < 4; ++pc)
                acc += rows[pr * IMG + gc * 4 + pc] * w[pr * 4 + pc];
        out[(size_t)(b * L + l) * DM + t] = acc;
    }
}

// ---------------- weight prep: W[K,N] -> W^T fp16 [N][K] ----------------
__global__ void prep_w_kernel(const float* __restrict__ W,
                              __half* __restrict__ outF,
                              int K, int N)
{
    __shared__ float sm[32][33];
    int n0 = blockIdx.x * 32, k0 = blockIdx.y * 32, l = blockIdx.z;
    const float* Wl = W + (size_t)l * K * N;
    __half* oF = outF + (size_t)l * N * K;
    int tid = threadIdx.x;
#pragma unroll
    for (int i = 0; i < 4; ++i) {
        int idx = tid + i * 256;
        int kk = idx >> 5, nn = idx & 31;
        sm[kk][nn] = Wl[(size_t)(k0 + kk) * N + n0 + nn];
    }
    __syncthreads();
#pragma unroll
    for (int i = 0; i < 4; ++i) {
        int idx = tid + i * 256;
        int nn = idx >> 5, kk = idx & 31;
        oF[(size_t)(n0 + nn) * K + k0 + kk] = __float2half_rn(sm[kk][nn]);
    }
}

// ---------------- LayerNorm -> fp16 ----------------
__global__ void layernorm_f_kernel(const float* __restrict__ in,
                                   __half* __restrict__ oF,
                                   const float* __restrict__ g,
                                   const float* __restrict__ b)
{
    __shared__ float ws[16], ws2[16];
    int r = blockIdx.x;
    int t = threadIdx.x;           // 512
    float v = in[(size_t)r * DM + t];
    float s = v, s2 = v * v;
#pragma unroll
    for (int o = 16; o; o >>= 1) {
        s  += __shfl_xor_sync(0xffffffffu, s,  o);
        s2 += __shfl_xor_sync(0xffffffffu, s2, o);
    }
    if ((t & 31) == 0) { ws[t >> 5] = s; ws2[t >> 5] = s2; }
    __syncthreads();
    if (t < 32) {
        float a  = (t < 16) ? ws[t]  : 0.0f;
        float a2 = (t < 16) ? ws2[t] : 0.0f;
#pragma unroll
        for (int o = 8; o; o >>= 1) {
            a  += __shfl_xor_sync(0xffffffffu, a,  o);
            a2 += __shfl_xor_sync(0xffffffffu, a2, o);
        }
        if (t == 0) { ws[0] = a; ws2[0] = a2; }
    }
    __syncthreads();
    float mean = ws[0] * (1.0f / DM);
    float var  = ws2[0] * (1.0f / DM) - mean * mean;
    float nv = (v - mean) * rsqrtf(var + 1e-5f) * g[t] + b[t];
    oF[(size_t)r * DM + t] = __float2half_rn(nv);
}

// ---------------- tensor-core GEMM (fp16, cp.async 3-stage, 1 barrier/chunk) ----------------
// C[M,N] = A[M,K+] @ B^T[N,K+];  CTA tile 128 x BN, 8 warps (2 x 4), warp tile 64 x BN/4.
// EPI: 0 = store fp32, 1 = fp32 +=, 2 = store fp16 (C is __half*).
#define SSTR 40   // smem row stride in halves (32 + 8 pad)

template <int BN, int EPI>
__global__ __launch_bounds__(256) void gemm_mma3_kernel(
    const __half* __restrict__ A, int lda,
    const __half* __restrict__ B, int ldb,
    void* __restrict__ Cv, int ldc, int K, size_t splitStride)
{
    constexpr int NI = BN / 32;
    constexpr int A_SZ = 128 * SSTR;
    constexpr int B_SZ = BN * SSTR;
    constexpr int STAGE = A_SZ + B_SZ;
    extern __shared__ __half dsm[];

    int tid = threadIdx.x;
    int wid = tid >> 5, lane = tid & 31;
    int rb = blockIdx.y, nb = blockIdx.x, z = blockIdx.z;
    int warp_m = wid >> 2;
    int warp_n = wid & 3;

    const __half* gA = A + (size_t)(rb * 128) * lda + (size_t)z * K;
    const __half* gB = B + (size_t)(nb * BN) * ldb + (size_t)z * K;
    float*  Cf = (float*)Cv + (size_t)z * splitStride;
    __half* Ch = (__half*)Cv;

    float acc[4][NI][4];
#pragma unroll
    for (int mi = 0; mi < 4; ++mi)
#pragma unroll
        for (int ni = 0; ni < NI; ++ni)
#pragma unroll
            for (int q = 0; q < 4; ++q) acc[mi][ni][q] = 0.0f;

    int a_m = (lane & 7) + ((lane & 8) ? 8 : 0);
    int a_k = (lane & 16) ? 8 : 0;
    int b_n = lane & 7;
    int b_k = (lane & 8) ? 8 : 0;

    int NCH = K / 32;

    auto load_chunk = [&](int k0, int s) {
        __half* sA = dsm + s * STAGE;
        __half* sB = sA + A_SZ;
#pragma unroll
        for (int i = 0; i < 2; ++i) {
            int idx = tid + i * 256;           // 0..511 (128 rows x 4 segs)
            int r = idx >> 2, sg = idx & 3;
            cpa16(s2u(sA + r * SSTR + sg * 8), gA + (size_t)r * lda + k0 + sg * 8);
        }
#pragma unroll
        for (int i = 0; i < BN / 64; ++i) {
            int idx = tid + i * 256;
            int r = idx >> 2, sg = idx & 3;
            cpa16(s2u(sB + r * SSTR + sg * 8), gB + (size_t)r * ldb + k0 + sg * 8);
        }
        cp_commit();
    };

    load_chunk(0, 0);
    if (NCH > 1) load_chunk(32, 1);

    for (int c = 0; c < NCH; ++c) {
        if (c + 1 < NCH) {
            asm volatile("cp.async.wait_group 1;" ::: "memory");
        } else {
            asm volatile("cp.async.wait_group 0;" ::: "memory");
        }
        __syncthreads();
        if (c + 2 < NCH) load_chunk((c + 2) * 32, (c + 2) % 3);

        __half* sA = dsm + (c % 3) * STAGE;
        __half* sB = sA + A_SZ;
        uint32_t uA = s2u(sA), uB = s2u(sB);

#pragma unroll
        for (int ks = 0; ks < 2; ++ks) {
            int kk = ks * 16;
            uint32_t bh[NI][2];
#pragma unroll
            for (int ni = 0; ni < NI; ++ni) {
                int row = warp_n * (BN / 4) + ni * 8 + b_n;
                uint32_t off = (uint32_t)(row * SSTR + kk + b_k) * 2;
                ldsm2(bh[ni][0], bh[ni][1], uB + off);
            }
#pragma unroll
            for (int mi = 0; mi < 4; ++mi) {
                int row = warp_m * 64 + mi * 16 + a_m;
                uint32_t off = (uint32_t)(row * SSTR + kk + a_k) * 2;
                uint32_t ah[4];
                ldsm4(ah[0], ah[1], ah[2], ah[3], uA + off);
#pragma unroll
                for (int ni = 0; ni < NI; ++ni)
                    mma16816h(acc[mi][ni], ah, bh[ni]);
            }
        }
    }

    __syncthreads();

    int g = lane >> 2, cpair = (lane & 3) * 2;
#pragma unroll
    for (int mi = 0; mi < 4; ++mi) {
        int r0 = rb * 128 + warp_m * 64 + mi * 16 + g;
        int r1 = r0 + 8;
#pragma unroll
        for (int ni = 0; ni < NI; ++ni) {
            int col = nb * BN + warp_n * (BN / 4) + ni * 8 + cpair;
            if (EPI == 0) {
                float* c0 = Cf + (size_t)r0 * ldc + col;
                float* c1 = Cf + (size_t)r1 * ldc + col;
                *(float2*)c0 = make_float2(acc[mi][ni][0], acc[mi][ni][1]);
                *(float2*)c1 = make_float2(acc[mi][ni][2], acc[mi][ni][3]);
            } else if (EPI == 1) {
                float* c0 = Cf + (size_t)r0 * ldc + col;
                float* c1 = Cf + (size_t)r1 * ldc + col;
                float2 o0 = *(float2*)c0, o1 = *(float2*)c1;
                o0.x += acc[mi][ni][0]; o0.y += acc[mi][ni][1];
                o1.x += acc[mi][ni][2]; o1.y += acc[mi][ni][3];
                *(float2*)c0 = o0;
                *(float2*)c1 = o1;
            } else {
                __half2 h0 = __floats2half2_rn(acc[mi][ni][0], acc[mi][ni][1]);
                __half2 h1 = __floats2half2_rn(acc[mi][ni][2], acc[mi][ni][3]);
                *(__half2*)(Ch + (size_t)r0 * ldc + col) = h0;
                *(__half2*)(Ch + (size_t)r1 * ldc + col) = h1;
            }
        }
    }
}

#define SMEM_MMA_128 (3 * (128 * SSTR + 128 * SSTR) * 2)   // 61440 B (needs attribute)
#define SMEM_MMA_64  (3 * (128 * SSTR + 64  * SSTR) * 2)   // 46080 B

// ---------------- SIMT FFMA2 GEMM (final MLP) ----------------
template <int BN_T, int EPI>
__global__ __launch_bounds__(256) void gemm2_kernel(
    const float* __restrict__ A, int lda,
    const float* __restrict__ Bm_, int ldb,
    float* __restrict__ C, int ldc,
    int K, const float* __restrict__ bias, size_t splitC_stride)
{
    constexpr int TN = BN_T / 16;
    __shared__ float As[16][130];
    __shared__ float Bs[16][BN_T];

    int tid = threadIdx.x;
    int bm = blockIdx.y * 128;
    int bn = blockIdx.x * BN_T;
    int z  = blockIdx.z;
    A   += (size_t)z * K;
    Bm_ += (size_t)z * K * ldb;
    C   += (size_t)z * splitC_stride;

    int m_a = tid >> 1, k_a = (tid & 1) * 8;
    int k_b = tid >> 4;
    int n_b = (tid & 15) * TN;
    int tx = tid & 15, ty = tid >> 4;

    ull acc[4][TN];
#pragma unroll
    for (int p = 0; p < 4; ++p)
#pragma unroll
        for (int j = 0; j < TN; ++j) acc[p][j] = 0ull;

    const float* Aptr = A + (size_t)(bm + m_a) * lda + k_a;
    const float* Bptr = Bm_ + (size_t)k_b * ldb + bn + n_b;

    float4 ra0 = *(const float4*)(Aptr);
    float4 ra1 = *(const float4*)(Aptr + 4);
    float4 rb0 = *(const float4*)(Bptr);
    float4 rb1;
    if constexpr (TN == 8) rb1 = *(const float4*)(Bptr + 4);

    int ntiles = K / 16;
    for (int kt = 0; kt < ntiles; ++kt) {
        As[k_a + 0][m_a] = ra0.x; As[k_a + 1][m_a] = ra0.y;
        As[k_a + 2][m_a] = ra0.z; As[k_a + 3][m_a] = ra0.w;
        As[k_a + 4][m_a] = ra1.x; As[k_a + 5][m_a] = ra1.y;
        As[k_a + 6][m_a] = ra1.z; As[k_a + 7][m_a] = ra1.w;
        *(float4*)&Bs[k_b][n_b] = rb0;
        if constexpr (TN == 8) *(float4*)&Bs[k_b][n_b + 4] = rb1;
        __syncthreads();

        if (kt + 1 < ntiles) {
            const float* Ap = Aptr + (kt + 1) * 16;
            ra0 = *(const float4*)(Ap);
            ra1 = *(const float4*)(Ap + 4);
            const float* Bp = Bptr + (size_t)(kt + 1) * 16 * ldb;
            rb0 = *(const float4*)(Bp);
            if constexpr (TN == 8) rb1 = *(const float4*)(Bp + 4);
        }

#pragma unroll
        for (int kk = 0; kk < 16; ++kk) {
            ull a2[4];
            const ull* ap = (const ull*)&As[kk][ty * 8];
            a2[0] = ap[0]; a2[1] = ap[1]; a2[2] = ap[2]; a2[3] = ap[3];
            float bf[TN];
            {
                float4 t0 = *(const float4*)&Bs[kk][tx * TN];
                bf[0] = t0.x; bf[1] = t0.y; bf[2] = t0.z; bf[3] = t0.w;
                if constexpr (TN == 8) {
                    float4 t1 = *(const float4*)&Bs[kk][tx * TN + 4];
                    bf[4] = t1.x; bf[5] = t1.y; bf[6] = t1.z; bf[7] = t1.w;
                }
            }
#pragma unroll
            for (int j = 0; j < TN; ++j) {
                ull bb = pack2(bf[j], bf[j]);
#pragma unroll
                for (int p = 0; p < 4; ++p) fma2(acc[p][j], a2[p], bb);
            }
        }
        __syncthreads();
    }

    float cf[8][TN];
#pragma unroll
    for (int p = 0; p < 4; ++p)
#pragma unroll
        for (int j = 0; j < TN; ++j) unpack2(acc[p][j], cf[2 * p][j], cf[2 * p + 1][j]);

#pragma unroll
    for (int i = 0; i < 8; ++i) {
        int m = bm + ty * 8 + i;
        float* cp = C + (size_t)m * ldc + bn + tx * TN;
        if (EPI == 0) {
#pragma unroll
            for (int j = 0; j < TN; j += 4)
                *(float4*)(cp + j) = make_float4(cf[i][j], cf[i][j + 1], cf[i][j + 2], cf[i][j + 3]);
        } else if (EPI == 3) {
#pragma unroll
            for (int j = 0; j < TN; ++j) {
                float v = cf[i][j] + bias[bn + tx * TN + j];
                cp[j] = 0.5f * v * (1.0f + erff(v * 0.70710678118654752f));
            }
        }
    }
}

// ---------------- causal conv1d + silu (fp16 in) -> fp16 ----------------
__global__ void conv_silu_kernel(const __half* __restrict__ xzF,
                                 const float* __restrict__ w,
                                 const float* __restrict__ cb,
                                 __half* __restrict__ oF)
{
    int id = blockIdx.x * 256 + threadIdx.x;
    if (id >= BL * DI / 4) return;
    int dq = id % (DI / 4);
    int bl = id / (DI / 4);
    int d = dq * 4;
    int t = bl % L;
    int b = bl / L;
    float4 w0 = ((const float4*)w)[d + 0];
    float4 w1 = ((const float4*)w)[d + 1];
    float4 w2 = ((const float4*)w)[d + 2];
    float4 w3 = ((const float4*)w)[d + 3];
    float4 acc = *(const float4*)&cb[d];
    const __half* base = xzF + (size_t)(b * L) * (2 * DI) + d;
    auto tap = [&](int tt, float wa, float wb, float wc, float wd) {
        union { uint2 u; __half v[4]; } px;
        px.u = *(const uint2*)(base + (size_t)tt * (2 * DI));
        acc.x += wa * __half2float(px.v[0]);
        acc.y += wb * __half2float(px.v[1]);
        acc.z += wc * __half2float(px.v[2]);
        acc.w += wd * __half2float(px.v[3]);
    };
    if (t - 3 >= 0) tap(t - 3, w0.x, w1.x, w2.x, w3.x);
    if (t - 2 >= 0) tap(t - 2, w0.y, w1.y, w2.y, w3.y);
    if (t - 1 >= 0) tap(t - 1, w0.z, w1.z, w2.z, w3.z);
    tap(t, w0.w, w1.w, w2.w, w3.w);
    acc.x = acc.x / (1.0f + __expf(-acc.x));
    acc.y = acc.y / (1.0f + __expf(-acc.y));
    acc.z = acc.z / (1.0f + __expf(-acc.z));
    acc.w = acc.w / (1.0f + __expf(-acc.w));
    size_t o = (size_t)bl * DI + d;
    union { __half v[4]; uint2 u; } pf;
    pf.v[0] = __float2half_rn(acc.x);
    pf.v[1] = __float2half_rn(acc.y);
    pf.v[2] = __float2half_rn(acc.z);
    pf.v[3] = __float2half_rn(acc.w);
    *(uint2*)&oF[o] = pf.u;
}

// ---------------- selective scan (dt fused, dbc partials reduced in-smem) -> fp16 y ----------------
__global__ __launch_bounds__(256) void scan_kernel(
    const __half* __restrict__ xcF,
    const float* __restrict__ dbcp,   // 8 split-K partial slices
    const __half* __restrict__ xzF,
    const float* __restrict__ Wdt,    // [DTR, DI]
    const float* __restrict__ bdt,    // [DI]
    const float* __restrict__ A_log,
    const float* __restrict__ Dp,
    __half* __restrict__ yF)
{
    __shared__ float sdbc[L * 64];    // 12.25 KB: dt_lo|B|C for all 49 steps
    int bb = blockIdx.x;
    int d = blockIdx.y * 256 + threadIdx.x;

    {
        const int n4 = BL * 16;       // float4s per slice
        const float4* p4 = (const float4*)dbcp;
        float4* dst = (float4*)sdbc;
        for (int i = threadIdx.x; i < L * 16; i += 256) {
            int gi = bb * L * 16 + i;
            float4 a = p4[gi];
#pragma unroll
            for (int s = 1; s < 8; ++s) {
                float4 bx = p4[gi + s * n4];
                a.x += bx.x; a.y += bx.y; a.z += bx.z; a.w += bx.w;
            }
            dst[i] = a;
        }
    }

    float A[DS], h[DS], wdt[DTR];
#pragma unroll
    for (int n = 0; n < DS; ++n) { A[n] = -__expf(A_log[d * DS + n]); h[n] = 0.0f; }
#pragma unroll
    for (int k = 0; k < DTR; ++k) wdt[k] = Wdt[k * DI + d];
    float bdtd = bdt[d];
    float Dpd = Dp[d];
    __syncthreads();

    for (int t = 0; t < L; ++t) {
        const float* row = sdbc + t * 64;
        float dtv = bdtd;
#pragma unroll
        for (int k = 0; k < DTR; ++k) dtv += row[k] * wdt[k];
        dtv = fmaxf(dtv, 0.0f) + log1pf(__expf(-fabsf(dtv)));   // softplus
        size_t idx = (size_t)(bb * L + t) * DI + d;
        float xv = __half2float(xcF[idx]);
        float dx = dtv * xv;
        float yv = 0.0f;
#pragma unroll
        for (int n = 0; n < DS; ++n) {
            float dA = __expf(dtv * A[n]);
            h[n] = dA * h[n] + dx * row[32 + n];
            yv += h[n] * row[48 + n];
        }
        yv += Dpd * xv;
        float z = __half2float(xzF[(size_t)(bb * L + t) * (2 * DI) + DI + d]);
        yv *= z / (1.0f + __expf(-z));
        yF[idx] = __float2half_rn(yv);
    }
}

// ---------------- mean-pool over L + LayerNorm ----------------
__global__ void pool_ln_kernel(const float* __restrict__ hin,
                               float* __restrict__ out,
                               const float* __restrict__ g,
                               const float* __restrict__ b)
{
    __shared__ float ws[16], ws2[16];
    int bb = blockIdx.x;
    int t = threadIdx.x;
    float s = 0.0f;
    for (int tt = 0; tt < L; ++tt) s += hin[(size_t)(bb * L + tt) * DM + t];
    float v = s * (1.0f / L);
    float sm = v, s2 = v * v;
#pragma unroll
    for (int o = 16; o; o >>= 1) {
        sm += __shfl_xor_sync(0xffffffffu, sm, o);
        s2 += __shfl_xor_sync(0xffffffffu, s2, o);
    }
    if ((t & 31) == 0) { ws[t >> 5] = sm; ws2[t >> 5] = s2; }
    __syncthreads();
    if (t < 32) {
        float a  = (t < 16) ? ws[t]  : 0.0f;
        float a2 = (t < 16) ? ws2[t] : 0.0f;
#pragma unroll
        for (int o = 8; o; o >>= 1) {
            a  += __shfl_xor_sync(0xffffffffu, a,  o);
            a2 += __shfl_xor_sync(0xffffffffu, a2, o);
        }
        if (t == 0) { ws[0] = a; ws2[0] = a2; }
    }
    __syncthreads();
    float mean = ws[0] * (1.0f / DM);
    float var  = ws2[0] * (1.0f / DM) - mean * mean;
    out[bb * DM + t] = (v - mean) * rsqrtf(var + 1e-5f) * g[t] + b[t];
}

// ---------------- final logits ----------------
__global__ void logits_kernel(const float* __restrict__ hid,
                              const float* __restrict__ W2,
                              const float* __restrict__ b2,
                              float* __restrict__ out)
{
    int id = blockIdx.x * blockDim.x + threadIdx.x;
    if (id >= Bz * NC) return;
    int b = id / NC, c = id % NC;
    float acc = b2[c];
    const float* hp = hid + b * (DM / 2);
    for (int k = 0; k < DM / 2; ++k) acc += hp[k] * W2[k * NC + c];
    out[id] = acc;
}

// ---------------- launch ----------------
extern "C" void kernel_launch(void* const* d_in, const int* in_sizes, int n_in,
                              void* d_out, int out_size)
{
    const float* x      = (const float*)d_in[0];
    const float* pw     = (const float*)d_in[1];
    const float* pb     = (const float*)d_in[2];
    const float* pos    = (const float*)d_in[3];
    const float* Win    = (const float*)d_in[4];
    const float* conv_w = (const float*)d_in[5];
    const float* conv_b = (const float*)d_in[6];
    const float* Wx     = (const float*)d_in[7];
    const float* Wdt    = (const float*)d_in[8];
    const float* bdt    = (const float*)d_in[9];
    const float* A_log  = (const float*)d_in[10];
    const float* Dp     = (const float*)d_in[11];
    const float* Wout   = (const float*)d_in[12];
    const float* ln_g   = (const float*)d_in[13];
    const float* ln_b   = (const float*)d_in[14];
    const float* norm_g = (const float*)d_in[15];
    const float* norm_b = (const float*)d_in[16];
    const float* W1     = (const float*)d_in[17];
    const float* b1     = (const float*)d_in[18];
    const float* W2     = (const float*)d_in[19];
    const float* b2     = (const float*)d_in[20];

    float *h, *dbcp, *pool, *hid;
    __half *lnF, *xzF, *xcF, *yF, *WinF, *WoutF, *WxF;
    cudaGetSymbolAddress((void**)&h,    g_h);
    cudaGetSymbolAddress((void**)&dbcp, g_dbcp);
    cudaGetSymbolAddress((void**)&pool, g_pool);
    cudaGetSymbolAddress((void**)&hid,  g_hid);
    cudaGetSymbolAddress((void**)&lnF,  g_lnF);
    cudaGetSymbolAddress((void**)&xzF,  g_xzF);
    cudaGetSymbolAddress((void**)&xcF,  g_xcF);
    cudaGetSymbolAddress((void**)&yF,   g_yF);
    cudaGetSymbolAddress((void**)&WinF, g_WinF);
    cudaGetSymbolAddress((void**)&WoutF, g_WoutF);
    cudaGetSymbolAddress((void**)&WxF,  g_WxF);

    // opt-in >48KB dynamic smem (skip during capture; attribute persists)
    cudaStreamCaptureStatus cst = cudaStreamCaptureStatusNone;
    cudaStreamIsCapturing(0, &cst);
    if (cst == cudaStreamCaptureStatusNone) {
        cudaFuncSetAttribute(gemm_mma3_kernel<128, 2>, cudaFuncAttributeMaxDynamicSharedMemorySize, SMEM_MMA_128);
    }

    // weight prep: W^T fp16
    prep_w_kernel<<<dim3(64, 16, NL), 256>>>(Win,  WinF,  DM, 2 * DI);
    prep_w_kernel<<<dim3(16, 32, NL), 256>>>(Wout, WoutF, DI, DM);
    prep_w_kernel<<<dim3(2, 32, NL), 256>>>(Wx,   WxF,   DI, 64);

    patch3_kernel<<<dim3(Bz, GRID7), 512>>>(x, pw, pb, pos, h);

    for (int i = 0; i < NL; ++i) {
        layernorm_f_kernel<<<BL, DM>>>(h, lnF, ln_g + i * DM, ln_b + i * DM);

        // xz = ln @ Win[i]   [6272,512]@[512,2048] -> fp16
        gemm_mma3_kernel<128, 2><<<dim3(16, 49), 256, SMEM_MMA_128>>>(
            lnF, DM, WinF + (size_t)i * 2 * DI * DM, DM,
            xzF, 2 * DI, DM, 0);

        conv_silu_kernel<<<(BL * DI / 4 + 255) / 256, 256>>>(
            xzF, conv_w + (size_t)i * DI * DC, conv_b + (size_t)i * DI, xcF);

        // dbc partials = xc @ Wx[i]   [6272,1024]@[1024,64] — tensor, split-K x8
        gemm_mma3_kernel<64, 0><<<dim3(1, 49, 8), 256, SMEM_MMA_64>>>(
            xcF, DI, WxF + (size_t)i * 64 * DI, DI,
            dbcp, 64, DI / 8, (size_t)BL * 64);

        // scan (dt fused, partials reduced in-smem) + gate
        scan_kernel<<<dim3(Bz, DI / 256), 256>>>(
            xcF, dbcp, xzF,
            Wdt + (size_t)i * DTR * DI, bdt + (size_t)i * DI,
            A_log + (size_t)i * DI * DS, Dp + (size_t)i * DI, yF);

        // h += y @ Wout[i]   [6272,1024]@[1024,512] — BN=64 for 392 CTAs
        gemm_mma3_kernel<64, 1><<<dim3(8, 49), 256, SMEM_MMA_64>>>(
            yF, DI, WoutF + (size_t)i * DM * DI, DI,
            h, DM, DI, 0);
    }

    pool_ln_kernel<<<Bz, DM>>>(h, pool, norm_g, norm_b);

    gemm2_kernel<128, 3><<<dim3(2, 1), 256>>>(
        pool, DM, W1, DM / 2, hid, DM / 2, DM, b1, 0);

    logits_kernel<<<(Bz * NC + 255) / 256, 256>>>(hid, W2, b2, (float*)d_out);
}